// round 1
// baseline (speedup 1.0000x reference)
#include <cuda_runtime.h>
#include <math.h>

#define B_  2
#define T_  2048
#define M_  2048
#define H_  16
#define D_  128
#define BT_ (B_ * T_)

// ---------------------------------------------------------------------------
// Scratch (device globals: allocation-free per harness rules)
// ---------------------------------------------------------------------------
__device__ float g_q[(size_t)BT_ * H_ * D_];
__device__ float g_k[(size_t)BT_ * H_ * D_];
__device__ float g_v[(size_t)BT_ * H_ * D_];
__device__ float g_o[(size_t)BT_ * H_ * D_];

// ---------------------------------------------------------------------------
// Generic row-major GEMM: C[r,c] = sum_k A[r,k] * B[k,c]
// BM=64, BN=128, BK=8, 256 threads, 8x4 per-thread register tile.
// blockIdx.y selects a "panel": B += y*bStrideY, C += y*cStrideY.
//   - projections: y = head  (bStrideY = M*D, cStrideY = D)
//   - out-proj:    y = n-tile (bStrideY = 128, cStrideY = 128)
// ---------------------------------------------------------------------------
__global__ __launch_bounds__(256) void gemm_rrr(
    const float* __restrict__ A, int lda,
    const float* __restrict__ B, int ldb, long bStrideY,
    float* __restrict__ C, int ldc, long cStrideY, int K)
{
    __shared__ float As[8][64];    // As[k][m]
    __shared__ float Bs[8][128];   // Bs[k][n]

    const int tid = threadIdx.x;
    const int tx = tid & 31;       // 32 col-groups * 4 = 128
    const int ty = tid >> 5;       // 8 row-groups * 8 = 64
    const int row0 = blockIdx.x * 64;

    B += (long)blockIdx.y * bStrideY;
    C += (long)blockIdx.y * cStrideY;

    float acc[8][4];
#pragma unroll
    for (int i = 0; i < 8; ++i)
#pragma unroll
        for (int j = 0; j < 4; ++j) acc[i][j] = 0.f;

    const int ar = tid >> 2;            // 0..63
    const int ac = (tid & 3) * 2;       // 0,2,4,6
    const int br = tid >> 5;            // 0..7
    const int bc = (tid & 31) * 4;      // 0..124

    for (int k0 = 0; k0 < K; k0 += 8) {
        float2 av = *(const float2*)(A + (size_t)(row0 + ar) * lda + k0 + ac);
        float4 bv = *(const float4*)(B + (size_t)(k0 + br) * ldb + bc);
        __syncthreads();
        As[ac][ar]     = av.x;
        As[ac + 1][ar] = av.y;
        *(float4*)&Bs[br][bc] = bv;
        __syncthreads();

#pragma unroll
        for (int kk = 0; kk < 8; ++kk) {
            float4 a0 = *(const float4*)&As[kk][ty * 8];
            float4 a1 = *(const float4*)&As[kk][ty * 8 + 4];
            float4 b4 = *(const float4*)&Bs[kk][tx * 4];
            float a[8] = {a0.x, a0.y, a0.z, a0.w, a1.x, a1.y, a1.z, a1.w};
            float bb[4] = {b4.x, b4.y, b4.z, b4.w};
#pragma unroll
            for (int i = 0; i < 8; ++i)
#pragma unroll
                for (int j = 0; j < 4; ++j)
                    acc[i][j] = fmaf(a[i], bb[j], acc[i][j]);
        }
    }

#pragma unroll
    for (int i = 0; i < 8; ++i) {
        float4 o4 = make_float4(acc[i][0], acc[i][1], acc[i][2], acc[i][3]);
        *(float4*)(C + (size_t)(row0 + ty * 8 + i) * ldc + tx * 4) = o4;
    }
}

// ---------------------------------------------------------------------------
// RoPE (in-place on q and k). Layout [bt][h][d], pairs (d, d+64).
// ---------------------------------------------------------------------------
__global__ __launch_bounds__(1024) void rope_kernel(float* __restrict__ q,
                                                    float* __restrict__ k)
{
    const int bt = blockIdx.x;
    const int t  = bt % T_;
    const int h  = threadIdx.x >> 6;
    const int d  = threadIdx.x & 63;

    float freq = powf(10000.0f, -(float)d * (1.0f / 64.0f));
    float ang  = (float)t * freq;
    float s, c;
    sincosf(ang, &s, &c);

    const size_t base = ((size_t)bt * H_ + h) * D_ + d;

    float qe = q[base], qo = q[base + 64];
    q[base]      = qe * c - qo * s;
    q[base + 64] = qe * s + qo * c;

    float ke = k[base], ko = k[base + 64];
    k[base]      = ke * c - ko * s;
    k[base + 64] = ke * s + ko * c;
}

// ---------------------------------------------------------------------------
// Causal flash attention, fp32. 64x64 tiles, D=128. 256 threads.
// smem strides: Qs/Ks = 133 (odd -> conflict-free column access),
//               Vs = 132 (float4-aligned row access), Ps = 68.
// ---------------------------------------------------------------------------
#define QS_STR 133
#define VS_STR 132
#define PS_STR 68
#define ATTN_SMEM_FLOATS (64*QS_STR /*Q*/ + 64*QS_STR /*K*/ + 64*VS_STR /*V*/ \
                          + 64*PS_STR /*P*/ + 64*17 /*red*/ + 3*64 /*m,l,al*/)

__global__ __launch_bounds__(256) void attn_kernel(
    const float* __restrict__ Q, const float* __restrict__ K,
    const float* __restrict__ V, float* __restrict__ O)
{
    extern __shared__ float sm[];
    float* Qs  = sm;
    float* Ks  = Qs + 64 * QS_STR;
    float* Vs  = Ks + 64 * QS_STR;
    float* Ps  = Vs + 64 * VS_STR;
    float* red = Ps + 64 * PS_STR;
    float* m_s = red + 64 * 17;
    float* l_s = m_s + 64;
    float* al_s = l_s + 64;

    const int tid = threadIdx.x;
    const int qi = blockIdx.x, h = blockIdx.y, b = blockIdx.z;
    const int i0 = qi * 64;

    const float* Qp = Q + (((size_t)b * T_ + i0) * H_ + h) * D_;

    // Load Q tile, fold in muP scale 1/D.
    for (int idx = tid; idx < 64 * 32; idx += 256) {
        int r = idx >> 5, c4 = (idx & 31) * 4;
        float4 qv = *(const float4*)(Qp + (size_t)r * (H_ * D_) + c4);
        float* dst = &Qs[r * QS_STR + c4];
        const float sc = 1.0f / 128.0f;
        dst[0] = qv.x * sc; dst[1] = qv.y * sc;
        dst[2] = qv.z * sc; dst[3] = qv.w * sc;
    }
    if (tid < 64) { m_s[tid] = -3.0e38f; l_s[tid] = 0.f; }

    float acc[8][4];
#pragma unroll
    for (int i = 0; i < 8; ++i)
#pragma unroll
        for (int j = 0; j < 4; ++j) acc[i][j] = 0.f;

    const int ts_x = tid & 15, ts_y = tid >> 4;   // S-phase: 16x16 threads, 4x4 each
    const int tyo = tid >> 5, txo = tid & 31;     // PV-phase: 8 row groups x 32 cols

    for (int jt = 0; jt <= qi; ++jt) {
        const int j0 = jt * 64;
        __syncthreads();   // previous PV done before K/V overwrite; Q/minit visible

        const float* Kp = K + (((size_t)b * T_ + j0) * H_ + h) * D_;
        const float* Vp = V + (((size_t)b * T_ + j0) * H_ + h) * D_;
        for (int idx = tid; idx < 64 * 32; idx += 256) {
            int r = idx >> 5, c4 = (idx & 31) * 4;
            float4 kv = *(const float4*)(Kp + (size_t)r * (H_ * D_) + c4);
            float* kd = &Ks[r * QS_STR + c4];
            kd[0] = kv.x; kd[1] = kv.y; kd[2] = kv.z; kd[3] = kv.w;
            float4 vv = *(const float4*)(Vp + (size_t)r * (H_ * D_) + c4);
            *(float4*)&Vs[r * VS_STR + c4] = vv;
        }
        __syncthreads();

        // --- S = (Q/128) * K^T, 4x4 per thread ---
        float s[4][4];
#pragma unroll
        for (int i = 0; i < 4; ++i)
#pragma unroll
            for (int j = 0; j < 4; ++j) s[i][j] = 0.f;

#pragma unroll 4
        for (int kk = 0; kk < 128; ++kk) {
            float a0 = Qs[(ts_y * 4 + 0) * QS_STR + kk];
            float a1 = Qs[(ts_y * 4 + 1) * QS_STR + kk];
            float a2 = Qs[(ts_y * 4 + 2) * QS_STR + kk];
            float a3 = Qs[(ts_y * 4 + 3) * QS_STR + kk];
            float b0 = Ks[(ts_x * 4 + 0) * QS_STR + kk];
            float b1 = Ks[(ts_x * 4 + 1) * QS_STR + kk];
            float b2 = Ks[(ts_x * 4 + 2) * QS_STR + kk];
            float b3 = Ks[(ts_x * 4 + 3) * QS_STR + kk];
            s[0][0] = fmaf(a0, b0, s[0][0]); s[0][1] = fmaf(a0, b1, s[0][1]);
            s[0][2] = fmaf(a0, b2, s[0][2]); s[0][3] = fmaf(a0, b3, s[0][3]);
            s[1][0] = fmaf(a1, b0, s[1][0]); s[1][1] = fmaf(a1, b1, s[1][1]);
            s[1][2] = fmaf(a1, b2, s[1][2]); s[1][3] = fmaf(a1, b3, s[1][3]);
            s[2][0] = fmaf(a2, b0, s[2][0]); s[2][1] = fmaf(a2, b1, s[2][1]);
            s[2][2] = fmaf(a2, b2, s[2][2]); s[2][3] = fmaf(a2, b3, s[2][3]);
            s[3][0] = fmaf(a3, b0, s[3][0]); s[3][1] = fmaf(a3, b1, s[3][1]);
            s[3][2] = fmaf(a3, b2, s[3][2]); s[3][3] = fmaf(a3, b3, s[3][3]);
        }

        // --- causal mask + per-thread row max ---
#pragma unroll
        for (int i = 0; i < 4; ++i) {
            int gr = i0 + ts_y * 4 + i;
#pragma unroll
            for (int j = 0; j < 4; ++j) {
                int gc = j0 + ts_x * 4 + j;
                if (gc > gr) s[i][j] = -1e30f;
            }
            float mx = fmaxf(fmaxf(s[i][0], s[i][1]), fmaxf(s[i][2], s[i][3]));
            red[(ts_y * 4 + i) * 17 + ts_x] = mx;
        }
        __syncthreads();

        if (tid < 64) {
            float mloc = red[tid * 17];
#pragma unroll
            for (int x = 1; x < 16; ++x) mloc = fmaxf(mloc, red[tid * 17 + x]);
            float mo = m_s[tid];
            float mn = fmaxf(mo, mloc);
            m_s[tid] = mn;
            float al = expf(mo - mn);   // first tile: expf(-3e38 - mn) -> 0
            al_s[tid] = al;
            l_s[tid] *= al;
        }
        __syncthreads();

        // --- P = exp(S - m), write Ps, partial row sums ---
#pragma unroll
        for (int i = 0; i < 4; ++i) {
            int row = ts_y * 4 + i;
            float mn = m_s[row];
            float p0 = expf(s[i][0] - mn);
            float p1 = expf(s[i][1] - mn);
            float p2 = expf(s[i][2] - mn);
            float p3 = expf(s[i][3] - mn);
            *(float4*)&Ps[row * PS_STR + ts_x * 4] = make_float4(p0, p1, p2, p3);
            red[row * 17 + ts_x] = p0 + p1 + p2 + p3;
        }
        __syncthreads();

        if (tid < 64) {
            float sum = 0.f;
#pragma unroll
            for (int x = 0; x < 16; ++x) sum += red[tid * 17 + x];
            l_s[tid] += sum;
        }

        // --- rescale O accumulator by alpha ---
#pragma unroll
        for (int ii = 0; ii < 8; ++ii) {
            float al = al_s[tyo * 8 + ii];
#pragma unroll
            for (int cc = 0; cc < 4; ++cc) acc[ii][cc] *= al;
        }

        // --- O += P * V ---
#pragma unroll 2
        for (int j = 0; j < 64; ++j) {
            float pr[8];
#pragma unroll
            for (int ii = 0; ii < 8; ++ii) pr[ii] = Ps[(tyo * 8 + ii) * PS_STR + j];
            float v0 = Vs[j * VS_STR + txo];
            float v1 = Vs[j * VS_STR + txo + 32];
            float v2 = Vs[j * VS_STR + txo + 64];
            float v3 = Vs[j * VS_STR + txo + 96];
#pragma unroll
            for (int ii = 0; ii < 8; ++ii) {
                acc[ii][0] = fmaf(pr[ii], v0, acc[ii][0]);
                acc[ii][1] = fmaf(pr[ii], v1, acc[ii][1]);
                acc[ii][2] = fmaf(pr[ii], v2, acc[ii][2]);
                acc[ii][3] = fmaf(pr[ii], v3, acc[ii][3]);
            }
        }
    }

    __syncthreads();   // l_s final values visible

#pragma unroll
    for (int ii = 0; ii < 8; ++ii) {
        int r = tyo * 8 + ii;
        float inv = 1.0f / l_s[r];
        float* op = O + (((size_t)b * T_ + i0 + r) * H_ + h) * D_ + txo;
        op[0]  = acc[ii][0] * inv;
        op[32] = acc[ii][1] * inv;
        op[64] = acc[ii][2] * inv;
        op[96] = acc[ii][3] * inv;
    }
}

// ---------------------------------------------------------------------------
// Launch
// ---------------------------------------------------------------------------
extern "C" void kernel_launch(void* const* d_in, const int* in_sizes, int n_in,
                              void* d_out, int out_size)
{
    const float* x    = (const float*)d_in[0];
    const float* w_aq = (const float*)d_in[1];
    const float* w_ak = (const float*)d_in[2];
    const float* w_av = (const float*)d_in[3];
    const float* w_ao = (const float*)d_in[4];
    float* out = (float*)d_out;

    float *q, *k, *v, *o;
    cudaGetSymbolAddress((void**)&q, g_q);
    cudaGetSymbolAddress((void**)&k, g_k);
    cudaGetSymbolAddress((void**)&v, g_v);
    cudaGetSymbolAddress((void**)&o, g_o);

    // QKV projections: per-head GEMMs [4096x2048]x[2048x128]
    dim3 gp(BT_ / 64, H_);
    gemm_rrr<<<gp, 256>>>(x, M_, w_aq, D_, (long)M_ * D_, q, H_ * D_, (long)D_, M_);
    gemm_rrr<<<gp, 256>>>(x, M_, w_ak, D_, (long)M_ * D_, k, H_ * D_, (long)D_, M_);
    gemm_rrr<<<gp, 256>>>(x, M_, w_av, D_, (long)M_ * D_, v, H_ * D_, (long)D_, M_);

    // RoPE on q, k
    rope_kernel<<<BT_, 1024>>>(q, k);

    // Flash attention
    size_t smem = (size_t)ATTN_SMEM_FLOATS * sizeof(float);
    cudaFuncSetAttribute(attn_kernel, cudaFuncAttributeMaxDynamicSharedMemorySize,
                         (int)smem);
    dim3 ga(T_ / 64, H_, B_);
    attn_kernel<<<ga, 256, smem>>>(q, k, v, o);

    // Output projection: [4096x2048]x[2048x2048]
    dim3 go(BT_ / 64, M_ / 128);
    gemm_rrr<<<go, 256>>>(o, H_ * D_, w_ao, M_, 128L, out, M_, 128L, H_ * D_);
}

// round 3
// speedup vs baseline: 1.5344x; 1.5344x over previous
#include <cuda_runtime.h>
#include <cuda_bf16.h>
#include <math.h>
#include <stdint.h>

#define B_  2
#define T_  2048
#define M_  2048
#define H_  16
#define D_  128
#define BT_ (B_ * T_)
#define K_  M_

// ---------------------------------------------------------------------------
// Scratch (device globals: allocation-free per harness rules)
// ---------------------------------------------------------------------------
__device__ float g_q[(size_t)BT_ * H_ * D_];
__device__ float g_k[(size_t)BT_ * H_ * D_];
__device__ float g_v[(size_t)BT_ * H_ * D_];
__device__ float g_o[(size_t)BT_ * H_ * D_];

__device__ __nv_bfloat16 g_xh[(size_t)BT_ * M_];
__device__ __nv_bfloat16 g_xl[(size_t)BT_ * M_];
__device__ __nv_bfloat16 g_oh[(size_t)BT_ * M_];
__device__ __nv_bfloat16 g_ol[(size_t)BT_ * M_];

__device__ __nv_bfloat16 g_wqh[(size_t)H_ * D_ * M_];
__device__ __nv_bfloat16 g_wql[(size_t)H_ * D_ * M_];
__device__ __nv_bfloat16 g_wkh[(size_t)H_ * D_ * M_];
__device__ __nv_bfloat16 g_wkl[(size_t)H_ * D_ * M_];
__device__ __nv_bfloat16 g_wvh[(size_t)H_ * D_ * M_];
__device__ __nv_bfloat16 g_wvl[(size_t)H_ * D_ * M_];
__device__ __nv_bfloat16 g_woh[(size_t)M_ * M_];
__device__ __nv_bfloat16 g_wol[(size_t)M_ * M_];

// ---------------------------------------------------------------------------
// PTX helpers (sm_80-class only: legal under plain sm_103 target)
// ---------------------------------------------------------------------------
__device__ __forceinline__ uint32_t s2u(const void* p) {
    uint32_t a;
    asm("{ .reg .u64 t; cvta.to.shared.u64 t, %1; cvt.u32.u64 %0, t; }"
        : "=r"(a) : "l"(p));
    return a;
}

__device__ __forceinline__ void cp16(uint32_t dst, const void* src) {
    asm volatile("cp.async.cg.shared.global [%0], [%1], 16;"
                 :: "r"(dst), "l"(src) : "memory");
}

#define LDSM4(r, a) \
    asm volatile("ldmatrix.sync.aligned.m8n8.x4.shared.b16 {%0,%1,%2,%3}, [%4];" \
                 : "=r"((r)[0]), "=r"((r)[1]), "=r"((r)[2]), "=r"((r)[3])        \
                 : "r"(a))

__device__ __forceinline__ void mma16816(float* d, const uint32_t* a,
                                         uint32_t b0, uint32_t b1) {
    asm volatile(
        "mma.sync.aligned.m16n8k16.row.col.f32.bf16.bf16.f32 "
        "{%0,%1,%2,%3}, {%4,%5,%6,%7}, {%8,%9}, {%0,%1,%2,%3};"
        : "+f"(d[0]), "+f"(d[1]), "+f"(d[2]), "+f"(d[3])
        : "r"(a[0]), "r"(a[1]), "r"(a[2]), "r"(a[3]), "r"(b0), "r"(b1));
}

// ---------------------------------------------------------------------------
// Split conversion: fp32 -> (hi, lo) bf16
// ---------------------------------------------------------------------------
__global__ __launch_bounds__(256) void split_kernel(
    const float* __restrict__ x, __nv_bfloat16* __restrict__ h,
    __nv_bfloat16* __restrict__ l, int n4)
{
    int i = blockIdx.x * blockDim.x + threadIdx.x;
    if (i >= n4) return;
    float4 v = ((const float4*)x)[i];
    __nv_bfloat16 h0 = __float2bfloat16(v.x);
    __nv_bfloat16 h1 = __float2bfloat16(v.y);
    __nv_bfloat16 h2 = __float2bfloat16(v.z);
    __nv_bfloat16 h3 = __float2bfloat16(v.w);
    __nv_bfloat16 l0 = __float2bfloat16(v.x - __bfloat162float(h0));
    __nv_bfloat16 l1 = __float2bfloat16(v.y - __bfloat162float(h1));
    __nv_bfloat16 l2 = __float2bfloat16(v.z - __bfloat162float(h2));
    __nv_bfloat16 l3 = __float2bfloat16(v.w - __bfloat162float(h3));
    __nv_bfloat162* H = (__nv_bfloat162*)h;
    __nv_bfloat162* L = (__nv_bfloat162*)l;
    H[2*i]   = __halves2bfloat162(h0, h1);
    H[2*i+1] = __halves2bfloat162(h2, h3);
    L[2*i]   = __halves2bfloat162(l0, l1);
    L[2*i+1] = __halves2bfloat162(l2, l3);
}

// ---------------------------------------------------------------------------
// Transpose + split: src [R, C] fp32 (per-z panel) -> dst [C, R] hi/lo bf16
// ---------------------------------------------------------------------------
__global__ __launch_bounds__(256) void tsplit_kernel(
    const float* __restrict__ src, long srcZ,
    __nv_bfloat16* __restrict__ dh, __nv_bfloat16* __restrict__ dl, long dstZ,
    int R, int C)
{
    __shared__ float t[32][33];
    src += (size_t)blockIdx.z * srcZ;
    dh  += (size_t)blockIdx.z * dstZ;
    dl  += (size_t)blockIdx.z * dstZ;
    int c0 = blockIdx.x * 32, r0 = blockIdx.y * 32;
    int tx = threadIdx.x, ty = threadIdx.y;  // 32 x 8
#pragma unroll
    for (int j = 0; j < 4; j++)
        t[ty + 8*j][tx] = src[(size_t)(r0 + ty + 8*j) * C + c0 + tx];
    __syncthreads();
#pragma unroll
    for (int j = 0; j < 4; j++) {
        float v = t[tx][ty + 8*j];
        __nv_bfloat16 hi = __float2bfloat16(v);
        __nv_bfloat16 lo = __float2bfloat16(v - __bfloat162float(hi));
        size_t o = (size_t)(c0 + ty + 8*j) * R + r0 + tx;
        dh[o] = hi;
        dl[o] = lo;
    }
}

// ---------------------------------------------------------------------------
// HMMA GEMM: C[128x128 tile] = A[128,K] @ B[128,K]^T  (bf16 hi/lo split)
// A row-major [Mtot, 2048], B row-major [Ntot, 2048] (pre-transposed weights),
// C row-major. grid = (Mtiles, Ntiles, nProblems<=3). 256 threads, 8 warps
// in a 2(m) x 4(n) grid, each warp 64x32. BK=32, 3-stage cp.async pipeline.
// smem rows padded to 80B -> conflict-free ldmatrix.
// ---------------------------------------------------------------------------
#define ROWB      80
#define MAT_BYTES (128 * ROWB)       // 10240
#define STG_BYTES (4 * MAT_BYTES)    // 40960 (Ah, Al, Bh, Bl)
#define NSTG      3
#define GEMM_SMEM (NSTG * STG_BYTES) // 122880
#define KSTEPS    (K_ / 32)          // 64

__device__ __forceinline__ void load_stage(
    uint32_t buf,
    const __nv_bfloat16* __restrict__ Ah, const __nv_bfloat16* __restrict__ Al,
    const __nv_bfloat16* __restrict__ Bh, const __nv_bfloat16* __restrict__ Bl,
    int k0, int tid)
{
#pragma unroll
    for (int it = 0; it < 2; it++) {
        int idx = tid + it * 256;        // 0..511
        int row = idx >> 2, c = idx & 3; // 128 rows x 4 x 16B chunks
        uint32_t so = (uint32_t)(row * ROWB + c * 16);
        const size_t go = (size_t)row * K_ + k0 + c * 8;
        cp16(buf + so,                 Ah + go);
        cp16(buf + MAT_BYTES + so,     Al + go);
        cp16(buf + 2 * MAT_BYTES + so, Bh + go);
        cp16(buf + 3 * MAT_BYTES + so, Bl + go);
    }
}

__global__ __launch_bounds__(256) void gemm_mma(
    const __nv_bfloat16* __restrict__ Ah, const __nv_bfloat16* __restrict__ Al,
    const __nv_bfloat16* __restrict__ B0h, const __nv_bfloat16* __restrict__ B0l,
    const __nv_bfloat16* __restrict__ B1h, const __nv_bfloat16* __restrict__ B1l,
    const __nv_bfloat16* __restrict__ B2h, const __nv_bfloat16* __restrict__ B2l,
    float* __restrict__ C0, float* __restrict__ C1, float* __restrict__ C2)
{
    extern __shared__ char smraw[];
    const uint32_t sb = s2u(smraw);
    const int tid = threadIdx.x;
    const int wid = tid >> 5, lane = tid & 31;
    const int warp_m = wid >> 2;      // 0..1  (64 rows each)
    const int warp_n = wid & 3;       // 0..3  (32 cols each)

    const __nv_bfloat16 *Bh, *Bl;
    float* C;
    if (blockIdx.z == 0)      { Bh = B0h; Bl = B0l; C = C0; }
    else if (blockIdx.z == 1) { Bh = B1h; Bl = B1l; C = C1; }
    else                      { Bh = B2h; Bl = B2l; C = C2; }

    const int row0 = blockIdx.x * 128;
    const int col0 = blockIdx.y * 128;
    Ah += (size_t)row0 * K_;  Al += (size_t)row0 * K_;
    Bh += (size_t)col0 * K_;  Bl += (size_t)col0 * K_;

    // Prologue: stages 0 and 1
    load_stage(sb,             Ah, Al, Bh, Bl, 0,  tid);
    asm volatile("cp.async.commit_group;" ::: "memory");
    load_stage(sb + STG_BYTES, Ah, Al, Bh, Bl, 32, tid);
    asm volatile("cp.async.commit_group;" ::: "memory");

    float acc[4][4][4];
#pragma unroll
    for (int i = 0; i < 4; i++)
#pragma unroll
        for (int j = 0; j < 4; j++)
#pragma unroll
            for (int r = 0; r < 4; r++) acc[i][j][r] = 0.f;

    // Per-lane ldmatrix base offsets
    const int lrow = lane & 15;           // row within 16-row group
    const int lchk = (lane >> 4) * 16;    // 16B chunk select

    for (int s = 0; s < KSTEPS; s++) {
        if (s + 1 < KSTEPS)
            asm volatile("cp.async.wait_group 1;" ::: "memory");
        else
            asm volatile("cp.async.wait_group 0;" ::: "memory");
        __syncthreads();

        if (s + 2 < KSTEPS) {
            load_stage(sb + (uint32_t)((s + 2) % NSTG) * STG_BYTES,
                       Ah, Al, Bh, Bl, (s + 2) * 32, tid);
            asm volatile("cp.async.commit_group;" ::: "memory");
        }

        const uint32_t base = sb + (uint32_t)(s % NSTG) * STG_BYTES;

#pragma unroll
        for (int kh = 0; kh < 2; kh++) {   // two k16 steps in BK=32
            const uint32_t koff = (uint32_t)(kh * 32 + lchk);

            uint32_t a_hi[4][4], a_lo[4][4];
#pragma unroll
            for (int mi = 0; mi < 4; mi++) {
                uint32_t ad = base +
                    (uint32_t)((warp_m * 64 + mi * 16 + lrow) * ROWB) + koff;
                LDSM4(a_hi[mi], ad);
                LDSM4(a_lo[mi], ad + MAT_BYTES);
            }
            uint32_t b_hi[2][4], b_lo[2][4];
#pragma unroll
            for (int bj = 0; bj < 2; bj++) {
                uint32_t bd = base + 2 * MAT_BYTES +
                    (uint32_t)((warp_n * 32 + bj * 16 + lrow) * ROWB) + koff;
                LDSM4(b_hi[bj], bd);
                LDSM4(b_lo[bj], bd + MAT_BYTES);
            }
#pragma unroll
            for (int mi = 0; mi < 4; mi++) {
#pragma unroll
                for (int ni = 0; ni < 4; ni++) {
                    const int bj = ni >> 1, sel = ni & 1;
                    mma16816(acc[mi][ni], a_hi[mi], b_hi[bj][sel], b_hi[bj][sel + 2]);
                    mma16816(acc[mi][ni], a_hi[mi], b_lo[bj][sel], b_lo[bj][sel + 2]);
                    mma16816(acc[mi][ni], a_lo[mi], b_hi[bj][sel], b_hi[bj][sel + 2]);
                }
            }
        }
    }

    // Epilogue: direct float2 stores
    const int grp = lane >> 2, tig = lane & 3;
#pragma unroll
    for (int mi = 0; mi < 4; mi++) {
#pragma unroll
        for (int ni = 0; ni < 4; ni++) {
            int r = row0 + warp_m * 64 + mi * 16 + grp;
            int c = col0 + warp_n * 32 + ni * 8 + tig * 2;
            *(float2*)(C + (size_t)r * M_ + c) =
                make_float2(acc[mi][ni][0], acc[mi][ni][1]);
            *(float2*)(C + (size_t)(r + 8) * M_ + c) =
                make_float2(acc[mi][ni][2], acc[mi][ni][3]);
        }
    }
}

// ---------------------------------------------------------------------------
// RoPE (in-place on q and k). Layout [bt][h][d], pairs (d, d+64).
// ---------------------------------------------------------------------------
__global__ __launch_bounds__(1024) void rope_kernel(float* __restrict__ q,
                                                    float* __restrict__ k)
{
    const int bt = blockIdx.x;
    const int t  = bt % T_;
    const int h  = threadIdx.x >> 6;
    const int d  = threadIdx.x & 63;

    float freq = powf(10000.0f, -(float)d * (1.0f / 64.0f));
    float ang  = (float)t * freq;
    float s, c;
    sincosf(ang, &s, &c);

    const size_t base = ((size_t)bt * H_ + h) * D_ + d;

    float qe = q[base], qo = q[base + 64];
    q[base]      = qe * c - qo * s;
    q[base + 64] = qe * s + qo * c;

    float ke = k[base], ko = k[base + 64];
    k[base]      = ke * c - ko * s;
    k[base + 64] = ke * s + ko * c;
}

// ---------------------------------------------------------------------------
// Causal flash attention, fp32. 64x64 tiles, D=128. 256 threads.
// ---------------------------------------------------------------------------
#define QS_STR 133
#define VS_STR 132
#define PS_STR 68
#define ATTN_SMEM_FLOATS (64*QS_STR + 64*QS_STR + 64*VS_STR + 64*PS_STR + 64*17 + 3*64)

__global__ __launch_bounds__(256) void attn_kernel(
    const float* __restrict__ Q, const float* __restrict__ K,
    const float* __restrict__ V, float* __restrict__ O)
{
    extern __shared__ float sm[];
    float* Qs  = sm;
    float* Ks  = Qs + 64 * QS_STR;
    float* Vs  = Ks + 64 * QS_STR;
    float* Ps  = Vs + 64 * VS_STR;
    float* red = Ps + 64 * PS_STR;
    float* m_s = red + 64 * 17;
    float* l_s = m_s + 64;
    float* al_s = l_s + 64;

    const int tid = threadIdx.x;
    const int qi = blockIdx.x, h = blockIdx.y, b = blockIdx.z;
    const int i0 = qi * 64;

    const float* Qp = Q + (((size_t)b * T_ + i0) * H_ + h) * D_;

    for (int idx = tid; idx < 64 * 32; idx += 256) {
        int r = idx >> 5, c4 = (idx & 31) * 4;
        float4 qv = *(const float4*)(Qp + (size_t)r * (H_ * D_) + c4);
        float* dst = &Qs[r * QS_STR + c4];
        const float sc = 1.0f / 128.0f;
        dst[0] = qv.x * sc; dst[1] = qv.y * sc;
        dst[2] = qv.z * sc; dst[3] = qv.w * sc;
    }
    if (tid < 64) { m_s[tid] = -3.0e38f; l_s[tid] = 0.f; }

    float acc[8][4];
#pragma unroll
    for (int i = 0; i < 8; ++i)
#pragma unroll
        for (int j = 0; j < 4; ++j) acc[i][j] = 0.f;

    const int ts_x = tid & 15, ts_y = tid >> 4;
    const int tyo = tid >> 5, txo = tid & 31;

    for (int jt = 0; jt <= qi; ++jt) {
        const int j0 = jt * 64;
        __syncthreads();

        const float* Kp = K + (((size_t)b * T_ + j0) * H_ + h) * D_;
        const float* Vp = V + (((size_t)b * T_ + j0) * H_ + h) * D_;
        for (int idx = tid; idx < 64 * 32; idx += 256) {
            int r = idx >> 5, c4 = (idx & 31) * 4;
            float4 kv = *(const float4*)(Kp + (size_t)r * (H_ * D_) + c4);
            float* kd = &Ks[r * QS_STR + c4];
            kd[0] = kv.x; kd[1] = kv.y; kd[2] = kv.z; kd[3] = kv.w;
            float4 vv = *(const float4*)(Vp + (size_t)r * (H_ * D_) + c4);
            *(float4*)&Vs[r * VS_STR + c4] = vv;
        }
        __syncthreads();

        float s[4][4];
#pragma unroll
        for (int i = 0; i < 4; ++i)
#pragma unroll
            for (int j = 0; j < 4; ++j) s[i][j] = 0.f;

#pragma unroll 4
        for (int kk = 0; kk < 128; ++kk) {
            float a0 = Qs[(ts_y * 4 + 0) * QS_STR + kk];
            float a1 = Qs[(ts_y * 4 + 1) * QS_STR + kk];
            float a2 = Qs[(ts_y * 4 + 2) * QS_STR + kk];
            float a3 = Qs[(ts_y * 4 + 3) * QS_STR + kk];
            float b0 = Ks[(ts_x * 4 + 0) * QS_STR + kk];
            float b1 = Ks[(ts_x * 4 + 1) * QS_STR + kk];
            float b2 = Ks[(ts_x * 4 + 2) * QS_STR + kk];
            float b3 = Ks[(ts_x * 4 + 3) * QS_STR + kk];
            s[0][0] = fmaf(a0, b0, s[0][0]); s[0][1] = fmaf(a0, b1, s[0][1]);
            s[0][2] = fmaf(a0, b2, s[0][2]); s[0][3] = fmaf(a0, b3, s[0][3]);
            s[1][0] = fmaf(a1, b0, s[1][0]); s[1][1] = fmaf(a1, b1, s[1][1]);
            s[1][2] = fmaf(a1, b2, s[1][2]); s[1][3] = fmaf(a1, b3, s[1][3]);
            s[2][0] = fmaf(a2, b0, s[2][0]); s[2][1] = fmaf(a2, b1, s[2][1]);
            s[2][2] = fmaf(a2, b2, s[2][2]); s[2][3] = fmaf(a2, b3, s[2][3]);
            s[3][0] = fmaf(a3, b0, s[3][0]); s[3][1] = fmaf(a3, b1, s[3][1]);
            s[3][2] = fmaf(a3, b2, s[3][2]); s[3][3] = fmaf(a3, b3, s[3][3]);
        }

#pragma unroll
        for (int i = 0; i < 4; ++i) {
            int gr = i0 + ts_y * 4 + i;
#pragma unroll
            for (int j = 0; j < 4; ++j) {
                int gc = j0 + ts_x * 4 + j;
                if (gc > gr) s[i][j] = -1e30f;
            }
            float mx = fmaxf(fmaxf(s[i][0], s[i][1]), fmaxf(s[i][2], s[i][3]));
            red[(ts_y * 4 + i) * 17 + ts_x] = mx;
        }
        __syncthreads();

        if (tid < 64) {
            float mloc = red[tid * 17];
#pragma unroll
            for (int x = 1; x < 16; ++x) mloc = fmaxf(mloc, red[tid * 17 + x]);
            float mo = m_s[tid];
            float mn = fmaxf(mo, mloc);
            m_s[tid] = mn;
            float al = expf(mo - mn);
            al_s[tid] = al;
            l_s[tid] *= al;
        }
        __syncthreads();

#pragma unroll
        for (int i = 0; i < 4; ++i) {
            int row = ts_y * 4 + i;
            float mn = m_s[row];
            float p0 = expf(s[i][0] - mn);
            float p1 = expf(s[i][1] - mn);
            float p2 = expf(s[i][2] - mn);
            float p3 = expf(s[i][3] - mn);
            *(float4*)&Ps[row * PS_STR + ts_x * 4] = make_float4(p0, p1, p2, p3);
            red[row * 17 + ts_x] = p0 + p1 + p2 + p3;
        }
        __syncthreads();

        if (tid < 64) {
            float sum = 0.f;
#pragma unroll
            for (int x = 0; x < 16; ++x) sum += red[tid * 17 + x];
            l_s[tid] += sum;
        }

#pragma unroll
        for (int ii = 0; ii < 8; ++ii) {
            float al = al_s[tyo * 8 + ii];
#pragma unroll
            for (int cc = 0; cc < 4; ++cc) acc[ii][cc] *= al;
        }

#pragma unroll 2
        for (int j = 0; j < 64; ++j) {
            float pr[8];
#pragma unroll
            for (int ii = 0; ii < 8; ++ii) pr[ii] = Ps[(tyo * 8 + ii) * PS_STR + j];
            float v0 = Vs[j * VS_STR + txo];
            float v1 = Vs[j * VS_STR + txo + 32];
            float v2 = Vs[j * VS_STR + txo + 64];
            float v3 = Vs[j * VS_STR + txo + 96];
#pragma unroll
            for (int ii = 0; ii < 8; ++ii) {
                acc[ii][0] = fmaf(pr[ii], v0, acc[ii][0]);
                acc[ii][1] = fmaf(pr[ii], v1, acc[ii][1]);
                acc[ii][2] = fmaf(pr[ii], v2, acc[ii][2]);
                acc[ii][3] = fmaf(pr[ii], v3, acc[ii][3]);
            }
        }
    }

    __syncthreads();

#pragma unroll
    for (int ii = 0; ii < 8; ++ii) {
        int r = tyo * 8 + ii;
        float inv = 1.0f / l_s[r];
        float* op = O + (((size_t)b * T_ + i0 + r) * H_ + h) * D_ + txo;
        op[0]  = acc[ii][0] * inv;
        op[32] = acc[ii][1] * inv;
        op[64] = acc[ii][2] * inv;
        op[96] = acc[ii][3] * inv;
    }
}

// ---------------------------------------------------------------------------
// Launch
// ---------------------------------------------------------------------------
extern "C" void kernel_launch(void* const* d_in, const int* in_sizes, int n_in,
                              void* d_out, int out_size)
{
    const float* x    = (const float*)d_in[0];
    const float* w_aq = (const float*)d_in[1];
    const float* w_ak = (const float*)d_in[2];
    const float* w_av = (const float*)d_in[3];
    const float* w_ao = (const float*)d_in[4];
    float* out = (float*)d_out;

    float *q, *k, *v, *o;
    cudaGetSymbolAddress((void**)&q, g_q);
    cudaGetSymbolAddress((void**)&k, g_k);
    cudaGetSymbolAddress((void**)&v, g_v);
    cudaGetSymbolAddress((void**)&o, g_o);

    __nv_bfloat16 *xh, *xl, *oh, *ol;
    cudaGetSymbolAddress((void**)&xh, g_xh);
    cudaGetSymbolAddress((void**)&xl, g_xl);
    cudaGetSymbolAddress((void**)&oh, g_oh);
    cudaGetSymbolAddress((void**)&ol, g_ol);

    __nv_bfloat16 *wqh, *wql, *wkh, *wkl, *wvh, *wvl, *woh, *wol;
    cudaGetSymbolAddress((void**)&wqh, g_wqh);
    cudaGetSymbolAddress((void**)&wql, g_wql);
    cudaGetSymbolAddress((void**)&wkh, g_wkh);
    cudaGetSymbolAddress((void**)&wkl, g_wkl);
    cudaGetSymbolAddress((void**)&wvh, g_wvh);
    cudaGetSymbolAddress((void**)&wvl, g_wvl);
    cudaGetSymbolAddress((void**)&woh, g_woh);
    cudaGetSymbolAddress((void**)&wol, g_wol);

    // Weight transpose+split: per head [2048,128] -> [128,2048]
    dim3 tb(32, 8);
    dim3 tgw(D_ / 32, M_ / 32, H_);
    tsplit_kernel<<<tgw, tb>>>(w_aq, (long)M_ * D_, wqh, wql, (long)D_ * M_, M_, D_);
    tsplit_kernel<<<tgw, tb>>>(w_ak, (long)M_ * D_, wkh, wkl, (long)D_ * M_, M_, D_);
    tsplit_kernel<<<tgw, tb>>>(w_av, (long)M_ * D_, wvh, wvl, (long)D_ * M_, M_, D_);
    // w_ao flattened [2048(k=h*d), 2048(m)] -> [2048(m), 2048(k)]
    dim3 tgo(M_ / 32, M_ / 32, 1);
    tsplit_kernel<<<tgo, tb>>>(w_ao, 0L, woh, wol, 0L, M_, M_);

    // Split x
    split_kernel<<<(BT_ * M_ / 4 + 255) / 256, 256>>>(x, xh, xl, BT_ * M_ / 4);

    // QKV projection GEMMs on HMMA tensor cores
    cudaFuncSetAttribute(gemm_mma, cudaFuncAttributeMaxDynamicSharedMemorySize,
                         GEMM_SMEM);
    dim3 gg(BT_ / 128, M_ / 128, 3);
    gemm_mma<<<gg, 256, GEMM_SMEM>>>(xh, xl, wqh, wql, wkh, wkl, wvh, wvl, q, k, v);

    // RoPE on q, k
    rope_kernel<<<BT_, 1024>>>(q, k);

    // Flash attention
    size_t smem = (size_t)ATTN_SMEM_FLOATS * sizeof(float);
    cudaFuncSetAttribute(attn_kernel, cudaFuncAttributeMaxDynamicSharedMemorySize,
                         (int)smem);
    dim3 ga(T_ / 64, H_, B_);
    attn_kernel<<<ga, 256, smem>>>(q, k, v, o);

    // Split o, then output projection on HMMA tensor cores
    split_kernel<<<(BT_ * M_ / 4 + 255) / 256, 256>>>(o, oh, ol, BT_ * M_ / 4);
    dim3 gg2(BT_ / 128, M_ / 128, 1);
    gemm_mma<<<gg2, 256, GEMM_SMEM>>>(oh, ol, woh, wol, woh, wol, woh, wol,
                                      out, out, out);
}

// round 4
// speedup vs baseline: 2.4562x; 1.6007x over previous
#include <cuda_runtime.h>
#include <cuda_bf16.h>
#include <math.h>
#include <stdint.h>

#define B_  2
#define T_  2048
#define M_  2048
#define H_  16
#define D_  128
#define BT_ (B_ * T_)
#define K_  M_

// ---------------------------------------------------------------------------
// Scratch (device globals: allocation-free per harness rules)
// ---------------------------------------------------------------------------
__device__ float g_q[(size_t)BT_ * H_ * D_];
__device__ float g_k[(size_t)BT_ * H_ * D_];
__device__ float g_v[(size_t)BT_ * H_ * D_];

__device__ __nv_bfloat16 g_qh[(size_t)BT_ * M_];
__device__ __nv_bfloat16 g_kh[(size_t)BT_ * M_];
__device__ __nv_bfloat16 g_vh[(size_t)BT_ * M_];
__device__ __nv_bfloat16 g_vl[(size_t)BT_ * M_];

__device__ __nv_bfloat16 g_xh[(size_t)BT_ * M_];
__device__ __nv_bfloat16 g_xl[(size_t)BT_ * M_];
__device__ __nv_bfloat16 g_oh[(size_t)BT_ * M_];
__device__ __nv_bfloat16 g_ol[(size_t)BT_ * M_];

__device__ __nv_bfloat16 g_wqh[(size_t)H_ * D_ * M_];
__device__ __nv_bfloat16 g_wql[(size_t)H_ * D_ * M_];
__device__ __nv_bfloat16 g_wkh[(size_t)H_ * D_ * M_];
__device__ __nv_bfloat16 g_wkl[(size_t)H_ * D_ * M_];
__device__ __nv_bfloat16 g_wvh[(size_t)H_ * D_ * M_];
__device__ __nv_bfloat16 g_wvl[(size_t)H_ * D_ * M_];
__device__ __nv_bfloat16 g_woh[(size_t)M_ * M_];
__device__ __nv_bfloat16 g_wol[(size_t)M_ * M_];

// ---------------------------------------------------------------------------
// PTX helpers (sm_80-class only: legal under plain sm_103 target)
// ---------------------------------------------------------------------------
__device__ __forceinline__ uint32_t s2u(const void* p) {
    uint32_t a;
    asm("{ .reg .u64 t; cvta.to.shared.u64 t, %1; cvt.u32.u64 %0, t; }"
        : "=r"(a) : "l"(p));
    return a;
}

__device__ __forceinline__ void cp16(uint32_t dst, const void* src) {
    asm volatile("cp.async.cg.shared.global [%0], [%1], 16;"
                 :: "r"(dst), "l"(src) : "memory");
}

#define LDSM4(r, a) \
    asm volatile("ldmatrix.sync.aligned.m8n8.x4.shared.b16 {%0,%1,%2,%3}, [%4];" \
                 : "=r"((r)[0]), "=r"((r)[1]), "=r"((r)[2]), "=r"((r)[3])        \
                 : "r"(a))

#define LDSM4T(r, a) \
    asm volatile("ldmatrix.sync.aligned.m8n8.x4.trans.shared.b16 {%0,%1,%2,%3}, [%4];" \
                 : "=r"((r)[0]), "=r"((r)[1]), "=r"((r)[2]), "=r"((r)[3])              \
                 : "r"(a))

__device__ __forceinline__ void mma16816(float* d, const uint32_t* a,
                                         uint32_t b0, uint32_t b1) {
    asm volatile(
        "mma.sync.aligned.m16n8k16.row.col.f32.bf16.bf16.f32 "
        "{%0,%1,%2,%3}, {%4,%5,%6,%7}, {%8,%9}, {%0,%1,%2,%3};"
        : "+f"(d[0]), "+f"(d[1]), "+f"(d[2]), "+f"(d[3])
        : "r"(a[0]), "r"(a[1]), "r"(a[2]), "r"(a[3]), "r"(b0), "r"(b1));
}

__device__ __forceinline__ uint32_t packbf(float x, float y) {
    __nv_bfloat162 t = __halves2bfloat162(__float2bfloat16(x), __float2bfloat16(y));
    return *(uint32_t*)&t;
}

// ---------------------------------------------------------------------------
// Split conversion: fp32 -> (hi, lo) bf16
// ---------------------------------------------------------------------------
__global__ __launch_bounds__(256) void split_kernel(
    const float* __restrict__ x, __nv_bfloat16* __restrict__ h,
    __nv_bfloat16* __restrict__ l, int n4)
{
    int i = blockIdx.x * blockDim.x + threadIdx.x;
    if (i >= n4) return;
    float4 v = ((const float4*)x)[i];
    __nv_bfloat16 h0 = __float2bfloat16(v.x);
    __nv_bfloat16 h1 = __float2bfloat16(v.y);
    __nv_bfloat16 h2 = __float2bfloat16(v.z);
    __nv_bfloat16 h3 = __float2bfloat16(v.w);
    __nv_bfloat16 l0 = __float2bfloat16(v.x - __bfloat162float(h0));
    __nv_bfloat16 l1 = __float2bfloat16(v.y - __bfloat162float(h1));
    __nv_bfloat16 l2 = __float2bfloat16(v.z - __bfloat162float(h2));
    __nv_bfloat16 l3 = __float2bfloat16(v.w - __bfloat162float(h3));
    __nv_bfloat162* H = (__nv_bfloat162*)h;
    __nv_bfloat162* L = (__nv_bfloat162*)l;
    H[2*i]   = __halves2bfloat162(h0, h1);
    H[2*i+1] = __halves2bfloat162(h2, h3);
    L[2*i]   = __halves2bfloat162(l0, l1);
    L[2*i+1] = __halves2bfloat162(l2, l3);
}

// ---------------------------------------------------------------------------
// Transpose + split: src [R, C] fp32 (per-z panel) -> dst [C, R] hi/lo bf16
// ---------------------------------------------------------------------------
__global__ __launch_bounds__(256) void tsplit_kernel(
    const float* __restrict__ src, long srcZ,
    __nv_bfloat16* __restrict__ dh, __nv_bfloat16* __restrict__ dl, long dstZ,
    int R, int C)
{
    __shared__ float t[32][33];
    src += (size_t)blockIdx.z * srcZ;
    dh  += (size_t)blockIdx.z * dstZ;
    dl  += (size_t)blockIdx.z * dstZ;
    int c0 = blockIdx.x * 32, r0 = blockIdx.y * 32;
    int tx = threadIdx.x, ty = threadIdx.y;  // 32 x 8
#pragma unroll
    for (int j = 0; j < 4; j++)
        t[ty + 8*j][tx] = src[(size_t)(r0 + ty + 8*j) * C + c0 + tx];
    __syncthreads();
#pragma unroll
    for (int j = 0; j < 4; j++) {
        float v = t[tx][ty + 8*j];
        __nv_bfloat16 hi = __float2bfloat16(v);
        __nv_bfloat16 lo = __float2bfloat16(v - __bfloat162float(hi));
        size_t o = (size_t)(c0 + ty + 8*j) * R + r0 + tx;
        dh[o] = hi;
        dl[o] = lo;
    }
}

// ---------------------------------------------------------------------------
// HMMA GEMM (unchanged from round 3): 128x128 tile, BK=32, 3-stage cp.async
// ---------------------------------------------------------------------------
#define ROWB      80
#define MAT_BYTES (128 * ROWB)
#define STG_BYTES (4 * MAT_BYTES)
#define NSTG      3
#define GEMM_SMEM (NSTG * STG_BYTES)
#define KSTEPS    (K_ / 32)

__device__ __forceinline__ void load_stage(
    uint32_t buf,
    const __nv_bfloat16* __restrict__ Ah, const __nv_bfloat16* __restrict__ Al,
    const __nv_bfloat16* __restrict__ Bh, const __nv_bfloat16* __restrict__ Bl,
    int k0, int tid)
{
#pragma unroll
    for (int it = 0; it < 2; it++) {
        int idx = tid + it * 256;
        int row = idx >> 2, c = idx & 3;
        uint32_t so = (uint32_t)(row * ROWB + c * 16);
        const size_t go = (size_t)row * K_ + k0 + c * 8;
        cp16(buf + so,                 Ah + go);
        cp16(buf + MAT_BYTES + so,     Al + go);
        cp16(buf + 2 * MAT_BYTES + so, Bh + go);
        cp16(buf + 3 * MAT_BYTES + so, Bl + go);
    }
}

__global__ __launch_bounds__(256) void gemm_mma(
    const __nv_bfloat16* __restrict__ Ah, const __nv_bfloat16* __restrict__ Al,
    const __nv_bfloat16* __restrict__ B0h, const __nv_bfloat16* __restrict__ B0l,
    const __nv_bfloat16* __restrict__ B1h, const __nv_bfloat16* __restrict__ B1l,
    const __nv_bfloat16* __restrict__ B2h, const __nv_bfloat16* __restrict__ B2l,
    float* __restrict__ C0, float* __restrict__ C1, float* __restrict__ C2)
{
    extern __shared__ char smraw[];
    const uint32_t sb = s2u(smraw);
    const int tid = threadIdx.x;
    const int wid = tid >> 5, lane = tid & 31;
    const int warp_m = wid >> 2;
    const int warp_n = wid & 3;

    const __nv_bfloat16 *Bh, *Bl;
    float* C;
    if (blockIdx.z == 0)      { Bh = B0h; Bl = B0l; C = C0; }
    else if (blockIdx.z == 1) { Bh = B1h; Bl = B1l; C = C1; }
    else                      { Bh = B2h; Bl = B2l; C = C2; }

    const int row0 = blockIdx.x * 128;
    const int col0 = blockIdx.y * 128;
    Ah += (size_t)row0 * K_;  Al += (size_t)row0 * K_;
    Bh += (size_t)col0 * K_;  Bl += (size_t)col0 * K_;

    load_stage(sb,             Ah, Al, Bh, Bl, 0,  tid);
    asm volatile("cp.async.commit_group;" ::: "memory");
    load_stage(sb + STG_BYTES, Ah, Al, Bh, Bl, 32, tid);
    asm volatile("cp.async.commit_group;" ::: "memory");

    float acc[4][4][4];
#pragma unroll
    for (int i = 0; i < 4; i++)
#pragma unroll
        for (int j = 0; j < 4; j++)
#pragma unroll
            for (int r = 0; r < 4; r++) acc[i][j][r] = 0.f;

    const int lrow = lane & 15;
    const int lchk = (lane >> 4) * 16;

    for (int s = 0; s < KSTEPS; s++) {
        if (s + 1 < KSTEPS)
            asm volatile("cp.async.wait_group 1;" ::: "memory");
        else
            asm volatile("cp.async.wait_group 0;" ::: "memory");
        __syncthreads();

        if (s + 2 < KSTEPS) {
            load_stage(sb + (uint32_t)((s + 2) % NSTG) * STG_BYTES,
                       Ah, Al, Bh, Bl, (s + 2) * 32, tid);
            asm volatile("cp.async.commit_group;" ::: "memory");
        }

        const uint32_t base = sb + (uint32_t)(s % NSTG) * STG_BYTES;

#pragma unroll
        for (int kh = 0; kh < 2; kh++) {
            const uint32_t koff = (uint32_t)(kh * 32 + lchk);

            uint32_t a_hi[4][4], a_lo[4][4];
#pragma unroll
            for (int mi = 0; mi < 4; mi++) {
                uint32_t ad = base +
                    (uint32_t)((warp_m * 64 + mi * 16 + lrow) * ROWB) + koff;
                LDSM4(a_hi[mi], ad);
                LDSM4(a_lo[mi], ad + MAT_BYTES);
            }
            uint32_t b_hi[2][4], b_lo[2][4];
#pragma unroll
            for (int bj = 0; bj < 2; bj++) {
                uint32_t bd = base + 2 * MAT_BYTES +
                    (uint32_t)((warp_n * 32 + bj * 16 + lrow) * ROWB) + koff;
                LDSM4(b_hi[bj], bd);
                LDSM4(b_lo[bj], bd + MAT_BYTES);
            }
#pragma unroll
            for (int mi = 0; mi < 4; mi++) {
#pragma unroll
                for (int ni = 0; ni < 4; ni++) {
                    const int bj = ni >> 1, sel = ni & 1;
                    mma16816(acc[mi][ni], a_hi[mi], b_hi[bj][sel], b_hi[bj][sel + 2]);
                    mma16816(acc[mi][ni], a_hi[mi], b_lo[bj][sel], b_lo[bj][sel + 2]);
                    mma16816(acc[mi][ni], a_lo[mi], b_hi[bj][sel], b_hi[bj][sel + 2]);
                }
            }
        }
    }

    const int grp = lane >> 2, tig = lane & 3;
#pragma unroll
    for (int mi = 0; mi < 4; mi++) {
#pragma unroll
        for (int ni = 0; ni < 4; ni++) {
            int r = row0 + warp_m * 64 + mi * 16 + grp;
            int c = col0 + warp_n * 32 + ni * 8 + tig * 2;
            *(float2*)(C + (size_t)r * M_ + c) =
                make_float2(acc[mi][ni][0], acc[mi][ni][1]);
            *(float2*)(C + (size_t)(r + 8) * M_ + c) =
                make_float2(acc[mi][ni][2], acc[mi][ni][3]);
        }
    }
}

// ---------------------------------------------------------------------------
// RoPE + split: fp32 q,k,v -> bf16 qh (scaled 1/128), kh, vh/vl
// ---------------------------------------------------------------------------
__global__ __launch_bounds__(1024) void rope_split_kernel(
    const float* __restrict__ q, const float* __restrict__ k,
    const float* __restrict__ v,
    __nv_bfloat16* __restrict__ qh, __nv_bfloat16* __restrict__ kh,
    __nv_bfloat16* __restrict__ vh, __nv_bfloat16* __restrict__ vl)
{
    const int bt = blockIdx.x;
    const int t  = bt % T_;
    const int h  = threadIdx.x >> 6;
    const int d  = threadIdx.x & 63;

    float freq = powf(10000.0f, -(float)d * (1.0f / 64.0f));
    float ang  = (float)t * freq;
    float s, c;
    sincosf(ang, &s, &c);

    const size_t base = ((size_t)bt * H_ + h) * D_ + d;

    float qe = q[base], qo = q[base + 64];
    qh[base]      = __float2bfloat16((qe * c - qo * s) * (1.0f / 128.0f));
    qh[base + 64] = __float2bfloat16((qe * s + qo * c) * (1.0f / 128.0f));

    float ke = k[base], ko = k[base + 64];
    kh[base]      = __float2bfloat16(ke * c - ko * s);
    kh[base + 64] = __float2bfloat16(ke * s + ko * c);

    float v0 = v[base], v1 = v[base + 64];
    __nv_bfloat16 a0 = __float2bfloat16(v0);
    __nv_bfloat16 a1 = __float2bfloat16(v1);
    vh[base]      = a0;
    vl[base]      = __float2bfloat16(v0 - __bfloat162float(a0));
    vh[base + 64] = a1;
    vl[base + 64] = __float2bfloat16(v1 - __bfloat162float(a1));
}

// ---------------------------------------------------------------------------
// HMMA causal flash attention: 128q x 64kv tiles, D=128, 256 threads/8 warps.
// S = Qh*Kh^T (1 product); PV = Phi*Vh + Plo*Vh + Phi*Vl (3 products).
// 3-stage cp.async for K/V, Q resident. Writes bf16 hi/lo output directly.
// ---------------------------------------------------------------------------
#define AROWB 272
#define AMAT  (64 * AROWB)            // 17408
#define ASTG  (3 * AMAT)              // 52224 (Kh, Vh, Vl)
#define QBYT  (128 * AROWB)           // 34816
#define ATTN_SMEM (QBYT + 3 * ASTG)   // 191488

__device__ __forceinline__ void attn_load_kv(
    uint32_t dst, const __nv_bfloat16* __restrict__ kh,
    const __nv_bfloat16* __restrict__ vh, const __nv_bfloat16* __restrict__ vl,
    int b, int h, int j0, int tid)
{
#pragma unroll
    for (int it = 0; it < 4; it++) {
        int idx = tid + it * 256;       // 0..1023
        int r = idx >> 4, c = idx & 15;
        size_t go = ((size_t)(b * T_ + j0 + r) * H_ + h) * D_ + c * 8;
        uint32_t so = (uint32_t)(r * AROWB + c * 16);
        cp16(dst + so,            kh + go);
        cp16(dst + AMAT + so,     vh + go);
        cp16(dst + 2 * AMAT + so, vl + go);
    }
}

__global__ __launch_bounds__(256, 1) void attn_mma(
    const __nv_bfloat16* __restrict__ qh, const __nv_bfloat16* __restrict__ kh,
    const __nv_bfloat16* __restrict__ vh, const __nv_bfloat16* __restrict__ vl,
    __nv_bfloat16* __restrict__ oh, __nv_bfloat16* __restrict__ ol)
{
    extern __shared__ char smraw[];
    const uint32_t sb = s2u(smraw);
    const int tid = threadIdx.x, wid = tid >> 5, lane = tid & 31;
    const int qi = (int)gridDim.x - 1 - (int)blockIdx.x;  // heavy tiles first
    const int h = blockIdx.y, b = blockIdx.z;
    const int i0 = qi * 128;
    const int numkv = (qi + 1) * 2;

    // Q tile load (grouped with kv stage 0)
    const __nv_bfloat16* Qp = qh + ((size_t)(b * T_ + i0) * H_ + h) * D_;
#pragma unroll
    for (int it = 0; it < 8; it++) {
        int idx = tid + it * 256;
        int r = idx >> 4, c = idx & 15;
        cp16(sb + (uint32_t)(r * AROWB + c * 16),
             Qp + (size_t)r * (H_ * D_) + c * 8);
    }
    const uint32_t kvb = sb + QBYT;
    attn_load_kv(kvb,        kh, vh, vl, b, h, 0,  tid);
    asm volatile("cp.async.commit_group;" ::: "memory");
    attn_load_kv(kvb + ASTG, kh, vh, vl, b, h, 64, tid);
    asm volatile("cp.async.commit_group;" ::: "memory");

    float oacc[16][4];
#pragma unroll
    for (int i = 0; i < 16; i++)
#pragma unroll
        for (int j = 0; j < 4; j++) oacc[i][j] = 0.f;
    float m0 = -3.0e38f, m1 = -3.0e38f, l0 = 0.f, l1 = 0.f;

    const int lrow = lane & 15, lchk = (lane >> 4) * 16;
    const int grp = lane >> 2, tig = lane & 3;
    const int wrow = i0 + wid * 16;
    const int row0g = wrow + grp, row1g = row0g + 8;
    const uint32_t qln = sb + (uint32_t)((wid * 16 + lrow) * AROWB + lchk);

    for (int s = 0; s < numkv; s++) {
        if (s + 1 < numkv)
            asm volatile("cp.async.wait_group 1;" ::: "memory");
        else
            asm volatile("cp.async.wait_group 0;" ::: "memory");
        __syncthreads();
        if (s + 2 < numkv) {
            attn_load_kv(kvb + (uint32_t)((s + 2) % 3) * ASTG,
                         kh, vh, vl, b, h, (s + 2) * 64, tid);
            asm volatile("cp.async.commit_group;" ::: "memory");
        }
        const uint32_t kbase = kvb + (uint32_t)(s % 3) * ASTG;
        const int j0 = s * 64;

        // ---- S = Qh * Kh^T ----
        float sacc[8][4];
#pragma unroll
        for (int i = 0; i < 8; i++)
#pragma unroll
            for (int j = 0; j < 4; j++) sacc[i][j] = 0.f;

        const uint32_t kln = kbase + (uint32_t)(lrow * AROWB + lchk);
#pragma unroll
        for (int kb = 0; kb < 8; kb++) {
            uint32_t a[4];
            LDSM4(a, qln + kb * 32);
#pragma unroll
            for (int ng = 0; ng < 4; ng++) {
                uint32_t bb[4];
                LDSM4(bb, kln + (uint32_t)(ng * (16 * AROWB)) + kb * 32);
                mma16816(sacc[2 * ng],     a, bb[0], bb[2]);
                mma16816(sacc[2 * ng + 1], a, bb[1], bb[3]);
            }
        }

        // ---- causal mask ----
        if (j0 + 63 > wrow) {
#pragma unroll
            for (int nb = 0; nb < 8; nb++) {
                int c0 = j0 + nb * 8 + tig * 2;
                if (c0     > row0g) sacc[nb][0] = -1e30f;
                if (c0 + 1 > row0g) sacc[nb][1] = -1e30f;
                if (c0     > row1g) sacc[nb][2] = -1e30f;
                if (c0 + 1 > row1g) sacc[nb][3] = -1e30f;
            }
        }

        // ---- online softmax ----
        float mx0 = -3.0e38f, mx1 = -3.0e38f;
#pragma unroll
        for (int nb = 0; nb < 8; nb++) {
            mx0 = fmaxf(mx0, fmaxf(sacc[nb][0], sacc[nb][1]));
            mx1 = fmaxf(mx1, fmaxf(sacc[nb][2], sacc[nb][3]));
        }
        mx0 = fmaxf(mx0, __shfl_xor_sync(0xffffffffu, mx0, 1));
        mx0 = fmaxf(mx0, __shfl_xor_sync(0xffffffffu, mx0, 2));
        mx1 = fmaxf(mx1, __shfl_xor_sync(0xffffffffu, mx1, 1));
        mx1 = fmaxf(mx1, __shfl_xor_sync(0xffffffffu, mx1, 2));
        float mn0 = fmaxf(m0, mx0), mn1 = fmaxf(m1, mx1);
        float al0 = __expf(m0 - mn0), al1 = __expf(m1 - mn1);
        m0 = mn0; m1 = mn1;
#pragma unroll
        for (int ng = 0; ng < 16; ng++) {
            oacc[ng][0] *= al0; oacc[ng][1] *= al0;
            oacc[ng][2] *= al1; oacc[ng][3] *= al1;
        }

        float rs0 = 0.f, rs1 = 0.f;
        uint32_t aPhi[4][4], aPlo[4][4];
#pragma unroll
        for (int kk = 0; kk < 4; kk++) {
#pragma unroll
            for (int hf = 0; hf < 2; hf++) {
                int nb = 2 * kk + hf;
                float p0 = __expf(sacc[nb][0] - m0);
                float p1 = __expf(sacc[nb][1] - m0);
                float p2 = __expf(sacc[nb][2] - m1);
                float p3 = __expf(sacc[nb][3] - m1);
                rs0 += p0 + p1;
                rs1 += p2 + p3;
                float h0 = __bfloat162float(__float2bfloat16(p0));
                float h1 = __bfloat162float(__float2bfloat16(p1));
                float h2 = __bfloat162float(__float2bfloat16(p2));
                float h3 = __bfloat162float(__float2bfloat16(p3));
                aPhi[kk][2 * hf]     = packbf(h0, h1);
                aPhi[kk][2 * hf + 1] = packbf(h2, h3);
                aPlo[kk][2 * hf]     = packbf(p0 - h0, p1 - h1);
                aPlo[kk][2 * hf + 1] = packbf(p2 - h2, p3 - h3);
            }
        }
        rs0 += __shfl_xor_sync(0xffffffffu, rs0, 1);
        rs0 += __shfl_xor_sync(0xffffffffu, rs0, 2);
        rs1 += __shfl_xor_sync(0xffffffffu, rs1, 1);
        rs1 += __shfl_xor_sync(0xffffffffu, rs1, 2);
        l0 = l0 * al0 + rs0;
        l1 = l1 * al1 + rs1;

        // ---- O += P * V (3-product split) ----
        const uint32_t vln = kbase + AMAT + (uint32_t)(lrow * AROWB + lchk);
#pragma unroll
        for (int kk = 0; kk < 4; kk++) {
            const uint32_t vrow = vln + (uint32_t)(kk * (16 * AROWB));
#pragma unroll
            for (int ng = 0; ng < 8; ng++) {
                uint32_t bh4[4], bl4[4];
                LDSM4T(bh4, vrow + ng * 32);
                LDSM4T(bl4, vrow + AMAT + ng * 32);
                mma16816(oacc[2 * ng],     aPhi[kk], bh4[0], bh4[1]);
                mma16816(oacc[2 * ng],     aPlo[kk], bh4[0], bh4[1]);
                mma16816(oacc[2 * ng],     aPhi[kk], bl4[0], bl4[1]);
                mma16816(oacc[2 * ng + 1], aPhi[kk], bh4[2], bh4[3]);
                mma16816(oacc[2 * ng + 1], aPlo[kk], bh4[2], bh4[3]);
                mma16816(oacc[2 * ng + 1], aPhi[kk], bl4[2], bl4[3]);
            }
        }
    }

    // ---- epilogue: O / l -> bf16 hi/lo ----
    const float inv0 = 1.0f / l0, inv1 = 1.0f / l1;
    const int orow0 = i0 + wid * 16 + grp;
    const size_t ob0 = ((size_t)(b * T_ + orow0) * H_ + h) * D_ + tig * 2;
    const size_t ob1 = ((size_t)(b * T_ + orow0 + 8) * H_ + h) * D_ + tig * 2;
#pragma unroll
    for (int ng = 0; ng < 16; ng++) {
        float v0 = oacc[ng][0] * inv0, v1 = oacc[ng][1] * inv0;
        float v2 = oacc[ng][2] * inv1, v3 = oacc[ng][3] * inv1;
        float h0 = __bfloat162float(__float2bfloat16(v0));
        float h1 = __bfloat162float(__float2bfloat16(v1));
        float h2 = __bfloat162float(__float2bfloat16(v2));
        float h3 = __bfloat162float(__float2bfloat16(v3));
        *(uint32_t*)(oh + ob0 + ng * 8) = packbf(h0, h1);
        *(uint32_t*)(ol + ob0 + ng * 8) = packbf(v0 - h0, v1 - h1);
        *(uint32_t*)(oh + ob1 + ng * 8) = packbf(h2, h3);
        *(uint32_t*)(ol + ob1 + ng * 8) = packbf(v2 - h2, v3 - h3);
    }
}

// ---------------------------------------------------------------------------
// Launch
// ---------------------------------------------------------------------------
extern "C" void kernel_launch(void* const* d_in, const int* in_sizes, int n_in,
                              void* d_out, int out_size)
{
    const float* x    = (const float*)d_in[0];
    const float* w_aq = (const float*)d_in[1];
    const float* w_ak = (const float*)d_in[2];
    const float* w_av = (const float*)d_in[3];
    const float* w_ao = (const float*)d_in[4];
    float* out = (float*)d_out;

    float *q, *k, *v;
    cudaGetSymbolAddress((void**)&q, g_q);
    cudaGetSymbolAddress((void**)&k, g_k);
    cudaGetSymbolAddress((void**)&v, g_v);

    __nv_bfloat16 *qh, *khp, *vhp, *vlp;
    cudaGetSymbolAddress((void**)&qh, g_qh);
    cudaGetSymbolAddress((void**)&khp, g_kh);
    cudaGetSymbolAddress((void**)&vhp, g_vh);
    cudaGetSymbolAddress((void**)&vlp, g_vl);

    __nv_bfloat16 *xh, *xl, *oh, *ol;
    cudaGetSymbolAddress((void**)&xh, g_xh);
    cudaGetSymbolAddress((void**)&xl, g_xl);
    cudaGetSymbolAddress((void**)&oh, g_oh);
    cudaGetSymbolAddress((void**)&ol, g_ol);

    __nv_bfloat16 *wqh, *wql, *wkh, *wkl, *wvh, *wvl, *woh, *wol;
    cudaGetSymbolAddress((void**)&wqh, g_wqh);
    cudaGetSymbolAddress((void**)&wql, g_wql);
    cudaGetSymbolAddress((void**)&wkh, g_wkh);
    cudaGetSymbolAddress((void**)&wkl, g_wkl);
    cudaGetSymbolAddress((void**)&wvh, g_wvh);
    cudaGetSymbolAddress((void**)&wvl, g_wvl);
    cudaGetSymbolAddress((void**)&woh, g_woh);
    cudaGetSymbolAddress((void**)&wol, g_wol);

    // Weight transpose+split
    dim3 tb(32, 8);
    dim3 tgw(D_ / 32, M_ / 32, H_);
    tsplit_kernel<<<tgw, tb>>>(w_aq, (long)M_ * D_, wqh, wql, (long)D_ * M_, M_, D_);
    tsplit_kernel<<<tgw, tb>>>(w_ak, (long)M_ * D_, wkh, wkl, (long)D_ * M_, M_, D_);
    tsplit_kernel<<<tgw, tb>>>(w_av, (long)M_ * D_, wvh, wvl, (long)D_ * M_, M_, D_);
    dim3 tgo(M_ / 32, M_ / 32, 1);
    tsplit_kernel<<<tgo, tb>>>(w_ao, 0L, woh, wol, 0L, M_, M_);

    // Split x
    split_kernel<<<(BT_ * M_ / 4 + 255) / 256, 256>>>(x, xh, xl, BT_ * M_ / 4);

    // QKV projections (HMMA)
    cudaFuncSetAttribute(gemm_mma, cudaFuncAttributeMaxDynamicSharedMemorySize,
                         GEMM_SMEM);
    dim3 gg(BT_ / 128, M_ / 128, 3);
    gemm_mma<<<gg, 256, GEMM_SMEM>>>(xh, xl, wqh, wql, wkh, wkl, wvh, wvl, q, k, v);

    // RoPE + bf16 split of q,k,v
    rope_split_kernel<<<BT_, 1024>>>(q, k, v, qh, khp, vhp, vlp);

    // HMMA flash attention -> oh/ol
    cudaFuncSetAttribute(attn_mma, cudaFuncAttributeMaxDynamicSharedMemorySize,
                         ATTN_SMEM);
    dim3 ga(T_ / 128, H_, B_);
    attn_mma<<<ga, 256, ATTN_SMEM>>>(qh, khp, vhp, vlp, oh, ol);

    // Output projection (HMMA)
    dim3 gg2(BT_ / 128, M_ / 128, 1);
    gemm_mma<<<gg2, 256, GEMM_SMEM>>>(oh, ol, woh, wol, woh, wol, woh, wol,
                                      out, out, out);
}

// round 5
// speedup vs baseline: 3.5952x; 1.4637x over previous
#include <cuda_runtime.h>
#include <cuda_fp16.h>
#include <math.h>
#include <stdint.h>

#define B_  2
#define T_  2048
#define M_  2048
#define H_  16
#define D_  128
#define BT_ (B_ * T_)
#define K_  M_

// ---------------------------------------------------------------------------
// Scratch (device globals: allocation-free per harness rules)
// ---------------------------------------------------------------------------
__device__ float g_q[(size_t)BT_ * H_ * D_];
__device__ float g_k[(size_t)BT_ * H_ * D_];
__device__ float g_v[(size_t)BT_ * H_ * D_];

__device__ __half g_qh[(size_t)BT_ * M_];
__device__ __half g_kh[(size_t)BT_ * M_];
__device__ __half g_vh[(size_t)BT_ * M_];
__device__ __half g_vl[(size_t)BT_ * M_];

__device__ __half g_xh[(size_t)BT_ * M_];
__device__ __half g_xl[(size_t)BT_ * M_];
__device__ __half g_oh[(size_t)BT_ * M_];
__device__ __half g_ol[(size_t)BT_ * M_];

__device__ __half g_wq[(size_t)H_ * D_ * M_];
__device__ __half g_wk[(size_t)H_ * D_ * M_];
__device__ __half g_wv[(size_t)H_ * D_ * M_];
__device__ __half g_wo[(size_t)M_ * M_];

// ---------------------------------------------------------------------------
// PTX helpers (sm_80-class only: legal under plain sm_103 target)
// ---------------------------------------------------------------------------
__device__ __forceinline__ uint32_t s2u(const void* p) {
    uint32_t a;
    asm("{ .reg .u64 t; cvta.to.shared.u64 t, %1; cvt.u32.u64 %0, t; }"
        : "=r"(a) : "l"(p));
    return a;
}

__device__ __forceinline__ void cp16(uint32_t dst, const void* src) {
    asm volatile("cp.async.cg.shared.global [%0], [%1], 16;"
                 :: "r"(dst), "l"(src) : "memory");
}

#define LDSM4(r, a) \
    asm volatile("ldmatrix.sync.aligned.m8n8.x4.shared.b16 {%0,%1,%2,%3}, [%4];" \
                 : "=r"((r)[0]), "=r"((r)[1]), "=r"((r)[2]), "=r"((r)[3])        \
                 : "r"(a))

#define LDSM4T(r, a) \
    asm volatile("ldmatrix.sync.aligned.m8n8.x4.trans.shared.b16 {%0,%1,%2,%3}, [%4];" \
                 : "=r"((r)[0]), "=r"((r)[1]), "=r"((r)[2]), "=r"((r)[3])              \
                 : "r"(a))

__device__ __forceinline__ void mma16816(float* d, const uint32_t* a,
                                         uint32_t b0, uint32_t b1) {
    asm volatile(
        "mma.sync.aligned.m16n8k16.row.col.f32.f16.f16.f32 "
        "{%0,%1,%2,%3}, {%4,%5,%6,%7}, {%8,%9}, {%0,%1,%2,%3};"
        : "+f"(d[0]), "+f"(d[1]), "+f"(d[2]), "+f"(d[3])
        : "r"(a[0]), "r"(a[1]), "r"(a[2]), "r"(a[3]), "r"(b0), "r"(b1));
}

__device__ __forceinline__ uint32_t packh(float x, float y) {
    __half2 t = __halves2half2(__float2half_rn(x), __float2half_rn(y));
    return *(uint32_t*)&t;
}

// ---------------------------------------------------------------------------
// Split conversion: fp32 -> (hi, lo) fp16
// ---------------------------------------------------------------------------
__global__ __launch_bounds__(256) void split_kernel(
    const float* __restrict__ x, __half* __restrict__ h,
    __half* __restrict__ l, int n4)
{
    int i = blockIdx.x * blockDim.x + threadIdx.x;
    if (i >= n4) return;
    float4 v = ((const float4*)x)[i];
    float h0 = __half2float(__float2half_rn(v.x));
    float h1 = __half2float(__float2half_rn(v.y));
    float h2 = __half2float(__float2half_rn(v.z));
    float h3 = __half2float(__float2half_rn(v.w));
    uint32_t* H = (uint32_t*)h;
    uint32_t* L = (uint32_t*)l;
    H[2*i]   = packh(h0, h1);
    H[2*i+1] = packh(h2, h3);
    L[2*i]   = packh(v.x - h0, v.y - h1);
    L[2*i+1] = packh(v.z - h2, v.w - h3);
}

// ---------------------------------------------------------------------------
// Transpose + convert: src [R, C] fp32 (per-z panel) -> dst [C, R] fp16
// ---------------------------------------------------------------------------
__global__ __launch_bounds__(256) void tconv_kernel(
    const float* __restrict__ src, long srcZ,
    __half* __restrict__ dh, long dstZ, int R, int C)
{
    __shared__ float t[32][33];
    src += (size_t)blockIdx.z * srcZ;
    dh  += (size_t)blockIdx.z * dstZ;
    int c0 = blockIdx.x * 32, r0 = blockIdx.y * 32;
    int tx = threadIdx.x, ty = threadIdx.y;  // 32 x 8
#pragma unroll
    for (int j = 0; j < 4; j++)
        t[ty + 8*j][tx] = src[(size_t)(r0 + ty + 8*j) * C + c0 + tx];
    __syncthreads();
#pragma unroll
    for (int j = 0; j < 4; j++) {
        float v = t[tx][ty + 8*j];
        dh[(size_t)(c0 + ty + 8*j) * R + r0 + tx] = __float2half_rn(v);
    }
}

// ---------------------------------------------------------------------------
// HMMA GEMM (2-product fp16): C[128x128] = (Ah+Al)[128,K] @ B[128,K]^T
// A split hi/lo; B single fp16 (pre-transposed). BK=32, 3-stage cp.async.
// ---------------------------------------------------------------------------
#define ROWB      80
#define MAT_BYTES (128 * ROWB)       // 10240
#define STG_BYTES (3 * MAT_BYTES)    // 30720 (Ah, Al, B)
#define NSTG      3
#define GEMM_SMEM (NSTG * STG_BYTES) // 92160
#define KSTEPS    (K_ / 32)

__device__ __forceinline__ void load_stage(
    uint32_t buf,
    const __half* __restrict__ Ah, const __half* __restrict__ Al,
    const __half* __restrict__ B, int k0, int tid)
{
#pragma unroll
    for (int it = 0; it < 2; it++) {
        int idx = tid + it * 256;
        int row = idx >> 2, c = idx & 3;
        uint32_t so = (uint32_t)(row * ROWB + c * 16);
        const size_t go = (size_t)row * K_ + k0 + c * 8;
        cp16(buf + so,                 Ah + go);
        cp16(buf + MAT_BYTES + so,     Al + go);
        cp16(buf + 2 * MAT_BYTES + so, B  + go);
    }
}

__global__ __launch_bounds__(256) void gemm_mma(
    const __half* __restrict__ Ah, const __half* __restrict__ Al,
    const __half* __restrict__ B0, const __half* __restrict__ B1,
    const __half* __restrict__ B2,
    float* __restrict__ C0, float* __restrict__ C1, float* __restrict__ C2)
{
    extern __shared__ char smraw[];
    const uint32_t sb = s2u(smraw);
    const int tid = threadIdx.x;
    const int wid = tid >> 5, lane = tid & 31;
    const int warp_m = wid >> 2;
    const int warp_n = wid & 3;

    const __half* B;
    float* C;
    if (blockIdx.z == 0)      { B = B0; C = C0; }
    else if (blockIdx.z == 1) { B = B1; C = C1; }
    else                      { B = B2; C = C2; }

    const int row0 = blockIdx.x * 128;
    const int col0 = blockIdx.y * 128;
    Ah += (size_t)row0 * K_;  Al += (size_t)row0 * K_;
    B  += (size_t)col0 * K_;

    load_stage(sb,             Ah, Al, B, 0,  tid);
    asm volatile("cp.async.commit_group;" ::: "memory");
    load_stage(sb + STG_BYTES, Ah, Al, B, 32, tid);
    asm volatile("cp.async.commit_group;" ::: "memory");

    float acc[4][4][4];
#pragma unroll
    for (int i = 0; i < 4; i++)
#pragma unroll
        for (int j = 0; j < 4; j++)
#pragma unroll
            for (int r = 0; r < 4; r++) acc[i][j][r] = 0.f;

    const int lrow = lane & 15;
    const int lchk = (lane >> 4) * 16;

    for (int s = 0; s < KSTEPS; s++) {
        if (s + 1 < KSTEPS)
            asm volatile("cp.async.wait_group 1;" ::: "memory");
        else
            asm volatile("cp.async.wait_group 0;" ::: "memory");
        __syncthreads();

        if (s + 2 < KSTEPS) {
            load_stage(sb + (uint32_t)((s + 2) % NSTG) * STG_BYTES,
                       Ah, Al, B, (s + 2) * 32, tid);
            asm volatile("cp.async.commit_group;" ::: "memory");
        }

        const uint32_t base = sb + (uint32_t)(s % NSTG) * STG_BYTES;

#pragma unroll
        for (int kh = 0; kh < 2; kh++) {
            const uint32_t koff = (uint32_t)(kh * 32 + lchk);

            uint32_t a_hi[4][4], a_lo[4][4];
#pragma unroll
            for (int mi = 0; mi < 4; mi++) {
                uint32_t ad = base +
                    (uint32_t)((warp_m * 64 + mi * 16 + lrow) * ROWB) + koff;
                LDSM4(a_hi[mi], ad);
                LDSM4(a_lo[mi], ad + MAT_BYTES);
            }
            uint32_t b4[2][4];
#pragma unroll
            for (int bj = 0; bj < 2; bj++) {
                uint32_t bd = base + 2 * MAT_BYTES +
                    (uint32_t)((warp_n * 32 + bj * 16 + lrow) * ROWB) + koff;
                LDSM4(b4[bj], bd);
            }
#pragma unroll
            for (int mi = 0; mi < 4; mi++) {
#pragma unroll
                for (int ni = 0; ni < 4; ni++) {
                    const int bj = ni >> 1, sel = ni & 1;
                    mma16816(acc[mi][ni], a_hi[mi], b4[bj][sel], b4[bj][sel + 2]);
                    mma16816(acc[mi][ni], a_lo[mi], b4[bj][sel], b4[bj][sel + 2]);
                }
            }
        }
    }

    const int grp = lane >> 2, tig = lane & 3;
#pragma unroll
    for (int mi = 0; mi < 4; mi++) {
#pragma unroll
        for (int ni = 0; ni < 4; ni++) {
            int r = row0 + warp_m * 64 + mi * 16 + grp;
            int c = col0 + warp_n * 32 + ni * 8 + tig * 2;
            *(float2*)(C + (size_t)r * M_ + c) =
                make_float2(acc[mi][ni][0], acc[mi][ni][1]);
            *(float2*)(C + (size_t)(r + 8) * M_ + c) =
                make_float2(acc[mi][ni][2], acc[mi][ni][3]);
        }
    }
}

// ---------------------------------------------------------------------------
// RoPE + convert: fp32 q,k,v -> fp16 qh (scaled 1/128), kh, vh/vl
// ---------------------------------------------------------------------------
__global__ __launch_bounds__(1024) void rope_split_kernel(
    const float* __restrict__ q, const float* __restrict__ k,
    const float* __restrict__ v,
    __half* __restrict__ qh, __half* __restrict__ kh,
    __half* __restrict__ vh, __half* __restrict__ vl)
{
    const int bt = blockIdx.x;
    const int t  = bt % T_;
    const int h  = threadIdx.x >> 6;
    const int d  = threadIdx.x & 63;

    float freq = powf(10000.0f, -(float)d * (1.0f / 64.0f));
    float ang  = (float)t * freq;
    float s, c;
    sincosf(ang, &s, &c);

    const size_t base = ((size_t)bt * H_ + h) * D_ + d;

    float qe = q[base], qo = q[base + 64];
    qh[base]      = __float2half_rn((qe * c - qo * s) * (1.0f / 128.0f));
    qh[base + 64] = __float2half_rn((qe * s + qo * c) * (1.0f / 128.0f));

    float ke = k[base], ko = k[base + 64];
    kh[base]      = __float2half_rn(ke * c - ko * s);
    kh[base + 64] = __float2half_rn(ke * s + ko * c);

    float v0 = v[base], v1 = v[base + 64];
    float a0 = __half2float(__float2half_rn(v0));
    float a1 = __half2float(__float2half_rn(v1));
    vh[base]      = __float2half_rn(v0);
    vl[base]      = __float2half_rn(v0 - a0);
    vh[base + 64] = __float2half_rn(v1);
    vl[base + 64] = __float2half_rn(v1 - a1);
}

// ---------------------------------------------------------------------------
// HMMA causal flash attention (fp16): 128q x 64kv tiles, D=128, 8 warps.
// S = Q*K^T (1 product); PV = Phi*Vh + Plo*Vh + Phi*Vl (3 products).
// ---------------------------------------------------------------------------
#define AROWB 272
#define AMAT  (64 * AROWB)
#define ASTG  (3 * AMAT)
#define QBYT  (128 * AROWB)
#define ATTN_SMEM (QBYT + 3 * ASTG)

__device__ __forceinline__ void attn_load_kv(
    uint32_t dst, const __half* __restrict__ kh,
    const __half* __restrict__ vh, const __half* __restrict__ vl,
    int b, int h, int j0, int tid)
{
#pragma unroll
    for (int it = 0; it < 4; it++) {
        int idx = tid + it * 256;
        int r = idx >> 4, c = idx & 15;
        size_t go = ((size_t)(b * T_ + j0 + r) * H_ + h) * D_ + c * 8;
        uint32_t so = (uint32_t)(r * AROWB + c * 16);
        cp16(dst + so,            kh + go);
        cp16(dst + AMAT + so,     vh + go);
        cp16(dst + 2 * AMAT + so, vl + go);
    }
}

__global__ __launch_bounds__(256, 1) void attn_mma(
    const __half* __restrict__ qh, const __half* __restrict__ kh,
    const __half* __restrict__ vh, const __half* __restrict__ vl,
    __half* __restrict__ oh, __half* __restrict__ ol)
{
    extern __shared__ char smraw[];
    const uint32_t sb = s2u(smraw);
    const int tid = threadIdx.x, wid = tid >> 5, lane = tid & 31;
    const int qi = (int)gridDim.x - 1 - (int)blockIdx.x;  // heavy tiles first
    const int h = blockIdx.y, b = blockIdx.z;
    const int i0 = qi * 128;
    const int numkv = (qi + 1) * 2;

    const __half* Qp = qh + ((size_t)(b * T_ + i0) * H_ + h) * D_;
#pragma unroll
    for (int it = 0; it < 8; it++) {
        int idx = tid + it * 256;
        int r = idx >> 4, c = idx & 15;
        cp16(sb + (uint32_t)(r * AROWB + c * 16),
             Qp + (size_t)r * (H_ * D_) + c * 8);
    }
    const uint32_t kvb = sb + QBYT;
    attn_load_kv(kvb,        kh, vh, vl, b, h, 0,  tid);
    asm volatile("cp.async.commit_group;" ::: "memory");
    attn_load_kv(kvb + ASTG, kh, vh, vl, b, h, 64, tid);
    asm volatile("cp.async.commit_group;" ::: "memory");

    float oacc[16][4];
#pragma unroll
    for (int i = 0; i < 16; i++)
#pragma unroll
        for (int j = 0; j < 4; j++) oacc[i][j] = 0.f;
    float m0 = -3.0e38f, m1 = -3.0e38f, l0 = 0.f, l1 = 0.f;

    const int lrow = lane & 15, lchk = (lane >> 4) * 16;
    const int grp = lane >> 2, tig = lane & 3;
    const int wrow = i0 + wid * 16;
    const int row0g = wrow + grp, row1g = row0g + 8;
    const uint32_t qln = sb + (uint32_t)((wid * 16 + lrow) * AROWB + lchk);

    for (int s = 0; s < numkv; s++) {
        if (s + 1 < numkv)
            asm volatile("cp.async.wait_group 1;" ::: "memory");
        else
            asm volatile("cp.async.wait_group 0;" ::: "memory");
        __syncthreads();
        if (s + 2 < numkv) {
            attn_load_kv(kvb + (uint32_t)((s + 2) % 3) * ASTG,
                         kh, vh, vl, b, h, (s + 2) * 64, tid);
            asm volatile("cp.async.commit_group;" ::: "memory");
        }
        const uint32_t kbase = kvb + (uint32_t)(s % 3) * ASTG;
        const int j0 = s * 64;

        // ---- S = Q * K^T ----
        float sacc[8][4];
#pragma unroll
        for (int i = 0; i < 8; i++)
#pragma unroll
            for (int j = 0; j < 4; j++) sacc[i][j] = 0.f;

        const uint32_t kln = kbase + (uint32_t)(lrow * AROWB + lchk);
#pragma unroll
        for (int kb = 0; kb < 8; kb++) {
            uint32_t a[4];
            LDSM4(a, qln + kb * 32);
#pragma unroll
            for (int ng = 0; ng < 4; ng++) {
                uint32_t bb[4];
                LDSM4(bb, kln + (uint32_t)(ng * (16 * AROWB)) + kb * 32);
                mma16816(sacc[2 * ng],     a, bb[0], bb[2]);
                mma16816(sacc[2 * ng + 1], a, bb[1], bb[3]);
            }
        }

        // ---- causal mask ----
        if (j0 + 63 > wrow) {
#pragma unroll
            for (int nb = 0; nb < 8; nb++) {
                int c0 = j0 + nb * 8 + tig * 2;
                if (c0     > row0g) sacc[nb][0] = -1e30f;
                if (c0 + 1 > row0g) sacc[nb][1] = -1e30f;
                if (c0     > row1g) sacc[nb][2] = -1e30f;
                if (c0 + 1 > row1g) sacc[nb][3] = -1e30f;
            }
        }

        // ---- online softmax ----
        float mx0 = -3.0e38f, mx1 = -3.0e38f;
#pragma unroll
        for (int nb = 0; nb < 8; nb++) {
            mx0 = fmaxf(mx0, fmaxf(sacc[nb][0], sacc[nb][1]));
            mx1 = fmaxf(mx1, fmaxf(sacc[nb][2], sacc[nb][3]));
        }
        mx0 = fmaxf(mx0, __shfl_xor_sync(0xffffffffu, mx0, 1));
        mx0 = fmaxf(mx0, __shfl_xor_sync(0xffffffffu, mx0, 2));
        mx1 = fmaxf(mx1, __shfl_xor_sync(0xffffffffu, mx1, 1));
        mx1 = fmaxf(mx1, __shfl_xor_sync(0xffffffffu, mx1, 2));
        float mn0 = fmaxf(m0, mx0), mn1 = fmaxf(m1, mx1);
        float al0 = __expf(m0 - mn0), al1 = __expf(m1 - mn1);
        m0 = mn0; m1 = mn1;
#pragma unroll
        for (int ng = 0; ng < 16; ng++) {
            oacc[ng][0] *= al0; oacc[ng][1] *= al0;
            oacc[ng][2] *= al1; oacc[ng][3] *= al1;
        }

        float rs0 = 0.f, rs1 = 0.f;
        uint32_t aPhi[4][4], aPlo[4][4];
#pragma unroll
        for (int kk = 0; kk < 4; kk++) {
#pragma unroll
            for (int hf = 0; hf < 2; hf++) {
                int nb = 2 * kk + hf;
                float p0 = __expf(sacc[nb][0] - m0);
                float p1 = __expf(sacc[nb][1] - m0);
                float p2 = __expf(sacc[nb][2] - m1);
                float p3 = __expf(sacc[nb][3] - m1);
                rs0 += p0 + p1;
                rs1 += p2 + p3;
                float h0 = __half2float(__float2half_rn(p0));
                float h1 = __half2float(__float2half_rn(p1));
                float h2 = __half2float(__float2half_rn(p2));
                float h3 = __half2float(__float2half_rn(p3));
                aPhi[kk][2 * hf]     = packh(h0, h1);
                aPhi[kk][2 * hf + 1] = packh(h2, h3);
                aPlo[kk][2 * hf]     = packh(p0 - h0, p1 - h1);
                aPlo[kk][2 * hf + 1] = packh(p2 - h2, p3 - h3);
            }
        }
        rs0 += __shfl_xor_sync(0xffffffffu, rs0, 1);
        rs0 += __shfl_xor_sync(0xffffffffu, rs0, 2);
        rs1 += __shfl_xor_sync(0xffffffffu, rs1, 1);
        rs1 += __shfl_xor_sync(0xffffffffu, rs1, 2);
        l0 = l0 * al0 + rs0;
        l1 = l1 * al1 + rs1;

        // ---- O += P * V (3-product split) ----
        const uint32_t vln = kbase + AMAT + (uint32_t)(lrow * AROWB + lchk);
#pragma unroll
        for (int kk = 0; kk < 4; kk++) {
            const uint32_t vrow = vln + (uint32_t)(kk * (16 * AROWB));
#pragma unroll
            for (int ng = 0; ng < 8; ng++) {
                uint32_t bh4[4], bl4[4];
                LDSM4T(bh4, vrow + ng * 32);
                LDSM4T(bl4, vrow + AMAT + ng * 32);
                mma16816(oacc[2 * ng],     aPhi[kk], bh4[0], bh4[1]);
                mma16816(oacc[2 * ng],     aPlo[kk], bh4[0], bh4[1]);
                mma16816(oacc[2 * ng],     aPhi[kk], bl4[0], bl4[1]);
                mma16816(oacc[2 * ng + 1], aPhi[kk], bh4[2], bh4[3]);
                mma16816(oacc[2 * ng + 1], aPlo[kk], bh4[2], bh4[3]);
                mma16816(oacc[2 * ng + 1], aPhi[kk], bl4[2], bl4[3]);
            }
        }
    }

    // ---- epilogue: O / l -> fp16 hi/lo ----
    const float inv0 = 1.0f / l0, inv1 = 1.0f / l1;
    const int orow0 = i0 + wid * 16 + grp;
    const size_t ob0 = ((size_t)(b * T_ + orow0) * H_ + h) * D_ + tig * 2;
    const size_t ob1 = ((size_t)(b * T_ + orow0 + 8) * H_ + h) * D_ + tig * 2;
#pragma unroll
    for (int ng = 0; ng < 16; ng++) {
        float v0 = oacc[ng][0] * inv0, v1 = oacc[ng][1] * inv0;
        float v2 = oacc[ng][2] * inv1, v3 = oacc[ng][3] * inv1;
        float h0 = __half2float(__float2half_rn(v0));
        float h1 = __half2float(__float2half_rn(v1));
        float h2 = __half2float(__float2half_rn(v2));
        float h3 = __half2float(__float2half_rn(v3));
        *(uint32_t*)(oh + ob0 + ng * 8) = packh(h0, h1);
        *(uint32_t*)(ol + ob0 + ng * 8) = packh(v0 - h0, v1 - h1);
        *(uint32_t*)(oh + ob1 + ng * 8) = packh(h2, h3);
        *(uint32_t*)(ol + ob1 + ng * 8) = packh(v2 - h2, v3 - h3);
    }
}

// ---------------------------------------------------------------------------
// Launch
// ---------------------------------------------------------------------------
extern "C" void kernel_launch(void* const* d_in, const int* in_sizes, int n_in,
                              void* d_out, int out_size)
{
    const float* x    = (const float*)d_in[0];
    const float* w_aq = (const float*)d_in[1];
    const float* w_ak = (const float*)d_in[2];
    const float* w_av = (const float*)d_in[3];
    const float* w_ao = (const float*)d_in[4];
    float* out = (float*)d_out;

    float *q, *k, *v;
    cudaGetSymbolAddress((void**)&q, g_q);
    cudaGetSymbolAddress((void**)&k, g_k);
    cudaGetSymbolAddress((void**)&v, g_v);

    __half *qh, *khp, *vhp, *vlp;
    cudaGetSymbolAddress((void**)&qh, g_qh);
    cudaGetSymbolAddress((void**)&khp, g_kh);
    cudaGetSymbolAddress((void**)&vhp, g_vh);
    cudaGetSymbolAddress((void**)&vlp, g_vl);

    __half *xh, *xl, *oh, *ol;
    cudaGetSymbolAddress((void**)&xh, g_xh);
    cudaGetSymbolAddress((void**)&xl, g_xl);
    cudaGetSymbolAddress((void**)&oh, g_oh);
    cudaGetSymbolAddress((void**)&ol, g_ol);

    __half *wq, *wk, *wv, *wo;
    cudaGetSymbolAddress((void**)&wq, g_wq);
    cudaGetSymbolAddress((void**)&wk, g_wk);
    cudaGetSymbolAddress((void**)&wv, g_wv);
    cudaGetSymbolAddress((void**)&wo, g_wo);

    // Weight transpose+convert (single fp16)
    dim3 tb(32, 8);
    dim3 tgw(D_ / 32, M_ / 32, H_);
    tconv_kernel<<<tgw, tb>>>(w_aq, (long)M_ * D_, wq, (long)D_ * M_, M_, D_);
    tconv_kernel<<<tgw, tb>>>(w_ak, (long)M_ * D_, wk, (long)D_ * M_, M_, D_);
    tconv_kernel<<<tgw, tb>>>(w_av, (long)M_ * D_, wv, (long)D_ * M_, M_, D_);
    dim3 tgo(M_ / 32, M_ / 32, 1);
    tconv_kernel<<<tgo, tb>>>(w_ao, 0L, wo, 0L, M_, M_);

    // Split x (hi/lo fp16)
    split_kernel<<<(BT_ * M_ / 4 + 255) / 256, 256>>>(x, xh, xl, BT_ * M_ / 4);

    // QKV projections (HMMA, 2-product)
    cudaFuncSetAttribute(gemm_mma, cudaFuncAttributeMaxDynamicSharedMemorySize,
                         GEMM_SMEM);
    dim3 gg(BT_ / 128, M_ / 128, 3);
    gemm_mma<<<gg, 256, GEMM_SMEM>>>(xh, xl, wq, wk, wv, q, k, v);

    // RoPE + fp16 conversion of q,k,v
    rope_split_kernel<<<BT_, 1024>>>(q, k, v, qh, khp, vhp, vlp);

    // HMMA flash attention -> oh/ol
    cudaFuncSetAttribute(attn_mma, cudaFuncAttributeMaxDynamicSharedMemorySize,
                         ATTN_SMEM);
    dim3 ga(T_ / 128, H_, B_);
    attn_mma<<<ga, 256, ATTN_SMEM>>>(qh, khp, vhp, vlp, oh, ol);

    // Output projection (HMMA, 2-product)
    dim3 gg2(BT_ / 128, M_ / 128, 1);
    gemm_mma<<<gg2, 256, GEMM_SMEM>>>(oh, ol, wo, wo, wo, out, out, out);
}

// round 6
// speedup vs baseline: 5.7180x; 1.5905x over previous
#include <cuda_runtime.h>
#include <cuda_fp16.h>
#include <math.h>
#include <stdint.h>

#define B_  2
#define T_  2048
#define M_  2048
#define H_  16
#define D_  128
#define BT_ (B_ * T_)
#define K_  M_

// ---------------------------------------------------------------------------
// Scratch (device globals: allocation-free per harness rules)
// ---------------------------------------------------------------------------
__device__ __half g_xh[(size_t)BT_ * M_];
__device__ __half g_qh[(size_t)BT_ * M_];
__device__ __half g_kh[(size_t)BT_ * M_];
__device__ __half g_vh[(size_t)BT_ * M_];
__device__ __half g_oh[(size_t)BT_ * M_];

__device__ __half g_wq[(size_t)H_ * D_ * M_];
__device__ __half g_wk[(size_t)H_ * D_ * M_];
__device__ __half g_wv[(size_t)H_ * D_ * M_];
__device__ __half g_wo[(size_t)M_ * M_];

// ---------------------------------------------------------------------------
// PTX helpers (sm_80-class only: legal under plain sm_103 target)
// ---------------------------------------------------------------------------
__device__ __forceinline__ uint32_t s2u(const void* p) {
    uint32_t a;
    asm("{ .reg .u64 t; cvta.to.shared.u64 t, %1; cvt.u32.u64 %0, t; }"
        : "=r"(a) : "l"(p));
    return a;
}

__device__ __forceinline__ void cp16(uint32_t dst, const void* src) {
    asm volatile("cp.async.cg.shared.global [%0], [%1], 16;"
                 :: "r"(dst), "l"(src) : "memory");
}

#define LDSM4(r, a) \
    asm volatile("ldmatrix.sync.aligned.m8n8.x4.shared.b16 {%0,%1,%2,%3}, [%4];" \
                 : "=r"((r)[0]), "=r"((r)[1]), "=r"((r)[2]), "=r"((r)[3])        \
                 : "r"(a))

#define LDSM4T(r, a) \
    asm volatile("ldmatrix.sync.aligned.m8n8.x4.trans.shared.b16 {%0,%1,%2,%3}, [%4];" \
                 : "=r"((r)[0]), "=r"((r)[1]), "=r"((r)[2]), "=r"((r)[3])              \
                 : "r"(a))

__device__ __forceinline__ void mma16816(float* d, const uint32_t* a,
                                         uint32_t b0, uint32_t b1) {
    asm volatile(
        "mma.sync.aligned.m16n8k16.row.col.f32.f16.f16.f32 "
        "{%0,%1,%2,%3}, {%4,%5,%6,%7}, {%8,%9}, {%0,%1,%2,%3};"
        : "+f"(d[0]), "+f"(d[1]), "+f"(d[2]), "+f"(d[3])
        : "r"(a[0]), "r"(a[1]), "r"(a[2]), "r"(a[3]), "r"(b0), "r"(b1));
}

__device__ __forceinline__ uint32_t packh(float x, float y) {
    __half2 t = __halves2half2(__float2half_rn(x), __float2half_rn(y));
    return *(uint32_t*)&t;
}

// ---------------------------------------------------------------------------
// Convert: fp32 -> fp16
// ---------------------------------------------------------------------------
__global__ __launch_bounds__(256) void conv_kernel(
    const float* __restrict__ x, __half* __restrict__ h, int n4)
{
    int i = blockIdx.x * blockDim.x + threadIdx.x;
    if (i >= n4) return;
    float4 v = ((const float4*)x)[i];
    uint32_t* H = (uint32_t*)h;
    H[2*i]   = packh(v.x, v.y);
    H[2*i+1] = packh(v.z, v.w);
}

// ---------------------------------------------------------------------------
// Transpose + convert: src [R, C] fp32 (per-z panel) -> dst [C, R] fp16
// ---------------------------------------------------------------------------
__global__ __launch_bounds__(256) void tconv_kernel(
    const float* __restrict__ src, long srcZ,
    __half* __restrict__ dh, long dstZ, int R, int C)
{
    __shared__ float t[32][33];
    src += (size_t)blockIdx.z * srcZ;
    dh  += (size_t)blockIdx.z * dstZ;
    int c0 = blockIdx.x * 32, r0 = blockIdx.y * 32;
    int tx = threadIdx.x, ty = threadIdx.y;  // 32 x 8
#pragma unroll
    for (int j = 0; j < 4; j++)
        t[ty + 8*j][tx] = src[(size_t)(r0 + ty + 8*j) * C + c0 + tx];
    __syncthreads();
#pragma unroll
    for (int j = 0; j < 4; j++) {
        float v = t[tx][ty + 8*j];
        dh[(size_t)(c0 + ty + 8*j) * R + r0 + tx] = __float2half_rn(v);
    }
}

// ---------------------------------------------------------------------------
// HMMA GEMM (single-product fp16): C[128x128] = A[128,K] @ B[128,K]^T
// B pre-transposed. BK=32, 3-stage cp.async. CT = __half or float.
// ---------------------------------------------------------------------------
#define ROWB      80
#define MAT_BYTES (128 * ROWB)       // 10240
#define STG_BYTES (2 * MAT_BYTES)    // 20480 (A, B)
#define NSTG      3
#define GEMM_SMEM (NSTG * STG_BYTES) // 61440
#define KSTEPS    (K_ / 32)

__device__ __forceinline__ void load_stage(
    uint32_t buf, const __half* __restrict__ A,
    const __half* __restrict__ B, int k0, int tid)
{
#pragma unroll
    for (int it = 0; it < 2; it++) {
        int idx = tid + it * 256;
        int row = idx >> 2, c = idx & 3;
        uint32_t so = (uint32_t)(row * ROWB + c * 16);
        const size_t go = (size_t)row * K_ + k0 + c * 8;
        cp16(buf + so,             A + go);
        cp16(buf + MAT_BYTES + so, B + go);
    }
}

template <typename CT>
__global__ __launch_bounds__(256) void gemm_mma(
    const __half* __restrict__ A,
    const __half* __restrict__ B0, const __half* __restrict__ B1,
    const __half* __restrict__ B2,
    CT* __restrict__ C0, CT* __restrict__ C1, CT* __restrict__ C2)
{
    extern __shared__ char smraw[];
    const uint32_t sb = s2u(smraw);
    const int tid = threadIdx.x;
    const int wid = tid >> 5, lane = tid & 31;
    const int warp_m = wid >> 2;
    const int warp_n = wid & 3;

    const __half* B;
    CT* C;
    if (blockIdx.z == 0)      { B = B0; C = C0; }
    else if (blockIdx.z == 1) { B = B1; C = C1; }
    else                      { B = B2; C = C2; }

    const int row0 = blockIdx.x * 128;
    const int col0 = blockIdx.y * 128;
    A += (size_t)row0 * K_;
    B += (size_t)col0 * K_;

    load_stage(sb,             A, B, 0,  tid);
    asm volatile("cp.async.commit_group;" ::: "memory");
    load_stage(sb + STG_BYTES, A, B, 32, tid);
    asm volatile("cp.async.commit_group;" ::: "memory");

    float acc[4][4][4];
#pragma unroll
    for (int i = 0; i < 4; i++)
#pragma unroll
        for (int j = 0; j < 4; j++)
#pragma unroll
            for (int r = 0; r < 4; r++) acc[i][j][r] = 0.f;

    const int lrow = lane & 15;
    const int lchk = (lane >> 4) * 16;

    for (int s = 0; s < KSTEPS; s++) {
        if (s + 1 < KSTEPS)
            asm volatile("cp.async.wait_group 1;" ::: "memory");
        else
            asm volatile("cp.async.wait_group 0;" ::: "memory");
        __syncthreads();

        if (s + 2 < KSTEPS) {
            load_stage(sb + (uint32_t)((s + 2) % NSTG) * STG_BYTES,
                       A, B, (s + 2) * 32, tid);
            asm volatile("cp.async.commit_group;" ::: "memory");
        }

        const uint32_t base = sb + (uint32_t)(s % NSTG) * STG_BYTES;

#pragma unroll
        for (int kh = 0; kh < 2; kh++) {
            const uint32_t koff = (uint32_t)(kh * 32 + lchk);

            uint32_t a4[4][4];
#pragma unroll
            for (int mi = 0; mi < 4; mi++) {
                uint32_t ad = base +
                    (uint32_t)((warp_m * 64 + mi * 16 + lrow) * ROWB) + koff;
                LDSM4(a4[mi], ad);
            }
            uint32_t b4[2][4];
#pragma unroll
            for (int bj = 0; bj < 2; bj++) {
                uint32_t bd = base + MAT_BYTES +
                    (uint32_t)((warp_n * 32 + bj * 16 + lrow) * ROWB) + koff;
                LDSM4(b4[bj], bd);
            }
#pragma unroll
            for (int mi = 0; mi < 4; mi++) {
#pragma unroll
                for (int ni = 0; ni < 4; ni++) {
                    const int bj = ni >> 1, sel = ni & 1;
                    mma16816(acc[mi][ni], a4[mi], b4[bj][sel], b4[bj][sel + 2]);
                }
            }
        }
    }

    const int grp = lane >> 2, tig = lane & 3;
#pragma unroll
    for (int mi = 0; mi < 4; mi++) {
#pragma unroll
        for (int ni = 0; ni < 4; ni++) {
            int r = row0 + warp_m * 64 + mi * 16 + grp;
            int c = col0 + warp_n * 32 + ni * 8 + tig * 2;
            if constexpr (sizeof(CT) == 2) {
                *(uint32_t*)(C + (size_t)r * M_ + c) =
                    packh(acc[mi][ni][0], acc[mi][ni][1]);
                *(uint32_t*)(C + (size_t)(r + 8) * M_ + c) =
                    packh(acc[mi][ni][2], acc[mi][ni][3]);
            } else {
                *(float2*)(C + (size_t)r * M_ + c) =
                    make_float2(acc[mi][ni][0], acc[mi][ni][1]);
                *(float2*)(C + (size_t)(r + 8) * M_ + c) =
                    make_float2(acc[mi][ni][2], acc[mi][ni][3]);
            }
        }
    }
}

// ---------------------------------------------------------------------------
// RoPE in-place on fp16 q (scaled 1/128) and k. Layout [bt][h][d], pairs (d, d+64).
// ---------------------------------------------------------------------------
__global__ __launch_bounds__(1024) void rope_h_kernel(
    __half* __restrict__ q, __half* __restrict__ k)
{
    const int bt = blockIdx.x;
    const int t  = bt % T_;
    const int h  = threadIdx.x >> 6;
    const int d  = threadIdx.x & 63;

    float freq = powf(10000.0f, -(float)d * (1.0f / 64.0f));
    float ang  = (float)t * freq;
    float s, c;
    sincosf(ang, &s, &c);

    const size_t base = ((size_t)bt * H_ + h) * D_ + d;

    float qe = __half2float(q[base]), qo = __half2float(q[base + 64]);
    q[base]      = __float2half_rn((qe * c - qo * s) * (1.0f / 128.0f));
    q[base + 64] = __float2half_rn((qe * s + qo * c) * (1.0f / 128.0f));

    float ke = __half2float(k[base]), ko = __half2float(k[base + 64]);
    k[base]      = __float2half_rn(ke * c - ko * s);
    k[base + 64] = __float2half_rn(ke * s + ko * c);
}

// ---------------------------------------------------------------------------
// HMMA causal flash attention (fp16): 128q x 64kv tiles, D=128, 8 warps.
// S = Q*K^T (1 product); PV = (Phi + Plo) * V (2 products).
// ---------------------------------------------------------------------------
#define AROWB 272
#define AMAT  (64 * AROWB)            // 17408
#define ASTG  (2 * AMAT)              // 34816 (Kh, Vh)
#define QBYT  (128 * AROWB)           // 34816
#define ATTN_SMEM (QBYT + 3 * ASTG)   // 139264

__device__ __forceinline__ void attn_load_kv(
    uint32_t dst, const __half* __restrict__ kh, const __half* __restrict__ vh,
    int b, int h, int j0, int tid)
{
#pragma unroll
    for (int it = 0; it < 4; it++) {
        int idx = tid + it * 256;
        int r = idx >> 4, c = idx & 15;
        size_t go = ((size_t)(b * T_ + j0 + r) * H_ + h) * D_ + c * 8;
        uint32_t so = (uint32_t)(r * AROWB + c * 16);
        cp16(dst + so,        kh + go);
        cp16(dst + AMAT + so, vh + go);
    }
}

__global__ __launch_bounds__(256, 1) void attn_mma(
    const __half* __restrict__ qh, const __half* __restrict__ kh,
    const __half* __restrict__ vh, __half* __restrict__ oh)
{
    extern __shared__ char smraw[];
    const uint32_t sb = s2u(smraw);
    const int tid = threadIdx.x, wid = tid >> 5, lane = tid & 31;
    const int qi = (int)gridDim.x - 1 - (int)blockIdx.x;  // heavy tiles first
    const int h = blockIdx.y, b = blockIdx.z;
    const int i0 = qi * 128;
    const int numkv = (qi + 1) * 2;

    const __half* Qp = qh + ((size_t)(b * T_ + i0) * H_ + h) * D_;
#pragma unroll
    for (int it = 0; it < 8; it++) {
        int idx = tid + it * 256;
        int r = idx >> 4, c = idx & 15;
        cp16(sb + (uint32_t)(r * AROWB + c * 16),
             Qp + (size_t)r * (H_ * D_) + c * 8);
    }
    const uint32_t kvb = sb + QBYT;
    attn_load_kv(kvb,        kh, vh, b, h, 0,  tid);
    asm volatile("cp.async.commit_group;" ::: "memory");
    attn_load_kv(kvb + ASTG, kh, vh, b, h, 64, tid);
    asm volatile("cp.async.commit_group;" ::: "memory");

    float oacc[16][4];
#pragma unroll
    for (int i = 0; i < 16; i++)
#pragma unroll
        for (int j = 0; j < 4; j++) oacc[i][j] = 0.f;
    float m0 = -3.0e38f, m1 = -3.0e38f, l0 = 0.f, l1 = 0.f;

    const int lrow = lane & 15, lchk = (lane >> 4) * 16;
    const int grp = lane >> 2, tig = lane & 3;
    const int wrow = i0 + wid * 16;
    const int row0g = wrow + grp, row1g = row0g + 8;
    const uint32_t qln = sb + (uint32_t)((wid * 16 + lrow) * AROWB + lchk);

    for (int s = 0; s < numkv; s++) {
        if (s + 1 < numkv)
            asm volatile("cp.async.wait_group 1;" ::: "memory");
        else
            asm volatile("cp.async.wait_group 0;" ::: "memory");
        __syncthreads();
        if (s + 2 < numkv) {
            attn_load_kv(kvb + (uint32_t)((s + 2) % 3) * ASTG,
                         kh, vh, b, h, (s + 2) * 64, tid);
            asm volatile("cp.async.commit_group;" ::: "memory");
        }
        const uint32_t kbase = kvb + (uint32_t)(s % 3) * ASTG;
        const int j0 = s * 64;

        // ---- S = Q * K^T ----
        float sacc[8][4];
#pragma unroll
        for (int i = 0; i < 8; i++)
#pragma unroll
            for (int j = 0; j < 4; j++) sacc[i][j] = 0.f;

        const uint32_t kln = kbase + (uint32_t)(lrow * AROWB + lchk);
#pragma unroll
        for (int kb = 0; kb < 8; kb++) {
            uint32_t a[4];
            LDSM4(a, qln + kb * 32);
#pragma unroll
            for (int ng = 0; ng < 4; ng++) {
                uint32_t bb[4];
                LDSM4(bb, kln + (uint32_t)(ng * (16 * AROWB)) + kb * 32);
                mma16816(sacc[2 * ng],     a, bb[0], bb[2]);
                mma16816(sacc[2 * ng + 1], a, bb[1], bb[3]);
            }
        }

        // ---- causal mask ----
        if (j0 + 63 > wrow) {
#pragma unroll
            for (int nb = 0; nb < 8; nb++) {
                int c0 = j0 + nb * 8 + tig * 2;
                if (c0     > row0g) sacc[nb][0] = -1e30f;
                if (c0 + 1 > row0g) sacc[nb][1] = -1e30f;
                if (c0     > row1g) sacc[nb][2] = -1e30f;
                if (c0 + 1 > row1g) sacc[nb][3] = -1e30f;
            }
        }

        // ---- online softmax ----
        float mx0 = -3.0e38f, mx1 = -3.0e38f;
#pragma unroll
        for (int nb = 0; nb < 8; nb++) {
            mx0 = fmaxf(mx0, fmaxf(sacc[nb][0], sacc[nb][1]));
            mx1 = fmaxf(mx1, fmaxf(sacc[nb][2], sacc[nb][3]));
        }
        mx0 = fmaxf(mx0, __shfl_xor_sync(0xffffffffu, mx0, 1));
        mx0 = fmaxf(mx0, __shfl_xor_sync(0xffffffffu, mx0, 2));
        mx1 = fmaxf(mx1, __shfl_xor_sync(0xffffffffu, mx1, 1));
        mx1 = fmaxf(mx1, __shfl_xor_sync(0xffffffffu, mx1, 2));
        float mn0 = fmaxf(m0, mx0), mn1 = fmaxf(m1, mx1);
        float al0 = __expf(m0 - mn0), al1 = __expf(m1 - mn1);
        m0 = mn0; m1 = mn1;
#pragma unroll
        for (int ng = 0; ng < 16; ng++) {
            oacc[ng][0] *= al0; oacc[ng][1] *= al0;
            oacc[ng][2] *= al1; oacc[ng][3] *= al1;
        }

        float rs0 = 0.f, rs1 = 0.f;
        uint32_t aPhi[4][4], aPlo[4][4];
#pragma unroll
        for (int kk = 0; kk < 4; kk++) {
#pragma unroll
            for (int hf = 0; hf < 2; hf++) {
                int nb = 2 * kk + hf;
                float p0 = __expf(sacc[nb][0] - m0);
                float p1 = __expf(sacc[nb][1] - m0);
                float p2 = __expf(sacc[nb][2] - m1);
                float p3 = __expf(sacc[nb][3] - m1);
                rs0 += p0 + p1;
                rs1 += p2 + p3;
                float h0 = __half2float(__float2half_rn(p0));
                float h1 = __half2float(__float2half_rn(p1));
                float h2 = __half2float(__float2half_rn(p2));
                float h3 = __half2float(__float2half_rn(p3));
                aPhi[kk][2 * hf]     = packh(h0, h1);
                aPhi[kk][2 * hf + 1] = packh(h2, h3);
                aPlo[kk][2 * hf]     = packh(p0 - h0, p1 - h1);
                aPlo[kk][2 * hf + 1] = packh(p2 - h2, p3 - h3);
            }
        }
        rs0 += __shfl_xor_sync(0xffffffffu, rs0, 1);
        rs0 += __shfl_xor_sync(0xffffffffu, rs0, 2);
        rs1 += __shfl_xor_sync(0xffffffffu, rs1, 1);
        rs1 += __shfl_xor_sync(0xffffffffu, rs1, 2);
        l0 = l0 * al0 + rs0;
        l1 = l1 * al1 + rs1;

        // ---- O += (Phi + Plo) * V ----
        const uint32_t vln = kbase + AMAT + (uint32_t)(lrow * AROWB + lchk);
#pragma unroll
        for (int kk = 0; kk < 4; kk++) {
            const uint32_t vrow = vln + (uint32_t)(kk * (16 * AROWB));
#pragma unroll
            for (int ng = 0; ng < 8; ng++) {
                uint32_t bv[4];
                LDSM4T(bv, vrow + ng * 32);
                mma16816(oacc[2 * ng],     aPhi[kk], bv[0], bv[1]);
                mma16816(oacc[2 * ng],     aPlo[kk], bv[0], bv[1]);
                mma16816(oacc[2 * ng + 1], aPhi[kk], bv[2], bv[3]);
                mma16816(oacc[2 * ng + 1], aPlo[kk], bv[2], bv[3]);
            }
        }
    }

    // ---- epilogue: O / l -> fp16 ----
    const float inv0 = 1.0f / l0, inv1 = 1.0f / l1;
    const int orow0 = i0 + wid * 16 + grp;
    const size_t ob0 = ((size_t)(b * T_ + orow0) * H_ + h) * D_ + tig * 2;
    const size_t ob1 = ((size_t)(b * T_ + orow0 + 8) * H_ + h) * D_ + tig * 2;
#pragma unroll
    for (int ng = 0; ng < 16; ng++) {
        *(uint32_t*)(oh + ob0 + ng * 8) =
            packh(oacc[ng][0] * inv0, oacc[ng][1] * inv0);
        *(uint32_t*)(oh + ob1 + ng * 8) =
            packh(oacc[ng][2] * inv1, oacc[ng][3] * inv1);
    }
}

// ---------------------------------------------------------------------------
// Launch
// ---------------------------------------------------------------------------
extern "C" void kernel_launch(void* const* d_in, const int* in_sizes, int n_in,
                              void* d_out, int out_size)
{
    const float* x    = (const float*)d_in[0];
    const float* w_aq = (const float*)d_in[1];
    const float* w_ak = (const float*)d_in[2];
    const float* w_av = (const float*)d_in[3];
    const float* w_ao = (const float*)d_in[4];
    float* out = (float*)d_out;

    __half *xh, *qh, *kh, *vh, *oh;
    cudaGetSymbolAddress((void**)&xh, g_xh);
    cudaGetSymbolAddress((void**)&qh, g_qh);
    cudaGetSymbolAddress((void**)&kh, g_kh);
    cudaGetSymbolAddress((void**)&vh, g_vh);
    cudaGetSymbolAddress((void**)&oh, g_oh);

    __half *wq, *wk, *wv, *wo;
    cudaGetSymbolAddress((void**)&wq, g_wq);
    cudaGetSymbolAddress((void**)&wk, g_wk);
    cudaGetSymbolAddress((void**)&wv, g_wv);
    cudaGetSymbolAddress((void**)&wo, g_wo);

    // Weight transpose+convert (fp16)
    dim3 tb(32, 8);
    dim3 tgw(D_ / 32, M_ / 32, H_);
    tconv_kernel<<<tgw, tb>>>(w_aq, (long)M_ * D_, wq, (long)D_ * M_, M_, D_);
    tconv_kernel<<<tgw, tb>>>(w_ak, (long)M_ * D_, wk, (long)D_ * M_, M_, D_);
    tconv_kernel<<<tgw, tb>>>(w_av, (long)M_ * D_, wv, (long)D_ * M_, M_, D_);
    dim3 tgo(M_ / 32, M_ / 32, 1);
    tconv_kernel<<<tgo, tb>>>(w_ao, 0L, wo, 0L, M_, M_);

    // Convert x -> fp16
    conv_kernel<<<(BT_ * M_ / 4 + 255) / 256, 256>>>(x, xh, BT_ * M_ / 4);

    // QKV projections (HMMA single-product), write fp16 q/k/v directly
    cudaFuncSetAttribute(gemm_mma<__half>,
                         cudaFuncAttributeMaxDynamicSharedMemorySize, GEMM_SMEM);
    cudaFuncSetAttribute(gemm_mma<float>,
                         cudaFuncAttributeMaxDynamicSharedMemorySize, GEMM_SMEM);
    dim3 gg(BT_ / 128, M_ / 128, 3);
    gemm_mma<__half><<<gg, 256, GEMM_SMEM>>>(xh, wq, wk, wv, qh, kh, vh);

    // RoPE in-place on fp16 q (scaled), k
    rope_h_kernel<<<BT_, 1024>>>(qh, kh);

    // HMMA flash attention -> oh
    cudaFuncSetAttribute(attn_mma, cudaFuncAttributeMaxDynamicSharedMemorySize,
                         ATTN_SMEM);
    dim3 ga(T_ / 128, H_, B_);
    attn_mma<<<ga, 256, ATTN_SMEM>>>(qh, kh, vh, oh);

    // Output projection (HMMA single-product) -> fp32 out
    dim3 gg2(BT_ / 128, M_ / 128, 1);
    gemm_mma<float><<<gg2, 256, GEMM_SMEM>>>(oh, wo, wo, wo, out, out, out);
}

// round 7
// speedup vs baseline: 6.0399x; 1.0563x over previous
#include <cuda_runtime.h>
#include <cuda_fp16.h>
#include <math.h>
#include <stdint.h>

#define B_  2
#define T_  2048
#define M_  2048
#define H_  16
#define D_  128
#define BT_ (B_ * T_)
#define K_  M_

// ---------------------------------------------------------------------------
// Scratch (device globals: allocation-free per harness rules)
// ---------------------------------------------------------------------------
__device__ __half g_xh[(size_t)BT_ * M_];
__device__ __half g_qh[(size_t)BT_ * M_];
__device__ __half g_kh[(size_t)BT_ * M_];
__device__ __half g_vh[(size_t)BT_ * M_];
__device__ __half g_oh[(size_t)BT_ * M_];

__device__ __half g_wq[(size_t)H_ * D_ * M_];
__device__ __half g_wk[(size_t)H_ * D_ * M_];
__device__ __half g_wv[(size_t)H_ * D_ * M_];
__device__ __half g_wo[(size_t)M_ * M_];

// ---------------------------------------------------------------------------
// PTX helpers (sm_80-class only: legal under plain sm_103 target)
// ---------------------------------------------------------------------------
__device__ __forceinline__ uint32_t s2u(const void* p) {
    uint32_t a;
    asm("{ .reg .u64 t; cvta.to.shared.u64 t, %1; cvt.u32.u64 %0, t; }"
        : "=r"(a) : "l"(p));
    return a;
}

__device__ __forceinline__ void cp16(uint32_t dst, const void* src) {
    asm volatile("cp.async.cg.shared.global [%0], [%1], 16;"
                 :: "r"(dst), "l"(src) : "memory");
}

#define LDSM4(r, a) \
    asm volatile("ldmatrix.sync.aligned.m8n8.x4.shared.b16 {%0,%1,%2,%3}, [%4];" \
                 : "=r"((r)[0]), "=r"((r)[1]), "=r"((r)[2]), "=r"((r)[3])        \
                 : "r"(a))

#define LDSM4T(r, a) \
    asm volatile("ldmatrix.sync.aligned.m8n8.x4.trans.shared.b16 {%0,%1,%2,%3}, [%4];" \
                 : "=r"((r)[0]), "=r"((r)[1]), "=r"((r)[2]), "=r"((r)[3])              \
                 : "r"(a))

__device__ __forceinline__ void mma16816(float* d, const uint32_t* a,
                                         uint32_t b0, uint32_t b1) {
    asm volatile(
        "mma.sync.aligned.m16n8k16.row.col.f32.f16.f16.f32 "
        "{%0,%1,%2,%3}, {%4,%5,%6,%7}, {%8,%9}, {%0,%1,%2,%3};"
        : "+f"(d[0]), "+f"(d[1]), "+f"(d[2]), "+f"(d[3])
        : "r"(a[0]), "r"(a[1]), "r"(a[2]), "r"(a[3]), "r"(b0), "r"(b1));
}

__device__ __forceinline__ uint32_t packh(float x, float y) {
    __half2 t = __halves2half2(__float2half_rn(x), __float2half_rn(y));
    return *(uint32_t*)&t;
}

// ---------------------------------------------------------------------------
// Convert: fp32 -> fp16
// ---------------------------------------------------------------------------
__global__ __launch_bounds__(256) void conv_kernel(
    const float* __restrict__ x, __half* __restrict__ h, int n4)
{
    int i = blockIdx.x * blockDim.x + threadIdx.x;
    if (i >= n4) return;
    float4 v = ((const float4*)x)[i];
    uint32_t* H = (uint32_t*)h;
    H[2*i]   = packh(v.x, v.y);
    H[2*i+1] = packh(v.z, v.w);
}

// ---------------------------------------------------------------------------
// Transpose + convert: src [R, C] fp32 (per-z panel) -> dst [C, R] fp16
// ---------------------------------------------------------------------------
__global__ __launch_bounds__(256) void tconv_kernel(
    const float* __restrict__ src, long srcZ,
    __half* __restrict__ dh, long dstZ, int R, int C)
{
    __shared__ float t[32][33];
    src += (size_t)blockIdx.z * srcZ;
    dh  += (size_t)blockIdx.z * dstZ;
    int c0 = blockIdx.x * 32, r0 = blockIdx.y * 32;
    int tx = threadIdx.x, ty = threadIdx.y;  // 32 x 8
#pragma unroll
    for (int j = 0; j < 4; j++)
        t[ty + 8*j][tx] = src[(size_t)(r0 + ty + 8*j) * C + c0 + tx];
    __syncthreads();
#pragma unroll
    for (int j = 0; j < 4; j++) {
        float v = t[tx][ty + 8*j];
        dh[(size_t)(c0 + ty + 8*j) * R + r0 + tx] = __float2half_rn(v);
    }
}

// ---------------------------------------------------------------------------
// HMMA GEMM (single-product fp16): C[128x128] = A[128,K] @ B[128,K]^T
// B pre-transposed. BK=32, 3-stage cp.async. CT = __half or float.
// ---------------------------------------------------------------------------
#define ROWB      80
#define MAT_BYTES (128 * ROWB)       // 10240
#define STG_BYTES (2 * MAT_BYTES)    // 20480 (A, B)
#define NSTG      3
#define GEMM_SMEM (NSTG * STG_BYTES) // 61440
#define KSTEPS    (K_ / 32)

__device__ __forceinline__ void load_stage(
    uint32_t buf, const __half* __restrict__ A,
    const __half* __restrict__ B, int k0, int tid)
{
#pragma unroll
    for (int it = 0; it < 2; it++) {
        int idx = tid + it * 256;
        int row = idx >> 2, c = idx & 3;
        uint32_t so = (uint32_t)(row * ROWB + c * 16);
        const size_t go = (size_t)row * K_ + k0 + c * 8;
        cp16(buf + so,             A + go);
        cp16(buf + MAT_BYTES + so, B + go);
    }
}

template <typename CT>
__global__ __launch_bounds__(256) void gemm_mma(
    const __half* __restrict__ A,
    const __half* __restrict__ B0, const __half* __restrict__ B1,
    const __half* __restrict__ B2,
    CT* __restrict__ C0, CT* __restrict__ C1, CT* __restrict__ C2)
{
    extern __shared__ char smraw[];
    const uint32_t sb = s2u(smraw);
    const int tid = threadIdx.x;
    const int wid = tid >> 5, lane = tid & 31;
    const int warp_m = wid >> 2;
    const int warp_n = wid & 3;

    const __half* B;
    CT* C;
    if (blockIdx.z == 0)      { B = B0; C = C0; }
    else if (blockIdx.z == 1) { B = B1; C = C1; }
    else                      { B = B2; C = C2; }

    const int row0 = blockIdx.x * 128;
    const int col0 = blockIdx.y * 128;
    A += (size_t)row0 * K_;
    B += (size_t)col0 * K_;

    load_stage(sb,             A, B, 0,  tid);
    asm volatile("cp.async.commit_group;" ::: "memory");
    load_stage(sb + STG_BYTES, A, B, 32, tid);
    asm volatile("cp.async.commit_group;" ::: "memory");

    float acc[4][4][4];
#pragma unroll
    for (int i = 0; i < 4; i++)
#pragma unroll
        for (int j = 0; j < 4; j++)
#pragma unroll
            for (int r = 0; r < 4; r++) acc[i][j][r] = 0.f;

    const int lrow = lane & 15;
    const int lchk = (lane >> 4) * 16;

    for (int s = 0; s < KSTEPS; s++) {
        if (s + 1 < KSTEPS)
            asm volatile("cp.async.wait_group 1;" ::: "memory");
        else
            asm volatile("cp.async.wait_group 0;" ::: "memory");
        __syncthreads();

        if (s + 2 < KSTEPS) {
            load_stage(sb + (uint32_t)((s + 2) % NSTG) * STG_BYTES,
                       A, B, (s + 2) * 32, tid);
            asm volatile("cp.async.commit_group;" ::: "memory");
        }

        const uint32_t base = sb + (uint32_t)(s % NSTG) * STG_BYTES;

#pragma unroll
        for (int kh = 0; kh < 2; kh++) {
            const uint32_t koff = (uint32_t)(kh * 32 + lchk);

            uint32_t a4[4][4];
#pragma unroll
            for (int mi = 0; mi < 4; mi++) {
                uint32_t ad = base +
                    (uint32_t)((warp_m * 64 + mi * 16 + lrow) * ROWB) + koff;
                LDSM4(a4[mi], ad);
            }
            uint32_t b4[2][4];
#pragma unroll
            for (int bj = 0; bj < 2; bj++) {
                uint32_t bd = base + MAT_BYTES +
                    (uint32_t)((warp_n * 32 + bj * 16 + lrow) * ROWB) + koff;
                LDSM4(b4[bj], bd);
            }
#pragma unroll
            for (int mi = 0; mi < 4; mi++) {
#pragma unroll
                for (int ni = 0; ni < 4; ni++) {
                    const int bj = ni >> 1, sel = ni & 1;
                    mma16816(acc[mi][ni], a4[mi], b4[bj][sel], b4[bj][sel + 2]);
                }
            }
        }
    }

    const int grp = lane >> 2, tig = lane & 3;
#pragma unroll
    for (int mi = 0; mi < 4; mi++) {
#pragma unroll
        for (int ni = 0; ni < 4; ni++) {
            int r = row0 + warp_m * 64 + mi * 16 + grp;
            int c = col0 + warp_n * 32 + ni * 8 + tig * 2;
            if constexpr (sizeof(CT) == 2) {
                *(uint32_t*)(C + (size_t)r * M_ + c) =
                    packh(acc[mi][ni][0], acc[mi][ni][1]);
                *(uint32_t*)(C + (size_t)(r + 8) * M_ + c) =
                    packh(acc[mi][ni][2], acc[mi][ni][3]);
            } else {
                *(float2*)(C + (size_t)r * M_ + c) =
                    make_float2(acc[mi][ni][0], acc[mi][ni][1]);
                *(float2*)(C + (size_t)(r + 8) * M_ + c) =
                    make_float2(acc[mi][ni][2], acc[mi][ni][3]);
            }
        }
    }
}

// ---------------------------------------------------------------------------
// RoPE in-place on fp16 q (scaled 1/128) and k. Layout [bt][h][d], pairs (d, d+64).
// freq = 10000^(-d/64) = 2^(-d * log2(10000)/64)
// ---------------------------------------------------------------------------
__global__ __launch_bounds__(1024) void rope_h_kernel(
    __half* __restrict__ q, __half* __restrict__ k)
{
    const int bt = blockIdx.x;
    const int t  = bt % T_;
    const int h  = threadIdx.x >> 6;
    const int d  = threadIdx.x & 63;

    float freq = exp2f(-(float)d * 0.20762050593045952f);
    float ang  = (float)t * freq;
    float s, c;
    sincosf(ang, &s, &c);

    const size_t base = ((size_t)bt * H_ + h) * D_ + d;

    float qe = __half2float(q[base]), qo = __half2float(q[base + 64]);
    q[base]      = __float2half_rn((qe * c - qo * s) * (1.0f / 128.0f));
    q[base + 64] = __float2half_rn((qe * s + qo * c) * (1.0f / 128.0f));

    float ke = __half2float(k[base]), ko = __half2float(k[base + 64]);
    k[base]      = __float2half_rn(ke * c - ko * s);
    k[base + 64] = __float2half_rn(ke * s + ko * c);
}

// ---------------------------------------------------------------------------
// HMMA causal flash attention (fp16): 128q x 64kv tiles, D=128, 8 warps.
// S = Q*K^T (1 product); PV = P*V (1 product, P rounded to fp16; l computed
// from the ROUNDED P so numerator/denominator stay consistent).
// ---------------------------------------------------------------------------
#define AROWB 272
#define AMAT  (64 * AROWB)            // 17408
#define ASTG  (2 * AMAT)              // 34816 (Kh, Vh)
#define QBYT  (128 * AROWB)           // 34816
#define ATTN_SMEM (QBYT + 3 * ASTG)   // 139264

__device__ __forceinline__ void attn_load_kv(
    uint32_t dst, const __half* __restrict__ kh, const __half* __restrict__ vh,
    int b, int h, int j0, int tid)
{
#pragma unroll
    for (int it = 0; it < 4; it++) {
        int idx = tid + it * 256;
        int r = idx >> 4, c = idx & 15;
        size_t go = ((size_t)(b * T_ + j0 + r) * H_ + h) * D_ + c * 8;
        uint32_t so = (uint32_t)(r * AROWB + c * 16);
        cp16(dst + so,        kh + go);
        cp16(dst + AMAT + so, vh + go);
    }
}

__global__ __launch_bounds__(256, 1) void attn_mma(
    const __half* __restrict__ qh, const __half* __restrict__ kh,
    const __half* __restrict__ vh, __half* __restrict__ oh)
{
    extern __shared__ char smraw[];
    const uint32_t sb = s2u(smraw);
    const int tid = threadIdx.x, wid = tid >> 5, lane = tid & 31;
    const int qi = (int)gridDim.x - 1 - (int)blockIdx.x;  // heavy tiles first
    const int h = blockIdx.y, b = blockIdx.z;
    const int i0 = qi * 128;
    const int numkv = (qi + 1) * 2;

    const __half* Qp = qh + ((size_t)(b * T_ + i0) * H_ + h) * D_;
#pragma unroll
    for (int it = 0; it < 8; it++) {
        int idx = tid + it * 256;
        int r = idx >> 4, c = idx & 15;
        cp16(sb + (uint32_t)(r * AROWB + c * 16),
             Qp + (size_t)r * (H_ * D_) + c * 8);
    }
    const uint32_t kvb = sb + QBYT;
    attn_load_kv(kvb,        kh, vh, b, h, 0,  tid);
    asm volatile("cp.async.commit_group;" ::: "memory");
    attn_load_kv(kvb + ASTG, kh, vh, b, h, 64, tid);
    asm volatile("cp.async.commit_group;" ::: "memory");

    float oacc[16][4];
#pragma unroll
    for (int i = 0; i < 16; i++)
#pragma unroll
        for (int j = 0; j < 4; j++) oacc[i][j] = 0.f;
    float m0 = -3.0e38f, m1 = -3.0e38f, l0 = 0.f, l1 = 0.f;

    const int lrow = lane & 15, lchk = (lane >> 4) * 16;
    const int grp = lane >> 2, tig = lane & 3;
    const int wrow = i0 + wid * 16;
    const int row0g = wrow + grp, row1g = row0g + 8;
    const uint32_t qln = sb + (uint32_t)((wid * 16 + lrow) * AROWB + lchk);

    for (int s = 0; s < numkv; s++) {
        if (s + 1 < numkv)
            asm volatile("cp.async.wait_group 1;" ::: "memory");
        else
            asm volatile("cp.async.wait_group 0;" ::: "memory");
        __syncthreads();
        if (s + 2 < numkv) {
            attn_load_kv(kvb + (uint32_t)((s + 2) % 3) * ASTG,
                         kh, vh, b, h, (s + 2) * 64, tid);
            asm volatile("cp.async.commit_group;" ::: "memory");
        }
        const uint32_t kbase = kvb + (uint32_t)(s % 3) * ASTG;
        const int j0 = s * 64;

        // ---- S = Q * K^T ----
        float sacc[8][4];
#pragma unroll
        for (int i = 0; i < 8; i++)
#pragma unroll
            for (int j = 0; j < 4; j++) sacc[i][j] = 0.f;

        const uint32_t kln = kbase + (uint32_t)(lrow * AROWB + lchk);
#pragma unroll
        for (int kb = 0; kb < 8; kb++) {
            uint32_t a[4];
            LDSM4(a, qln + kb * 32);
#pragma unroll
            for (int ng = 0; ng < 4; ng++) {
                uint32_t bb[4];
                LDSM4(bb, kln + (uint32_t)(ng * (16 * AROWB)) + kb * 32);
                mma16816(sacc[2 * ng],     a, bb[0], bb[2]);
                mma16816(sacc[2 * ng + 1], a, bb[1], bb[3]);
            }
        }

        // ---- causal mask ----
        if (j0 + 63 > wrow) {
#pragma unroll
            for (int nb = 0; nb < 8; nb++) {
                int c0 = j0 + nb * 8 + tig * 2;
                if (c0     > row0g) sacc[nb][0] = -1e30f;
                if (c0 + 1 > row0g) sacc[nb][1] = -1e30f;
                if (c0     > row1g) sacc[nb][2] = -1e30f;
                if (c0 + 1 > row1g) sacc[nb][3] = -1e30f;
            }
        }

        // ---- online softmax ----
        float mx0 = -3.0e38f, mx1 = -3.0e38f;
#pragma unroll
        for (int nb = 0; nb < 8; nb++) {
            mx0 = fmaxf(mx0, fmaxf(sacc[nb][0], sacc[nb][1]));
            mx1 = fmaxf(mx1, fmaxf(sacc[nb][2], sacc[nb][3]));
        }
        mx0 = fmaxf(mx0, __shfl_xor_sync(0xffffffffu, mx0, 1));
        mx0 = fmaxf(mx0, __shfl_xor_sync(0xffffffffu, mx0, 2));
        mx1 = fmaxf(mx1, __shfl_xor_sync(0xffffffffu, mx1, 1));
        mx1 = fmaxf(mx1, __shfl_xor_sync(0xffffffffu, mx1, 2));
        float mn0 = fmaxf(m0, mx0), mn1 = fmaxf(m1, mx1);
        float al0 = __expf(m0 - mn0), al1 = __expf(m1 - mn1);
        m0 = mn0; m1 = mn1;
#pragma unroll
        for (int ng = 0; ng < 16; ng++) {
            oacc[ng][0] *= al0; oacc[ng][1] *= al0;
            oacc[ng][2] *= al1; oacc[ng][3] *= al1;
        }

        float rs0 = 0.f, rs1 = 0.f;
        uint32_t aP[4][4];
#pragma unroll
        for (int kk = 0; kk < 4; kk++) {
#pragma unroll
            for (int hf = 0; hf < 2; hf++) {
                int nb = 2 * kk + hf;
                float p0 = __expf(sacc[nb][0] - m0);
                float p1 = __expf(sacc[nb][1] - m0);
                float p2 = __expf(sacc[nb][2] - m1);
                float p3 = __expf(sacc[nb][3] - m1);
                // round to fp16, use ROUNDED values for the row sum too
                float h0 = __half2float(__float2half_rn(p0));
                float h1 = __half2float(__float2half_rn(p1));
                float h2 = __half2float(__float2half_rn(p2));
                float h3 = __half2float(__float2half_rn(p3));
                rs0 += h0 + h1;
                rs1 += h2 + h3;
                aP[kk][2 * hf]     = packh(h0, h1);
                aP[kk][2 * hf + 1] = packh(h2, h3);
            }
        }
        rs0 += __shfl_xor_sync(0xffffffffu, rs0, 1);
        rs0 += __shfl_xor_sync(0xffffffffu, rs0, 2);
        rs1 += __shfl_xor_sync(0xffffffffu, rs1, 1);
        rs1 += __shfl_xor_sync(0xffffffffu, rs1, 2);
        l0 = l0 * al0 + rs0;
        l1 = l1 * al1 + rs1;

        // ---- O += P * V (single product) ----
        const uint32_t vln = kbase + AMAT + (uint32_t)(lrow * AROWB + lchk);
#pragma unroll
        for (int kk = 0; kk < 4; kk++) {
            const uint32_t vrow = vln + (uint32_t)(kk * (16 * AROWB));
#pragma unroll
            for (int ng = 0; ng < 8; ng++) {
                uint32_t bv[4];
                LDSM4T(bv, vrow + ng * 32);
                mma16816(oacc[2 * ng],     aP[kk], bv[0], bv[1]);
                mma16816(oacc[2 * ng + 1], aP[kk], bv[2], bv[3]);
            }
        }
    }

    // ---- epilogue: O / l -> fp16 ----
    const float inv0 = 1.0f / l0, inv1 = 1.0f / l1;
    const int orow0 = i0 + wid * 16 + grp;
    const size_t ob0 = ((size_t)(b * T_ + orow0) * H_ + h) * D_ + tig * 2;
    const size_t ob1 = ((size_t)(b * T_ + orow0 + 8) * H_ + h) * D_ + tig * 2;
#pragma unroll
    for (int ng = 0; ng < 16; ng++) {
        *(uint32_t*)(oh + ob0 + ng * 8) =
            packh(oacc[ng][0] * inv0, oacc[ng][1] * inv0);
        *(uint32_t*)(oh + ob1 + ng * 8) =
            packh(oacc[ng][2] * inv1, oacc[ng][3] * inv1);
    }
}

// ---------------------------------------------------------------------------
// Launch
// ---------------------------------------------------------------------------
extern "C" void kernel_launch(void* const* d_in, const int* in_sizes, int n_in,
                              void* d_out, int out_size)
{
    const float* x    = (const float*)d_in[0];
    const float* w_aq = (const float*)d_in[1];
    const float* w_ak = (const float*)d_in[2];
    const float* w_av = (const float*)d_in[3];
    const float* w_ao = (const float*)d_in[4];
    float* out = (float*)d_out;

    __half *xh, *qh, *kh, *vh, *oh;
    cudaGetSymbolAddress((void**)&xh, g_xh);
    cudaGetSymbolAddress((void**)&qh, g_qh);
    cudaGetSymbolAddress((void**)&kh, g_kh);
    cudaGetSymbolAddress((void**)&vh, g_vh);
    cudaGetSymbolAddress((void**)&oh, g_oh);

    __half *wq, *wk, *wv, *wo;
    cudaGetSymbolAddress((void**)&wq, g_wq);
    cudaGetSymbolAddress((void**)&wk, g_wk);
    cudaGetSymbolAddress((void**)&wv, g_wv);
    cudaGetSymbolAddress((void**)&wo, g_wo);

    // Weight transpose+convert (fp16)
    dim3 tb(32, 8);
    dim3 tgw(D_ / 32, M_ / 32, H_);
    tconv_kernel<<<tgw, tb>>>(w_aq, (long)M_ * D_, wq, (long)D_ * M_, M_, D_);
    tconv_kernel<<<tgw, tb>>>(w_ak, (long)M_ * D_, wk, (long)D_ * M_, M_, D_);
    tconv_kernel<<<tgw, tb>>>(w_av, (long)M_ * D_, wv, (long)D_ * M_, M_, D_);
    dim3 tgo(M_ / 32, M_ / 32, 1);
    tconv_kernel<<<tgo, tb>>>(w_ao, 0L, wo, 0L, M_, M_);

    // Convert x -> fp16
    conv_kernel<<<(BT_ * M_ / 4 + 255) / 256, 256>>>(x, xh, BT_ * M_ / 4);

    // QKV projections (HMMA single-product), write fp16 q/k/v directly
    cudaFuncSetAttribute(gemm_mma<__half>,
                         cudaFuncAttributeMaxDynamicSharedMemorySize, GEMM_SMEM);
    cudaFuncSetAttribute(gemm_mma<float>,
                         cudaFuncAttributeMaxDynamicSharedMemorySize, GEMM_SMEM);
    dim3 gg(BT_ / 128, M_ / 128, 3);
    gemm_mma<__half><<<gg, 256, GEMM_SMEM>>>(xh, wq, wk, wv, qh, kh, vh);

    // RoPE in-place on fp16 q (scaled), k
    rope_h_kernel<<<BT_, 1024>>>(qh, kh);

    // HMMA flash attention -> oh
    cudaFuncSetAttribute(attn_mma, cudaFuncAttributeMaxDynamicSharedMemorySize,
                         ATTN_SMEM);
    dim3 ga(T_ / 128, H_, B_);
    attn_mma<<<ga, 256, ATTN_SMEM>>>(qh, kh, vh, oh);

    // Output projection (HMMA single-product) -> fp32 out
    dim3 gg2(BT_ / 128, M_ / 128, 1);
    gemm_mma<float><<<gg2, 256, GEMM_SMEM>>>(oh, wo, wo, wo, out, out, out);
}

// round 8
// speedup vs baseline: 6.1438x; 1.0172x over previous
#include <cuda_runtime.h>
#include <cuda_fp16.h>
#include <math.h>
#include <stdint.h>

#define B_  2
#define T_  2048
#define M_  2048
#define H_  16
#define D_  128
#define BT_ (B_ * T_)
#define K_  M_

// ---------------------------------------------------------------------------
// Scratch (device globals: allocation-free per harness rules)
// ---------------------------------------------------------------------------
__device__ __half g_xh[(size_t)BT_ * M_];
__device__ __half g_qh[(size_t)BT_ * M_];
__device__ __half g_kh[(size_t)BT_ * M_];
__device__ __half g_vh[(size_t)BT_ * M_];
__device__ __half g_oh[(size_t)BT_ * M_];

__device__ __half g_wq[(size_t)H_ * D_ * M_];
__device__ __half g_wk[(size_t)H_ * D_ * M_];
__device__ __half g_wv[(size_t)H_ * D_ * M_];
__device__ __half g_wo[(size_t)M_ * M_];

// ---------------------------------------------------------------------------
// PTX helpers (sm_80-class only: legal under plain sm_103 target)
// ---------------------------------------------------------------------------
__device__ __forceinline__ uint32_t s2u(const void* p) {
    uint32_t a;
    asm("{ .reg .u64 t; cvta.to.shared.u64 t, %1; cvt.u32.u64 %0, t; }"
        : "=r"(a) : "l"(p));
    return a;
}

__device__ __forceinline__ void cp16(uint32_t dst, const void* src) {
    asm volatile("cp.async.cg.shared.global [%0], [%1], 16;"
                 :: "r"(dst), "l"(src) : "memory");
}

#define LDSM4(r, a) \
    asm volatile("ldmatrix.sync.aligned.m8n8.x4.shared.b16 {%0,%1,%2,%3}, [%4];" \
                 : "=r"((r)[0]), "=r"((r)[1]), "=r"((r)[2]), "=r"((r)[3])        \
                 : "r"(a))

#define LDSM4T(r, a) \
    asm volatile("ldmatrix.sync.aligned.m8n8.x4.trans.shared.b16 {%0,%1,%2,%3}, [%4];" \
                 : "=r"((r)[0]), "=r"((r)[1]), "=r"((r)[2]), "=r"((r)[3])              \
                 : "r"(a))

__device__ __forceinline__ void mma16816(float* d, const uint32_t* a,
                                         uint32_t b0, uint32_t b1) {
    asm volatile(
        "mma.sync.aligned.m16n8k16.row.col.f32.f16.f16.f32 "
        "{%0,%1,%2,%3}, {%4,%5,%6,%7}, {%8,%9}, {%0,%1,%2,%3};"
        : "+f"(d[0]), "+f"(d[1]), "+f"(d[2]), "+f"(d[3])
        : "r"(a[0]), "r"(a[1]), "r"(a[2]), "r"(a[3]), "r"(b0), "r"(b1));
}

// fp16-accumulate variant (rate probe; used only for q/k projections)
__device__ __forceinline__ void mma16816h(uint32_t* d, const uint32_t* a,
                                          uint32_t b0, uint32_t b1) {
    asm volatile(
        "mma.sync.aligned.m16n8k16.row.col.f16.f16.f16.f16 "
        "{%0,%1}, {%2,%3,%4,%5}, {%6,%7}, {%0,%1};"
        : "+r"(d[0]), "+r"(d[1])
        : "r"(a[0]), "r"(a[1]), "r"(a[2]), "r"(a[3]), "r"(b0), "r"(b1));
}

__device__ __forceinline__ uint32_t packh(float x, float y) {
    __half2 t = __halves2half2(__float2half_rn(x), __float2half_rn(y));
    return *(uint32_t*)&t;
}

// ---------------------------------------------------------------------------
// Convert: fp32 -> fp16
// ---------------------------------------------------------------------------
__global__ __launch_bounds__(256) void conv_kernel(
    const float* __restrict__ x, __half* __restrict__ h, int n4)
{
    int i = blockIdx.x * blockDim.x + threadIdx.x;
    if (i >= n4) return;
    float4 v = ((const float4*)x)[i];
    uint32_t* H = (uint32_t*)h;
    H[2*i]   = packh(v.x, v.y);
    H[2*i+1] = packh(v.z, v.w);
}

// ---------------------------------------------------------------------------
// Transpose + convert: src [R, C] fp32 (per-z panel) -> dst [C, R] fp16
// 64(src rows) x 32(src cols) tiles; half2 full-line writes.
// ---------------------------------------------------------------------------
__global__ __launch_bounds__(256) void tconv_kernel(
    const float* __restrict__ src, long srcZ,
    __half* __restrict__ dh, long dstZ, int R, int C)
{
    __shared__ float t[64][33];
    src += (size_t)blockIdx.z * srcZ;
    dh  += (size_t)blockIdx.z * dstZ;
    int c0 = blockIdx.x * 32, r0 = blockIdx.y * 64;
    int tx = threadIdx.x, ty = threadIdx.y;  // 32 x 8
#pragma unroll
    for (int j = 0; j < 8; j++)
        t[ty + 8*j][tx] = src[(size_t)(r0 + ty + 8*j) * C + c0 + tx];
    __syncthreads();
#pragma unroll
    for (int j = 0; j < 4; j++) {
        int c = ty + 8*j;
        __half2 o = __halves2half2(__float2half_rn(t[2*tx][c]),
                                   __float2half_rn(t[2*tx + 1][c]));
        *(__half2*)&dh[(size_t)(c0 + c) * R + r0 + 2*tx] = o;
    }
}

// ---------------------------------------------------------------------------
// HMMA GEMM shared pieces: 128x128 tile, BK=32, 3-stage cp.async
// ---------------------------------------------------------------------------
#define ROWB      80
#define MAT_BYTES (128 * ROWB)       // 10240
#define STG_BYTES (2 * MAT_BYTES)    // 20480 (A, B)
#define NSTG      3
#define GEMM_SMEM (NSTG * STG_BYTES) // 61440
#define KSTEPS    (K_ / 32)

__device__ __forceinline__ void load_stage(
    uint32_t buf, const __half* __restrict__ A,
    const __half* __restrict__ B, int k0, int tid)
{
#pragma unroll
    for (int it = 0; it < 2; it++) {
        int idx = tid + it * 256;
        int row = idx >> 2, c = idx & 3;
        uint32_t so = (uint32_t)(row * ROWB + c * 16);
        const size_t go = (size_t)row * K_ + k0 + c * 8;
        cp16(buf + so,             A + go);
        cp16(buf + MAT_BYTES + so, B + go);
    }
}

// fp32-accumulate GEMM (v projection / out projection)
template <typename CT>
__global__ __launch_bounds__(256) void gemm_mma(
    const __half* __restrict__ A,
    const __half* __restrict__ B0, CT* __restrict__ C0)
{
    extern __shared__ char smraw[];
    const uint32_t sb = s2u(smraw);
    const int tid = threadIdx.x;
    const int wid = tid >> 5, lane = tid & 31;
    const int warp_m = wid >> 2, warp_n = wid & 3;

    const __half* B = B0;
    CT* C = C0;

    const int row0 = blockIdx.x * 128;
    const int col0 = blockIdx.y * 128;
    A += (size_t)row0 * K_;
    B += (size_t)col0 * K_;

    load_stage(sb,             A, B, 0,  tid);
    asm volatile("cp.async.commit_group;" ::: "memory");
    load_stage(sb + STG_BYTES, A, B, 32, tid);
    asm volatile("cp.async.commit_group;" ::: "memory");

    float acc[4][4][4];
#pragma unroll
    for (int i = 0; i < 4; i++)
#pragma unroll
        for (int j = 0; j < 4; j++)
#pragma unroll
            for (int r = 0; r < 4; r++) acc[i][j][r] = 0.f;

    const int lrow = lane & 15;
    const int lchk = (lane >> 4) * 16;

    for (int s = 0; s < KSTEPS; s++) {
        if (s + 1 < KSTEPS)
            asm volatile("cp.async.wait_group 1;" ::: "memory");
        else
            asm volatile("cp.async.wait_group 0;" ::: "memory");
        __syncthreads();

        if (s + 2 < KSTEPS) {
            load_stage(sb + (uint32_t)((s + 2) % NSTG) * STG_BYTES,
                       A, B, (s + 2) * 32, tid);
            asm volatile("cp.async.commit_group;" ::: "memory");
        }

        const uint32_t base = sb + (uint32_t)(s % NSTG) * STG_BYTES;

#pragma unroll
        for (int kh = 0; kh < 2; kh++) {
            const uint32_t koff = (uint32_t)(kh * 32 + lchk);
            uint32_t a4[4][4];
#pragma unroll
            for (int mi = 0; mi < 4; mi++) {
                uint32_t ad = base +
                    (uint32_t)((warp_m * 64 + mi * 16 + lrow) * ROWB) + koff;
                LDSM4(a4[mi], ad);
            }
            uint32_t b4[2][4];
#pragma unroll
            for (int bj = 0; bj < 2; bj++) {
                uint32_t bd = base + MAT_BYTES +
                    (uint32_t)((warp_n * 32 + bj * 16 + lrow) * ROWB) + koff;
                LDSM4(b4[bj], bd);
            }
#pragma unroll
            for (int mi = 0; mi < 4; mi++) {
#pragma unroll
                for (int ni = 0; ni < 4; ni++) {
                    const int bj = ni >> 1, sel = ni & 1;
                    mma16816(acc[mi][ni], a4[mi], b4[bj][sel], b4[bj][sel + 2]);
                }
            }
        }
    }

    const int grp = lane >> 2, tig = lane & 3;
#pragma unroll
    for (int mi = 0; mi < 4; mi++) {
#pragma unroll
        for (int ni = 0; ni < 4; ni++) {
            int r = row0 + warp_m * 64 + mi * 16 + grp;
            int c = col0 + warp_n * 32 + ni * 8 + tig * 2;
            if constexpr (sizeof(CT) == 2) {
                *(uint32_t*)(C + (size_t)r * M_ + c) =
                    packh(acc[mi][ni][0], acc[mi][ni][1]);
                *(uint32_t*)(C + (size_t)(r + 8) * M_ + c) =
                    packh(acc[mi][ni][2], acc[mi][ni][3]);
            } else {
                *(float2*)(C + (size_t)r * M_ + c) =
                    make_float2(acc[mi][ni][0], acc[mi][ni][1]);
                *(float2*)(C + (size_t)(r + 8) * M_ + c) =
                    make_float2(acc[mi][ni][2], acc[mi][ni][3]);
            }
        }
    }
}

// fp16-accumulate GEMM (q/k projections; quantization softmax-suppressed)
__global__ __launch_bounds__(256) void gemm_mma_h(
    const __half* __restrict__ A,
    const __half* __restrict__ B0, const __half* __restrict__ B1,
    __half* __restrict__ C0, __half* __restrict__ C1)
{
    extern __shared__ char smraw[];
    const uint32_t sb = s2u(smraw);
    const int tid = threadIdx.x;
    const int wid = tid >> 5, lane = tid & 31;
    const int warp_m = wid >> 2, warp_n = wid & 3;

    const __half* B = (blockIdx.z == 0) ? B0 : B1;
    __half* C       = (blockIdx.z == 0) ? C0 : C1;

    const int row0 = blockIdx.x * 128;
    const int col0 = blockIdx.y * 128;
    A += (size_t)row0 * K_;
    B += (size_t)col0 * K_;

    load_stage(sb,             A, B, 0,  tid);
    asm volatile("cp.async.commit_group;" ::: "memory");
    load_stage(sb + STG_BYTES, A, B, 32, tid);
    asm volatile("cp.async.commit_group;" ::: "memory");

    uint32_t acch[4][4][2];
#pragma unroll
    for (int i = 0; i < 4; i++)
#pragma unroll
        for (int j = 0; j < 4; j++) { acch[i][j][0] = 0u; acch[i][j][1] = 0u; }

    const int lrow = lane & 15;
    const int lchk = (lane >> 4) * 16;

    for (int s = 0; s < KSTEPS; s++) {
        if (s + 1 < KSTEPS)
            asm volatile("cp.async.wait_group 1;" ::: "memory");
        else
            asm volatile("cp.async.wait_group 0;" ::: "memory");
        __syncthreads();

        if (s + 2 < KSTEPS) {
            load_stage(sb + (uint32_t)((s + 2) % NSTG) * STG_BYTES,
                       A, B, (s + 2) * 32, tid);
            asm volatile("cp.async.commit_group;" ::: "memory");
        }

        const uint32_t base = sb + (uint32_t)(s % NSTG) * STG_BYTES;

#pragma unroll
        for (int kh = 0; kh < 2; kh++) {
            const uint32_t koff = (uint32_t)(kh * 32 + lchk);
            uint32_t a4[4][4];
#pragma unroll
            for (int mi = 0; mi < 4; mi++) {
                uint32_t ad = base +
                    (uint32_t)((warp_m * 64 + mi * 16 + lrow) * ROWB) + koff;
                LDSM4(a4[mi], ad);
            }
            uint32_t b4[2][4];
#pragma unroll
            for (int bj = 0; bj < 2; bj++) {
                uint32_t bd = base + MAT_BYTES +
                    (uint32_t)((warp_n * 32 + bj * 16 + lrow) * ROWB) + koff;
                LDSM4(b4[bj], bd);
            }
#pragma unroll
            for (int mi = 0; mi < 4; mi++) {
#pragma unroll
                for (int ni = 0; ni < 4; ni++) {
                    const int bj = ni >> 1, sel = ni & 1;
                    mma16816h(acch[mi][ni], a4[mi], b4[bj][sel], b4[bj][sel + 2]);
                }
            }
        }
    }

    const int grp = lane >> 2, tig = lane & 3;
#pragma unroll
    for (int mi = 0; mi < 4; mi++) {
#pragma unroll
        for (int ni = 0; ni < 4; ni++) {
            int r = row0 + warp_m * 64 + mi * 16 + grp;
            int c = col0 + warp_n * 32 + ni * 8 + tig * 2;
            *(uint32_t*)(C + (size_t)r * M_ + c)       = acch[mi][ni][0];
            *(uint32_t*)(C + (size_t)(r + 8) * M_ + c) = acch[mi][ni][1];
        }
    }
}

// ---------------------------------------------------------------------------
// RoPE in-place on fp16 q (scaled 1/128) and k.
// ---------------------------------------------------------------------------
__global__ __launch_bounds__(1024) void rope_h_kernel(
    __half* __restrict__ q, __half* __restrict__ k)
{
    const int bt = blockIdx.x;
    const int t  = bt % T_;
    const int h  = threadIdx.x >> 6;
    const int d  = threadIdx.x & 63;

    float freq = exp2f(-(float)d * 0.20762050593045952f);
    float ang  = (float)t * freq;
    float s, c;
    sincosf(ang, &s, &c);

    const size_t base = ((size_t)bt * H_ + h) * D_ + d;

    float qe = __half2float(q[base]), qo = __half2float(q[base + 64]);
    q[base]      = __float2half_rn((qe * c - qo * s) * (1.0f / 128.0f));
    q[base + 64] = __float2half_rn((qe * s + qo * c) * (1.0f / 128.0f));

    float ke = __half2float(k[base]), ko = __half2float(k[base + 64]);
    k[base]      = __float2half_rn(ke * c - ko * s);
    k[base + 64] = __float2half_rn(ke * s + ko * c);
}

// ---------------------------------------------------------------------------
// HMMA causal flash attention: 128q x 64kv tiles, 8 warps, 2 CTAs/SM.
// Split K/V double-buffered pipelines; K(s+2) issued after S-phase,
// V(s+2) after PV. S and PV single-product fp16 (P rounded, l from rounded P).
// ---------------------------------------------------------------------------
#define AROWB 272
#define AMAT  (64 * AROWB)            // 17408
#define QBYT  (128 * AROWB)           // 34816
#define KVK   QBYT
#define KVV   (QBYT + 2 * AMAT)
#define ATTN_SMEM (QBYT + 4 * AMAT)   // 104448

__device__ __forceinline__ void load_half_tile(
    uint32_t dst, const __half* __restrict__ src, int b, int h, int j0, int tid)
{
#pragma unroll
    for (int it = 0; it < 4; it++) {
        int idx = tid + it * 256;
        int r = idx >> 4, c = idx & 15;
        cp16(dst + (uint32_t)(r * AROWB + c * 16),
             src + ((size_t)(b * T_ + j0 + r) * H_ + h) * D_ + c * 8);
    }
}

__global__ __launch_bounds__(256, 2) void attn_mma(
    const __half* __restrict__ qh, const __half* __restrict__ kh,
    const __half* __restrict__ vh, __half* __restrict__ oh)
{
    extern __shared__ char smraw[];
    const uint32_t sb = s2u(smraw);
    const int tid = threadIdx.x, wid = tid >> 5, lane = tid & 31;
    const int qi = (int)gridDim.x - 1 - (int)blockIdx.x;  // heavy tiles first
    const int h = blockIdx.y, b = blockIdx.z;
    const int i0 = qi * 128;
    const int numkv = (qi + 1) * 2;

    // group A: Q + K0 + V0
    const __half* Qp = qh + ((size_t)(b * T_ + i0) * H_ + h) * D_;
#pragma unroll
    for (int it = 0; it < 8; it++) {
        int idx = tid + it * 256;
        int r = idx >> 4, c = idx & 15;
        cp16(sb + (uint32_t)(r * AROWB + c * 16),
             Qp + (size_t)r * (H_ * D_) + c * 8);
    }
    load_half_tile(sb + KVK, kh, b, h, 0, tid);
    load_half_tile(sb + KVV, vh, b, h, 0, tid);
    asm volatile("cp.async.commit_group;" ::: "memory");
    // group B: K1 + V1
    load_half_tile(sb + KVK + AMAT, kh, b, h, 64, tid);
    load_half_tile(sb + KVV + AMAT, vh, b, h, 64, tid);
    asm volatile("cp.async.commit_group;" ::: "memory");

    float oacc[16][4];
#pragma unroll
    for (int i = 0; i < 16; i++)
#pragma unroll
        for (int j = 0; j < 4; j++) oacc[i][j] = 0.f;
    float m0 = -3.0e38f, m1 = -3.0e38f, l0 = 0.f, l1 = 0.f;

    const int lrow = lane & 15, lchk = (lane >> 4) * 16;
    const int grp = lane >> 2, tig = lane & 3;
    const int wrow = i0 + wid * 16;
    const int row0g = wrow + grp, row1g = row0g + 8;
    const uint32_t qln = sb + (uint32_t)((wid * 16 + lrow) * AROWB + lchk);

    for (int s = 0; s < numkv; s++) {
        if (s == 0)
            asm volatile("cp.async.wait_group 1;" ::: "memory");
        else
            asm volatile("cp.async.wait_group 2;" ::: "memory");
        __syncthreads();

        const uint32_t kbase = sb + KVK + (uint32_t)(s & 1) * AMAT;
        const uint32_t vbase = sb + KVV + (uint32_t)(s & 1) * AMAT;
        const int j0 = s * 64;

        // ---- S = Q * K^T ----
        float sacc[8][4];
#pragma unroll
        for (int i = 0; i < 8; i++)
#pragma unroll
            for (int j = 0; j < 4; j++) sacc[i][j] = 0.f;

        const uint32_t kln = kbase + (uint32_t)(lrow * AROWB + lchk);
#pragma unroll
        for (int kb = 0; kb < 8; kb++) {
            uint32_t a[4];
            LDSM4(a, qln + kb * 32);
#pragma unroll
            for (int ng = 0; ng < 4; ng++) {
                uint32_t bb[4];
                LDSM4(bb, kln + (uint32_t)(ng * (16 * AROWB)) + kb * 32);
                mma16816(sacc[2 * ng],     a, bb[0], bb[2]);
                mma16816(sacc[2 * ng + 1], a, bb[1], bb[3]);
            }
        }

        // K buffer consumed -> prefetch K(s+2) into this K buffer
        __syncthreads();
        if (s + 2 < numkv)
            load_half_tile(kbase, kh, b, h, (s + 2) * 64, tid);
        asm volatile("cp.async.commit_group;" ::: "memory");

        // ---- causal mask ----
        if (j0 + 63 > wrow) {
#pragma unroll
            for (int nb = 0; nb < 8; nb++) {
                int c0 = j0 + nb * 8 + tig * 2;
                if (c0     > row0g) sacc[nb][0] = -1e30f;
                if (c0 + 1 > row0g) sacc[nb][1] = -1e30f;
                if (c0     > row1g) sacc[nb][2] = -1e30f;
                if (c0 + 1 > row1g) sacc[nb][3] = -1e30f;
            }
        }

        // ---- online softmax (max + rescale) ----
        float mx0 = -3.0e38f, mx1 = -3.0e38f;
#pragma unroll
        for (int nb = 0; nb < 8; nb++) {
            mx0 = fmaxf(mx0, fmaxf(sacc[nb][0], sacc[nb][1]));
            mx1 = fmaxf(mx1, fmaxf(sacc[nb][2], sacc[nb][3]));
        }
        mx0 = fmaxf(mx0, __shfl_xor_sync(0xffffffffu, mx0, 1));
        mx0 = fmaxf(mx0, __shfl_xor_sync(0xffffffffu, mx0, 2));
        mx1 = fmaxf(mx1, __shfl_xor_sync(0xffffffffu, mx1, 1));
        mx1 = fmaxf(mx1, __shfl_xor_sync(0xffffffffu, mx1, 2));
        float mn0 = fmaxf(m0, mx0), mn1 = fmaxf(m1, mx1);
        float al0 = __expf(m0 - mn0), al1 = __expf(m1 - mn1);
        m0 = mn0; m1 = mn1;
#pragma unroll
        for (int ng = 0; ng < 16; ng++) {
            oacc[ng][0] *= al0; oacc[ng][1] *= al0;
            oacc[ng][2] *= al1; oacc[ng][3] *= al1;
        }

        // ---- fused exp + PV (P rounded to fp16; l from rounded P) ----
        float rs0 = 0.f, rs1 = 0.f;
        const uint32_t vln = vbase + (uint32_t)(lrow * AROWB + lchk);
#pragma unroll
        for (int kk = 0; kk < 4; kk++) {
            uint32_t aP[4];
#pragma unroll
            for (int hf = 0; hf < 2; hf++) {
                int nb = 2 * kk + hf;
                float p0 = __expf(sacc[nb][0] - m0);
                float p1 = __expf(sacc[nb][1] - m0);
                float p2 = __expf(sacc[nb][2] - m1);
                float p3 = __expf(sacc[nb][3] - m1);
                float h0 = __half2float(__float2half_rn(p0));
                float h1 = __half2float(__float2half_rn(p1));
                float h2 = __half2float(__float2half_rn(p2));
                float h3 = __half2float(__float2half_rn(p3));
                rs0 += h0 + h1;
                rs1 += h2 + h3;
                aP[2 * hf]     = packh(h0, h1);
                aP[2 * hf + 1] = packh(h2, h3);
            }
            const uint32_t vrow = vln + (uint32_t)(kk * (16 * AROWB));
#pragma unroll
            for (int ng = 0; ng < 8; ng++) {
                uint32_t bv[4];
                LDSM4T(bv, vrow + ng * 32);
                mma16816(oacc[2 * ng],     aP, bv[0], bv[1]);
                mma16816(oacc[2 * ng + 1], aP, bv[2], bv[3]);
            }
        }
        rs0 += __shfl_xor_sync(0xffffffffu, rs0, 1);
        rs0 += __shfl_xor_sync(0xffffffffu, rs0, 2);
        rs1 += __shfl_xor_sync(0xffffffffu, rs1, 1);
        rs1 += __shfl_xor_sync(0xffffffffu, rs1, 2);
        l0 = l0 * al0 + rs0;
        l1 = l1 * al1 + rs1;

        // V buffer consumed -> prefetch V(s+2) into this V buffer
        __syncthreads();
        if (s + 2 < numkv)
            load_half_tile(vbase, vh, b, h, (s + 2) * 64, tid);
        asm volatile("cp.async.commit_group;" ::: "memory");
    }

    // ---- epilogue: O / l -> fp16 ----
    const float inv0 = 1.0f / l0, inv1 = 1.0f / l1;
    const int orow0 = i0 + wid * 16 + grp;
    const size_t ob0 = ((size_t)(b * T_ + orow0) * H_ + h) * D_ + tig * 2;
    const size_t ob1 = ((size_t)(b * T_ + orow0 + 8) * H_ + h) * D_ + tig * 2;
#pragma unroll
    for (int ng = 0; ng < 16; ng++) {
        *(uint32_t*)(oh + ob0 + ng * 8) =
            packh(oacc[ng][0] * inv0, oacc[ng][1] * inv0);
        *(uint32_t*)(oh + ob1 + ng * 8) =
            packh(oacc[ng][2] * inv1, oacc[ng][3] * inv1);
    }
}

// ---------------------------------------------------------------------------
// Launch
// ---------------------------------------------------------------------------
extern "C" void kernel_launch(void* const* d_in, const int* in_sizes, int n_in,
                              void* d_out, int out_size)
{
    const float* x    = (const float*)d_in[0];
    const float* w_aq = (const float*)d_in[1];
    const float* w_ak = (const float*)d_in[2];
    const float* w_av = (const float*)d_in[3];
    const float* w_ao = (const float*)d_in[4];
    float* out = (float*)d_out;

    __half *xh, *qh, *kh, *vh, *oh;
    cudaGetSymbolAddress((void**)&xh, g_xh);
    cudaGetSymbolAddress((void**)&qh, g_qh);
    cudaGetSymbolAddress((void**)&kh, g_kh);
    cudaGetSymbolAddress((void**)&vh, g_vh);
    cudaGetSymbolAddress((void**)&oh, g_oh);

    __half *wq, *wk, *wv, *wo;
    cudaGetSymbolAddress((void**)&wq, g_wq);
    cudaGetSymbolAddress((void**)&wk, g_wk);
    cudaGetSymbolAddress((void**)&wv, g_wv);
    cudaGetSymbolAddress((void**)&wo, g_wo);

    // Weight transpose+convert (fp16)
    dim3 tb(32, 8);
    dim3 tgw(D_ / 32, M_ / 64, H_);
    tconv_kernel<<<tgw, tb>>>(w_aq, (long)M_ * D_, wq, (long)D_ * M_, M_, D_);
    tconv_kernel<<<tgw, tb>>>(w_ak, (long)M_ * D_, wk, (long)D_ * M_, M_, D_);
    tconv_kernel<<<tgw, tb>>>(w_av, (long)M_ * D_, wv, (long)D_ * M_, M_, D_);
    dim3 tgo(M_ / 32, M_ / 64, 1);
    tconv_kernel<<<tgo, tb>>>(w_ao, 0L, wo, 0L, M_, M_);

    // Convert x -> fp16
    conv_kernel<<<(BT_ * M_ / 4 + 255) / 256, 256>>>(x, xh, BT_ * M_ / 4);

    // q/k projections (fp16-accumulate probe), v projection (fp32-accumulate)
    cudaFuncSetAttribute(gemm_mma_h,
                         cudaFuncAttributeMaxDynamicSharedMemorySize, GEMM_SMEM);
    cudaFuncSetAttribute(gemm_mma<__half>,
                         cudaFuncAttributeMaxDynamicSharedMemorySize, GEMM_SMEM);
    cudaFuncSetAttribute(gemm_mma<float>,
                         cudaFuncAttributeMaxDynamicSharedMemorySize, GEMM_SMEM);
    dim3 ggqk(BT_ / 128, M_ / 128, 2);
    gemm_mma_h<<<ggqk, 256, GEMM_SMEM>>>(xh, wq, wk, qh, kh);
    dim3 ggv(BT_ / 128, M_ / 128, 1);
    gemm_mma<__half><<<ggv, 256, GEMM_SMEM>>>(xh, wv, vh);

    // RoPE in-place on fp16 q (scaled), k
    rope_h_kernel<<<BT_, 1024>>>(qh, kh);

    // HMMA flash attention -> oh (2 CTAs/SM)
    cudaFuncSetAttribute(attn_mma, cudaFuncAttributeMaxDynamicSharedMemorySize,
                         ATTN_SMEM);
    dim3 ga(T_ / 128, H_, B_);
    attn_mma<<<ga, 256, ATTN_SMEM>>>(qh, kh, vh, oh);

    // Output projection (fp32-accumulate) -> fp32 out
    dim3 ggo(BT_ / 128, M_ / 128, 1);
    gemm_mma<float><<<ggo, 256, GEMM_SMEM>>>(oh, wo, out);
}

// round 9
// speedup vs baseline: 6.1603x; 1.0027x over previous
#include <cuda_runtime.h>
#include <cuda_fp16.h>
#include <math.h>
#include <stdint.h>

#define B_  2
#define T_  2048
#define M_  2048
#define H_  16
#define D_  128
#define BT_ (B_ * T_)
#define K_  M_

// ---------------------------------------------------------------------------
// Scratch (device globals: allocation-free per harness rules)
// ---------------------------------------------------------------------------
__device__ __half g_xh[(size_t)BT_ * M_];
__device__ __half g_qh[(size_t)BT_ * M_];
__device__ __half g_kh[(size_t)BT_ * M_];
__device__ __half g_vh[(size_t)BT_ * M_];
__device__ __half g_oh[(size_t)BT_ * M_];

__device__ __half g_wq[(size_t)H_ * D_ * M_];
__device__ __half g_wk[(size_t)H_ * D_ * M_];
__device__ __half g_wv[(size_t)H_ * D_ * M_];
__device__ __half g_wo[(size_t)M_ * M_];

// ---------------------------------------------------------------------------
// PTX helpers (sm_80-class only: legal under plain sm_103 target)
// ---------------------------------------------------------------------------
__device__ __forceinline__ uint32_t s2u(const void* p) {
    uint32_t a;
    asm("{ .reg .u64 t; cvta.to.shared.u64 t, %1; cvt.u32.u64 %0, t; }"
        : "=r"(a) : "l"(p));
    return a;
}

__device__ __forceinline__ void cp16(uint32_t dst, const void* src) {
    asm volatile("cp.async.cg.shared.global [%0], [%1], 16;"
                 :: "r"(dst), "l"(src) : "memory");
}

#define LDSM4(r, a) \
    asm volatile("ldmatrix.sync.aligned.m8n8.x4.shared.b16 {%0,%1,%2,%3}, [%4];" \
                 : "=r"((r)[0]), "=r"((r)[1]), "=r"((r)[2]), "=r"((r)[3])        \
                 : "r"(a))

#define LDSM4T(r, a) \
    asm volatile("ldmatrix.sync.aligned.m8n8.x4.trans.shared.b16 {%0,%1,%2,%3}, [%4];" \
                 : "=r"((r)[0]), "=r"((r)[1]), "=r"((r)[2]), "=r"((r)[3])              \
                 : "r"(a))

__device__ __forceinline__ void mma16816(float* d, const uint32_t* a,
                                         uint32_t b0, uint32_t b1) {
    asm volatile(
        "mma.sync.aligned.m16n8k16.row.col.f32.f16.f16.f32 "
        "{%0,%1,%2,%3}, {%4,%5,%6,%7}, {%8,%9}, {%0,%1,%2,%3};"
        : "+f"(d[0]), "+f"(d[1]), "+f"(d[2]), "+f"(d[3])
        : "r"(a[0]), "r"(a[1]), "r"(a[2]), "r"(a[3]), "r"(b0), "r"(b1));
}

__device__ __forceinline__ uint32_t packh(float x, float y) {
    __half2 t = __halves2half2(__float2half_rn(x), __float2half_rn(y));
    return *(uint32_t*)&t;
}

// ---------------------------------------------------------------------------
// Convert: fp32 -> fp16
// ---------------------------------------------------------------------------
__global__ __launch_bounds__(256) void conv_kernel(
    const float* __restrict__ x, __half* __restrict__ h, int n4)
{
    int i = blockIdx.x * blockDim.x + threadIdx.x;
    if (i >= n4) return;
    float4 v = ((const float4*)x)[i];
    uint32_t* H = (uint32_t*)h;
    H[2*i]   = packh(v.x, v.y);
    H[2*i+1] = packh(v.z, v.w);
}

// ---------------------------------------------------------------------------
// Transpose + convert, 3 weights in one launch: src [R=2048, C=128] per panel
// -> dst [C, R] fp16. z = weight*16 + panel.
// ---------------------------------------------------------------------------
__global__ __launch_bounds__(256) void tconv3_kernel(
    const float* __restrict__ s0, const float* __restrict__ s1,
    const float* __restrict__ s2,
    __half* __restrict__ d0, __half* __restrict__ d1, __half* __restrict__ d2)
{
    __shared__ float t[64][33];
    const int w = blockIdx.z >> 4, p = blockIdx.z & 15;
    const float* src = (w == 0) ? s0 : (w == 1) ? s1 : s2;
    __half* dh       = (w == 0) ? d0 : (w == 1) ? d1 : d2;
    src += (size_t)p * M_ * D_;
    dh  += (size_t)p * D_ * M_;
    const int R = M_, C = D_;
    int c0 = blockIdx.x * 32, r0 = blockIdx.y * 64;
    int tx = threadIdx.x, ty = threadIdx.y;  // 32 x 8
#pragma unroll
    for (int j = 0; j < 8; j++)
        t[ty + 8*j][tx] = src[(size_t)(r0 + ty + 8*j) * C + c0 + tx];
    __syncthreads();
#pragma unroll
    for (int j = 0; j < 4; j++) {
        int c = ty + 8*j;
        __half2 o = __halves2half2(__float2half_rn(t[2*tx][c]),
                                   __float2half_rn(t[2*tx + 1][c]));
        *(__half2*)&dh[(size_t)(c0 + c) * R + r0 + 2*tx] = o;
    }
}

// single-tensor transpose (w_ao)
__global__ __launch_bounds__(256) void tconv_kernel(
    const float* __restrict__ src, __half* __restrict__ dh, int R, int C)
{
    __shared__ float t[64][33];
    int c0 = blockIdx.x * 32, r0 = blockIdx.y * 64;
    int tx = threadIdx.x, ty = threadIdx.y;
#pragma unroll
    for (int j = 0; j < 8; j++)
        t[ty + 8*j][tx] = src[(size_t)(r0 + ty + 8*j) * C + c0 + tx];
    __syncthreads();
#pragma unroll
    for (int j = 0; j < 4; j++) {
        int c = ty + 8*j;
        __half2 o = __halves2half2(__float2half_rn(t[2*tx][c]),
                                   __float2half_rn(t[2*tx + 1][c]));
        *(__half2*)&dh[(size_t)(c0 + c) * R + r0 + 2*tx] = o;
    }
}

// ---------------------------------------------------------------------------
// HMMA GEMM shared pieces: 128x128 tile, BK=32, 3-stage cp.async
// ---------------------------------------------------------------------------
#define ROWB      80
#define MAT_BYTES (128 * ROWB)       // 10240
#define STG_BYTES (2 * MAT_BYTES)    // 20480 (A, B)
#define NSTG      3
#define GEMM_SMEM (NSTG * STG_BYTES) // 61440
#define KSTEPS    (K_ / 32)

__device__ __forceinline__ void load_stage(
    uint32_t buf, const __half* __restrict__ A,
    const __half* __restrict__ B, int k0, int tid)
{
#pragma unroll
    for (int it = 0; it < 2; it++) {
        int idx = tid + it * 256;
        int row = idx >> 2, c = idx & 3;
        uint32_t so = (uint32_t)(row * ROWB + c * 16);
        const size_t go = (size_t)row * K_ + k0 + c * 8;
        cp16(buf + so,             A + go);
        cp16(buf + MAT_BYTES + so, B + go);
    }
}

// Mainloop producing fp32 acc[4][4][4] (shared by all GEMMs)
__device__ __forceinline__ void gemm_mainloop(
    uint32_t sb, const __half* A, const __half* B, int tid,
    float acc[4][4][4])
{
    const int wid = tid >> 5, lane = tid & 31;
    const int warp_m = wid >> 2, warp_n = wid & 3;

    load_stage(sb,             A, B, 0,  tid);
    asm volatile("cp.async.commit_group;" ::: "memory");
    load_stage(sb + STG_BYTES, A, B, 32, tid);
    asm volatile("cp.async.commit_group;" ::: "memory");

#pragma unroll
    for (int i = 0; i < 4; i++)
#pragma unroll
        for (int j = 0; j < 4; j++)
#pragma unroll
            for (int r = 0; r < 4; r++) acc[i][j][r] = 0.f;

    const int lrow = lane & 15;
    const int lchk = (lane >> 4) * 16;

    for (int s = 0; s < KSTEPS; s++) {
        if (s + 1 < KSTEPS)
            asm volatile("cp.async.wait_group 1;" ::: "memory");
        else
            asm volatile("cp.async.wait_group 0;" ::: "memory");
        __syncthreads();

        if (s + 2 < KSTEPS) {
            load_stage(sb + (uint32_t)((s + 2) % NSTG) * STG_BYTES,
                       A, B, (s + 2) * 32, tid);
            asm volatile("cp.async.commit_group;" ::: "memory");
        }

        const uint32_t base = sb + (uint32_t)(s % NSTG) * STG_BYTES;

#pragma unroll
        for (int kh = 0; kh < 2; kh++) {
            const uint32_t koff = (uint32_t)(kh * 32 + lchk);
            uint32_t a4[4][4];
#pragma unroll
            for (int mi = 0; mi < 4; mi++) {
                uint32_t ad = base +
                    (uint32_t)((warp_m * 64 + mi * 16 + lrow) * ROWB) + koff;
                LDSM4(a4[mi], ad);
            }
            uint32_t b4[2][4];
#pragma unroll
            for (int bj = 0; bj < 2; bj++) {
                uint32_t bd = base + MAT_BYTES +
                    (uint32_t)((warp_n * 32 + bj * 16 + lrow) * ROWB) + koff;
                LDSM4(b4[bj], bd);
            }
#pragma unroll
            for (int mi = 0; mi < 4; mi++) {
#pragma unroll
                for (int ni = 0; ni < 4; ni++) {
                    const int bj = ni >> 1, sel = ni & 1;
                    mma16816(acc[mi][ni], a4[mi], b4[bj][sel], b4[bj][sel + 2]);
                }
            }
        }
    }
}

// ---------------------------------------------------------------------------
// QKV projection GEMM with fused RoPE epilogue for q/k.
// z: 0 = q (rope + 1/128 scale), 1 = k (rope), 2 = v (plain).
// N tile (128 cols) == one head, so (d, d+64) pairs live in this CTA.
// ---------------------------------------------------------------------------
#define TILE_STR 130   // halves per row in epilogue staging tile

__global__ __launch_bounds__(256) void gemm_qkv(
    const __half* __restrict__ xh,
    const __half* __restrict__ wq, const __half* __restrict__ wk,
    const __half* __restrict__ wv,
    __half* __restrict__ qh, __half* __restrict__ kh, __half* __restrict__ vh)
{
    extern __shared__ char smraw[];
    const uint32_t sb = s2u(smraw);
    const int tid = threadIdx.x;
    const int wid = tid >> 5, lane = tid & 31;
    const int warp_m = wid >> 2, warp_n = wid & 3;
    const int z = blockIdx.z;

    const __half* B = (z == 0) ? wq : (z == 1) ? wk : wv;
    __half* C       = (z == 0) ? qh : (z == 1) ? kh : vh;

    const int row0 = blockIdx.x * 128;
    const int col0 = blockIdx.y * 128;
    const __half* A = xh + (size_t)row0 * K_;
    B += (size_t)col0 * K_;

    float acc[4][4][4];
    gemm_mainloop(sb, A, B, tid, acc);

    const int grp = lane >> 2, tig = lane & 3;

    if (z == 2) {
        // plain fp16 store
#pragma unroll
        for (int mi = 0; mi < 4; mi++) {
#pragma unroll
            for (int ni = 0; ni < 4; ni++) {
                int r = row0 + warp_m * 64 + mi * 16 + grp;
                int c = col0 + warp_n * 32 + ni * 8 + tig * 2;
                *(uint32_t*)(C + (size_t)r * M_ + c) =
                    packh(acc[mi][ni][0], acc[mi][ni][1]);
                *(uint32_t*)(C + (size_t)(r + 8) * M_ + c) =
                    packh(acc[mi][ni][2], acc[mi][ni][3]);
            }
        }
        return;
    }

    // ---- fused RoPE epilogue (q/k) ----
    __half* tile = (__half*)smraw;   // 128 x TILE_STR halves = 33280 B
    __syncthreads();                 // all warps done with stage buffers
#pragma unroll
    for (int mi = 0; mi < 4; mi++) {
#pragma unroll
        for (int ni = 0; ni < 4; ni++) {
            int rl = warp_m * 64 + mi * 16 + grp;
            int cl = warp_n * 32 + ni * 8 + tig * 2;
            *(uint32_t*)&tile[rl * TILE_STR + cl] =
                packh(acc[mi][ni][0], acc[mi][ni][1]);
            *(uint32_t*)&tile[(rl + 8) * TILE_STR + cl] =
                packh(acc[mi][ni][2], acc[mi][ni][3]);
        }
    }
    __syncthreads();

    const float scale = (z == 0) ? (1.0f / 128.0f) : 1.0f;
    const int d0 = lane * 2;  // d in [0,64), pairs (d, d+64)
    const float freq0 = exp2f(-(float)d0 * 0.20762050593045952f);
    const float freq1 = exp2f(-(float)(d0 + 1) * 0.20762050593045952f);

#pragma unroll 4
    for (int rr = 0; rr < 16; rr++) {
        const int rl = wid * 16 + rr;
        const int t = (row0 + rl) & (T_ - 1);
        float s0, c0, s1, c1;
        sincosf((float)t * freq0, &s0, &c0);
        sincosf((float)t * freq1, &s1, &c1);

        __half2 ev = *(__half2*)&tile[rl * TILE_STR + d0];
        __half2 od = *(__half2*)&tile[rl * TILE_STR + d0 + 64];
        float e0 = __half2float(ev.x), e1 = __half2float(ev.y);
        float o0 = __half2float(od.x), o1 = __half2float(od.y);

        float r0e = (e0 * c0 - o0 * s0) * scale;
        float r1e = (e1 * c1 - o1 * s1) * scale;
        float r0o = (e0 * s0 + o0 * c0) * scale;
        float r1o = (e1 * s1 + o1 * c1) * scale;

        __half* Cp = C + (size_t)(row0 + rl) * M_ + col0;
        *(uint32_t*)(Cp + d0)      = packh(r0e, r1e);
        *(uint32_t*)(Cp + d0 + 64) = packh(r0o, r1o);
    }
}

// ---------------------------------------------------------------------------
// Output projection GEMM (fp32 out)
// ---------------------------------------------------------------------------
__global__ __launch_bounds__(256) void gemm_out(
    const __half* __restrict__ A, const __half* __restrict__ B0,
    float* __restrict__ C)
{
    extern __shared__ char smraw[];
    const uint32_t sb = s2u(smraw);
    const int tid = threadIdx.x;
    const int wid = tid >> 5, lane = tid & 31;
    const int warp_m = wid >> 2, warp_n = wid & 3;

    const int row0 = blockIdx.x * 128;
    const int col0 = blockIdx.y * 128;
    const __half* Ap = A + (size_t)row0 * K_;
    const __half* Bp = B0 + (size_t)col0 * K_;

    float acc[4][4][4];
    gemm_mainloop(sb, Ap, Bp, tid, acc);

    const int grp = lane >> 2, tig = lane & 3;
#pragma unroll
    for (int mi = 0; mi < 4; mi++) {
#pragma unroll
        for (int ni = 0; ni < 4; ni++) {
            int r = row0 + warp_m * 64 + mi * 16 + grp;
            int c = col0 + warp_n * 32 + ni * 8 + tig * 2;
            *(float2*)(C + (size_t)r * M_ + c) =
                make_float2(acc[mi][ni][0], acc[mi][ni][1]);
            *(float2*)(C + (size_t)(r + 8) * M_ + c) =
                make_float2(acc[mi][ni][2], acc[mi][ni][3]);
        }
    }
}

// ---------------------------------------------------------------------------
// HMMA causal flash attention: 128q x 64kv tiles, 8 warps, 2 CTAs/SM.
// Split K/V double-buffered pipelines; K(s+2) issued after S-phase,
// V(s+2) after PV. S and PV single-product fp16 (P rounded, l from rounded P).
// ---------------------------------------------------------------------------
#define AROWB 272
#define AMAT  (64 * AROWB)            // 17408
#define QBYT  (128 * AROWB)           // 34816
#define KVK   QBYT
#define KVV   (QBYT + 2 * AMAT)
#define ATTN_SMEM (QBYT + 4 * AMAT)   // 104448

__device__ __forceinline__ void load_half_tile(
    uint32_t dst, const __half* __restrict__ src, int b, int h, int j0, int tid)
{
#pragma unroll
    for (int it = 0; it < 4; it++) {
        int idx = tid + it * 256;
        int r = idx >> 4, c = idx & 15;
        cp16(dst + (uint32_t)(r * AROWB + c * 16),
             src + ((size_t)(b * T_ + j0 + r) * H_ + h) * D_ + c * 8);
    }
}

__global__ __launch_bounds__(256, 2) void attn_mma(
    const __half* __restrict__ qh, const __half* __restrict__ kh,
    const __half* __restrict__ vh, __half* __restrict__ oh)
{
    extern __shared__ char smraw[];
    const uint32_t sb = s2u(smraw);
    const int tid = threadIdx.x, wid = tid >> 5, lane = tid & 31;
    const int qi = (int)gridDim.x - 1 - (int)blockIdx.x;  // heavy tiles first
    const int h = blockIdx.y, b = blockIdx.z;
    const int i0 = qi * 128;
    const int numkv = (qi + 1) * 2;

    // group A: Q + K0 + V0
    const __half* Qp = qh + ((size_t)(b * T_ + i0) * H_ + h) * D_;
#pragma unroll
    for (int it = 0; it < 8; it++) {
        int idx = tid + it * 256;
        int r = idx >> 4, c = idx & 15;
        cp16(sb + (uint32_t)(r * AROWB + c * 16),
             Qp + (size_t)r * (H_ * D_) + c * 8);
    }
    load_half_tile(sb + KVK, kh, b, h, 0, tid);
    load_half_tile(sb + KVV, vh, b, h, 0, tid);
    asm volatile("cp.async.commit_group;" ::: "memory");
    // group B: K1 + V1
    load_half_tile(sb + KVK + AMAT, kh, b, h, 64, tid);
    load_half_tile(sb + KVV + AMAT, vh, b, h, 64, tid);
    asm volatile("cp.async.commit_group;" ::: "memory");

    float oacc[16][4];
#pragma unroll
    for (int i = 0; i < 16; i++)
#pragma unroll
        for (int j = 0; j < 4; j++) oacc[i][j] = 0.f;
    float m0 = -3.0e38f, m1 = -3.0e38f, l0 = 0.f, l1 = 0.f;

    const int lrow = lane & 15, lchk = (lane >> 4) * 16;
    const int grp = lane >> 2, tig = lane & 3;
    const int wrow = i0 + wid * 16;
    const int row0g = wrow + grp, row1g = row0g + 8;
    const uint32_t qln = sb + (uint32_t)((wid * 16 + lrow) * AROWB + lchk);

    for (int s = 0; s < numkv; s++) {
        if (s == 0)
            asm volatile("cp.async.wait_group 1;" ::: "memory");
        else
            asm volatile("cp.async.wait_group 2;" ::: "memory");
        __syncthreads();

        const uint32_t kbase = sb + KVK + (uint32_t)(s & 1) * AMAT;
        const uint32_t vbase = sb + KVV + (uint32_t)(s & 1) * AMAT;
        const int j0 = s * 64;

        // ---- S = Q * K^T ----
        float sacc[8][4];
#pragma unroll
        for (int i = 0; i < 8; i++)
#pragma unroll
            for (int j = 0; j < 4; j++) sacc[i][j] = 0.f;

        const uint32_t kln = kbase + (uint32_t)(lrow * AROWB + lchk);
#pragma unroll
        for (int kb = 0; kb < 8; kb++) {
            uint32_t a[4];
            LDSM4(a, qln + kb * 32);
#pragma unroll
            for (int ng = 0; ng < 4; ng++) {
                uint32_t bb[4];
                LDSM4(bb, kln + (uint32_t)(ng * (16 * AROWB)) + kb * 32);
                mma16816(sacc[2 * ng],     a, bb[0], bb[2]);
                mma16816(sacc[2 * ng + 1], a, bb[1], bb[3]);
            }
        }

        // K buffer consumed -> prefetch K(s+2) into this K buffer
        __syncthreads();
        if (s + 2 < numkv)
            load_half_tile(kbase, kh, b, h, (s + 2) * 64, tid);
        asm volatile("cp.async.commit_group;" ::: "memory");

        // ---- causal mask ----
        if (j0 + 63 > wrow) {
#pragma unroll
            for (int nb = 0; nb < 8; nb++) {
                int c0 = j0 + nb * 8 + tig * 2;
                if (c0     > row0g) sacc[nb][0] = -1e30f;
                if (c0 + 1 > row0g) sacc[nb][1] = -1e30f;
                if (c0     > row1g) sacc[nb][2] = -1e30f;
                if (c0 + 1 > row1g) sacc[nb][3] = -1e30f;
            }
        }

        // ---- online softmax (max + rescale) ----
        float mx0 = -3.0e38f, mx1 = -3.0e38f;
#pragma unroll
        for (int nb = 0; nb < 8; nb++) {
            mx0 = fmaxf(mx0, fmaxf(sacc[nb][0], sacc[nb][1]));
            mx1 = fmaxf(mx1, fmaxf(sacc[nb][2], sacc[nb][3]));
        }
        mx0 = fmaxf(mx0, __shfl_xor_sync(0xffffffffu, mx0, 1));
        mx0 = fmaxf(mx0, __shfl_xor_sync(0xffffffffu, mx0, 2));
        mx1 = fmaxf(mx1, __shfl_xor_sync(0xffffffffu, mx1, 1));
        mx1 = fmaxf(mx1, __shfl_xor_sync(0xffffffffu, mx1, 2));
        float mn0 = fmaxf(m0, mx0), mn1 = fmaxf(m1, mx1);
        float al0 = __expf(m0 - mn0), al1 = __expf(m1 - mn1);
        m0 = mn0; m1 = mn1;
#pragma unroll
        for (int ng = 0; ng < 16; ng++) {
            oacc[ng][0] *= al0; oacc[ng][1] *= al0;
            oacc[ng][2] *= al1; oacc[ng][3] *= al1;
        }

        // ---- fused exp + PV (P rounded to fp16; l from rounded P) ----
        float rs0 = 0.f, rs1 = 0.f;
        const uint32_t vln = vbase + (uint32_t)(lrow * AROWB + lchk);
#pragma unroll
        for (int kk = 0; kk < 4; kk++) {
            uint32_t aP[4];
#pragma unroll
            for (int hf = 0; hf < 2; hf++) {
                int nb = 2 * kk + hf;
                float p0 = __expf(sacc[nb][0] - m0);
                float p1 = __expf(sacc[nb][1] - m0);
                float p2 = __expf(sacc[nb][2] - m1);
                float p3 = __expf(sacc[nb][3] - m1);
                float h0 = __half2float(__float2half_rn(p0));
                float h1 = __half2float(__float2half_rn(p1));
                float h2 = __half2float(__float2half_rn(p2));
                float h3 = __half2float(__float2half_rn(p3));
                rs0 += h0 + h1;
                rs1 += h2 + h3;
                aP[2 * hf]     = packh(h0, h1);
                aP[2 * hf + 1] = packh(h2, h3);
            }
            const uint32_t vrow = vln + (uint32_t)(kk * (16 * AROWB));
#pragma unroll
            for (int ng = 0; ng < 8; ng++) {
                uint32_t bv[4];
                LDSM4T(bv, vrow + ng * 32);
                mma16816(oacc[2 * ng],     aP, bv[0], bv[1]);
                mma16816(oacc[2 * ng + 1], aP, bv[2], bv[3]);
            }
        }
        rs0 += __shfl_xor_sync(0xffffffffu, rs0, 1);
        rs0 += __shfl_xor_sync(0xffffffffu, rs0, 2);
        rs1 += __shfl_xor_sync(0xffffffffu, rs1, 1);
        rs1 += __shfl_xor_sync(0xffffffffu, rs1, 2);
        l0 = l0 * al0 + rs0;
        l1 = l1 * al1 + rs1;

        // V buffer consumed -> prefetch V(s+2) into this V buffer
        __syncthreads();
        if (s + 2 < numkv)
            load_half_tile(vbase, vh, b, h, (s + 2) * 64, tid);
        asm volatile("cp.async.commit_group;" ::: "memory");
    }

    // ---- epilogue: O / l -> fp16 ----
    const float inv0 = 1.0f / l0, inv1 = 1.0f / l1;
    const int orow0 = i0 + wid * 16 + grp;
    const size_t ob0 = ((size_t)(b * T_ + orow0) * H_ + h) * D_ + tig * 2;
    const size_t ob1 = ((size_t)(b * T_ + orow0 + 8) * H_ + h) * D_ + tig * 2;
#pragma unroll
    for (int ng = 0; ng < 16; ng++) {
        *(uint32_t*)(oh + ob0 + ng * 8) =
            packh(oacc[ng][0] * inv0, oacc[ng][1] * inv0);
        *(uint32_t*)(oh + ob1 + ng * 8) =
            packh(oacc[ng][2] * inv1, oacc[ng][3] * inv1);
    }
}

// ---------------------------------------------------------------------------
// Launch
// ---------------------------------------------------------------------------
extern "C" void kernel_launch(void* const* d_in, const int* in_sizes, int n_in,
                              void* d_out, int out_size)
{
    const float* x    = (const float*)d_in[0];
    const float* w_aq = (const float*)d_in[1];
    const float* w_ak = (const float*)d_in[2];
    const float* w_av = (const float*)d_in[3];
    const float* w_ao = (const float*)d_in[4];
    float* out = (float*)d_out;

    __half *xh, *qh, *kh, *vh, *oh;
    cudaGetSymbolAddress((void**)&xh, g_xh);
    cudaGetSymbolAddress((void**)&qh, g_qh);
    cudaGetSymbolAddress((void**)&kh, g_kh);
    cudaGetSymbolAddress((void**)&vh, g_vh);
    cudaGetSymbolAddress((void**)&oh, g_oh);

    __half *wq, *wk, *wv, *wo;
    cudaGetSymbolAddress((void**)&wq, g_wq);
    cudaGetSymbolAddress((void**)&wk, g_wk);
    cudaGetSymbolAddress((void**)&wv, g_wv);
    cudaGetSymbolAddress((void**)&wo, g_wo);

    // Weight transpose+convert: q/k/v in one launch, wo separate
    dim3 tb(32, 8);
    dim3 tg3(D_ / 32, M_ / 64, 3 * H_);
    tconv3_kernel<<<tg3, tb>>>(w_aq, w_ak, w_av, wq, wk, wv);
    dim3 tgo(M_ / 32, M_ / 64, 1);
    tconv_kernel<<<tgo, tb>>>(w_ao, wo, M_, M_);

    // Convert x -> fp16
    conv_kernel<<<(BT_ * M_ / 4 + 255) / 256, 256>>>(x, xh, BT_ * M_ / 4);

    // QKV projections with fused RoPE epilogue (one launch, z=3)
    cudaFuncSetAttribute(gemm_qkv,
                         cudaFuncAttributeMaxDynamicSharedMemorySize, GEMM_SMEM);
    cudaFuncSetAttribute(gemm_out,
                         cudaFuncAttributeMaxDynamicSharedMemorySize, GEMM_SMEM);
    dim3 gg(BT_ / 128, M_ / 128, 3);
    gemm_qkv<<<gg, 256, GEMM_SMEM>>>(xh, wq, wk, wv, qh, kh, vh);

    // HMMA flash attention -> oh (2 CTAs/SM)
    cudaFuncSetAttribute(attn_mma, cudaFuncAttributeMaxDynamicSharedMemorySize,
                         ATTN_SMEM);
    dim3 ga(T_ / 128, H_, B_);
    attn_mma<<<ga, 256, ATTN_SMEM>>>(qh, kh, vh, oh);

    // Output projection -> fp32 out
    dim3 ggo(BT_ / 128, M_ / 128, 1);
    gemm_out<<<ggo, 256, GEMM_SMEM>>>(oh, wo, out);
}

// round 10
// speedup vs baseline: 6.1779x; 1.0029x over previous
#include <cuda_runtime.h>
#include <cuda_fp16.h>
#include <math.h>
#include <stdint.h>

#define B_  2
#define T_  2048
#define M_  2048
#define H_  16
#define D_  128
#define BT_ (B_ * T_)
#define K_  M_

// ---------------------------------------------------------------------------
// Scratch (device globals: allocation-free per harness rules)
// ---------------------------------------------------------------------------
__device__ __half g_xh[(size_t)BT_ * M_];
__device__ __half g_qh[(size_t)BT_ * M_];
__device__ __half g_kh[(size_t)BT_ * M_];
__device__ __half g_vh[(size_t)BT_ * M_];
__device__ __half g_oh[(size_t)BT_ * M_];

__device__ __half g_wq[(size_t)H_ * D_ * M_];
__device__ __half g_wk[(size_t)H_ * D_ * M_];
__device__ __half g_wv[(size_t)H_ * D_ * M_];
__device__ __half g_wo[(size_t)M_ * M_];

// ---------------------------------------------------------------------------
// PTX helpers (sm_80-class only: legal under plain sm_103 target)
// ---------------------------------------------------------------------------
__device__ __forceinline__ uint32_t s2u(const void* p) {
    uint32_t a;
    asm("{ .reg .u64 t; cvta.to.shared.u64 t, %1; cvt.u32.u64 %0, t; }"
        : "=r"(a) : "l"(p));
    return a;
}

__device__ __forceinline__ void cp16(uint32_t dst, const void* src) {
    asm volatile("cp.async.cg.shared.global [%0], [%1], 16;"
                 :: "r"(dst), "l"(src) : "memory");
}

#define LDSM4(r, a) \
    asm volatile("ldmatrix.sync.aligned.m8n8.x4.shared.b16 {%0,%1,%2,%3}, [%4];" \
                 : "=r"((r)[0]), "=r"((r)[1]), "=r"((r)[2]), "=r"((r)[3])        \
                 : "r"(a))

#define LDSM4T(r, a) \
    asm volatile("ldmatrix.sync.aligned.m8n8.x4.trans.shared.b16 {%0,%1,%2,%3}, [%4];" \
                 : "=r"((r)[0]), "=r"((r)[1]), "=r"((r)[2]), "=r"((r)[3])              \
                 : "r"(a))

__device__ __forceinline__ void mma16816(float* d, const uint32_t* a,
                                         uint32_t b0, uint32_t b1) {
    asm volatile(
        "mma.sync.aligned.m16n8k16.row.col.f32.f16.f16.f32 "
        "{%0,%1,%2,%3}, {%4,%5,%6,%7}, {%8,%9}, {%0,%1,%2,%3};"
        : "+f"(d[0]), "+f"(d[1]), "+f"(d[2]), "+f"(d[3])
        : "r"(a[0]), "r"(a[1]), "r"(a[2]), "r"(a[3]), "r"(b0), "r"(b1));
}

__device__ __forceinline__ uint32_t packh(float x, float y) {
    __half2 t = __halves2half2(__float2half_rn(x), __float2half_rn(y));
    return *(uint32_t*)&t;
}

// ---------------------------------------------------------------------------
// Convert: fp32 -> fp16
// ---------------------------------------------------------------------------
__global__ __launch_bounds__(256) void conv_kernel(
    const float* __restrict__ x, __half* __restrict__ h, int n4)
{
    int i = blockIdx.x * blockDim.x + threadIdx.x;
    if (i >= n4) return;
    float4 v = ((const float4*)x)[i];
    uint32_t* H = (uint32_t*)h;
    H[2*i]   = packh(v.x, v.y);
    H[2*i+1] = packh(v.z, v.w);
}

// ---------------------------------------------------------------------------
// Transpose + convert, 3 weights in one launch
// ---------------------------------------------------------------------------
__global__ __launch_bounds__(256) void tconv3_kernel(
    const float* __restrict__ s0, const float* __restrict__ s1,
    const float* __restrict__ s2,
    __half* __restrict__ d0, __half* __restrict__ d1, __half* __restrict__ d2)
{
    __shared__ float t[64][33];
    const int w = blockIdx.z >> 4, p = blockIdx.z & 15;
    const float* src = (w == 0) ? s0 : (w == 1) ? s1 : s2;
    __half* dh       = (w == 0) ? d0 : (w == 1) ? d1 : d2;
    src += (size_t)p * M_ * D_;
    dh  += (size_t)p * D_ * M_;
    const int R = M_, C = D_;
    int c0 = blockIdx.x * 32, r0 = blockIdx.y * 64;
    int tx = threadIdx.x, ty = threadIdx.y;  // 32 x 8
#pragma unroll
    for (int j = 0; j < 8; j++)
        t[ty + 8*j][tx] = src[(size_t)(r0 + ty + 8*j) * C + c0 + tx];
    __syncthreads();
#pragma unroll
    for (int j = 0; j < 4; j++) {
        int c = ty + 8*j;
        __half2 o = __halves2half2(__float2half_rn(t[2*tx][c]),
                                   __float2half_rn(t[2*tx + 1][c]));
        *(__half2*)&dh[(size_t)(c0 + c) * R + r0 + 2*tx] = o;
    }
}

__global__ __launch_bounds__(256) void tconv_kernel(
    const float* __restrict__ src, __half* __restrict__ dh, int R, int C)
{
    __shared__ float t[64][33];
    int c0 = blockIdx.x * 32, r0 = blockIdx.y * 64;
    int tx = threadIdx.x, ty = threadIdx.y;
#pragma unroll
    for (int j = 0; j < 8; j++)
        t[ty + 8*j][tx] = src[(size_t)(r0 + ty + 8*j) * C + c0 + tx];
    __syncthreads();
#pragma unroll
    for (int j = 0; j < 4; j++) {
        int c = ty + 8*j;
        __half2 o = __halves2half2(__float2half_rn(t[2*tx][c]),
                                   __float2half_rn(t[2*tx + 1][c]));
        *(__half2*)&dh[(size_t)(c0 + c) * R + r0 + 2*tx] = o;
    }
}

// ---------------------------------------------------------------------------
// HMMA GEMM: 128x128 CTA tile, 4 warps (128 threads), warp tile 64x64.
// BK=32, 3-stage cp.async. MMA:LDSM = 4:1 per k16 step.
// ---------------------------------------------------------------------------
#define ROWB      80
#define MAT_BYTES (128 * ROWB)       // 10240
#define STG_BYTES (2 * MAT_BYTES)    // 20480 (A, B)
#define NSTG      3
#define GEMM_SMEM (NSTG * STG_BYTES) // 61440
#define KSTEPS    (K_ / 32)
#define GTHREADS  128

__device__ __forceinline__ void load_stage(
    uint32_t buf, const __half* __restrict__ A,
    const __half* __restrict__ B, int k0, int tid)
{
#pragma unroll
    for (int it = 0; it < 4; it++) {
        int idx = tid + it * GTHREADS;   // 0..511
        int row = idx >> 2, c = idx & 3;
        uint32_t so = (uint32_t)(row * ROWB + c * 16);
        const size_t go = (size_t)row * K_ + k0 + c * 8;
        cp16(buf + so,             A + go);
        cp16(buf + MAT_BYTES + so, B + go);
    }
}

// Mainloop producing fp32 acc[4][8][4] (warp tile 64x64)
__device__ __forceinline__ void gemm_mainloop(
    uint32_t sb, const __half* A, const __half* B, int tid,
    float acc[4][8][4])
{
    const int wid = tid >> 5, lane = tid & 31;
    const int warp_m = wid >> 1, warp_n = wid & 1;

    load_stage(sb,             A, B, 0,  tid);
    asm volatile("cp.async.commit_group;" ::: "memory");
    load_stage(sb + STG_BYTES, A, B, 32, tid);
    asm volatile("cp.async.commit_group;" ::: "memory");

#pragma unroll
    for (int i = 0; i < 4; i++)
#pragma unroll
        for (int j = 0; j < 8; j++)
#pragma unroll
            for (int r = 0; r < 4; r++) acc[i][j][r] = 0.f;

    const int lrow = lane & 15;
    const int lchk = (lane >> 4) * 16;

    for (int s = 0; s < KSTEPS; s++) {
        if (s + 1 < KSTEPS)
            asm volatile("cp.async.wait_group 1;" ::: "memory");
        else
            asm volatile("cp.async.wait_group 0;" ::: "memory");
        __syncthreads();

        if (s + 2 < KSTEPS) {
            load_stage(sb + (uint32_t)((s + 2) % NSTG) * STG_BYTES,
                       A, B, (s + 2) * 32, tid);
            asm volatile("cp.async.commit_group;" ::: "memory");
        }

        const uint32_t base = sb + (uint32_t)(s % NSTG) * STG_BYTES;

#pragma unroll
        for (int kh = 0; kh < 2; kh++) {
            const uint32_t koff = (uint32_t)(kh * 32 + lchk);
            uint32_t a4[4][4];
#pragma unroll
            for (int mi = 0; mi < 4; mi++) {
                uint32_t ad = base +
                    (uint32_t)((warp_m * 64 + mi * 16 + lrow) * ROWB) + koff;
                LDSM4(a4[mi], ad);
            }
            uint32_t b4[4][4];
#pragma unroll
            for (int bj = 0; bj < 4; bj++) {
                uint32_t bd = base + MAT_BYTES +
                    (uint32_t)((warp_n * 64 + bj * 16 + lrow) * ROWB) + koff;
                LDSM4(b4[bj], bd);
            }
#pragma unroll
            for (int mi = 0; mi < 4; mi++) {
#pragma unroll
                for (int ni = 0; ni < 8; ni++) {
                    const int bj = ni >> 1, sel = ni & 1;
                    mma16816(acc[mi][ni], a4[mi], b4[bj][sel], b4[bj][sel + 2]);
                }
            }
        }
    }
}

// ---------------------------------------------------------------------------
// QKV projection GEMM with fused RoPE epilogue for q/k.
// z: 0 = q (rope + 1/128 scale), 1 = k (rope), 2 = v (plain).
// ---------------------------------------------------------------------------
#define TILE_STR 130   // halves per row in epilogue staging tile

__global__ __launch_bounds__(GTHREADS) void gemm_qkv(
    const __half* __restrict__ xh,
    const __half* __restrict__ wq, const __half* __restrict__ wk,
    const __half* __restrict__ wv,
    __half* __restrict__ qh, __half* __restrict__ kh, __half* __restrict__ vh)
{
    extern __shared__ char smraw[];
    const uint32_t sb = s2u(smraw);
    const int tid = threadIdx.x;
    const int wid = tid >> 5, lane = tid & 31;
    const int warp_m = wid >> 1, warp_n = wid & 1;
    const int z = blockIdx.z;

    const __half* B = (z == 0) ? wq : (z == 1) ? wk : wv;
    __half* C       = (z == 0) ? qh : (z == 1) ? kh : vh;

    const int row0 = blockIdx.x * 128;
    const int col0 = blockIdx.y * 128;
    const __half* A = xh + (size_t)row0 * K_;
    B += (size_t)col0 * K_;

    float acc[4][8][4];
    gemm_mainloop(sb, A, B, tid, acc);

    const int grp = lane >> 2, tig = lane & 3;

    if (z == 2) {
        // plain fp16 store
#pragma unroll
        for (int mi = 0; mi < 4; mi++) {
#pragma unroll
            for (int ni = 0; ni < 8; ni++) {
                int r = row0 + warp_m * 64 + mi * 16 + grp;
                int c = col0 + warp_n * 64 + ni * 8 + tig * 2;
                *(uint32_t*)(C + (size_t)r * M_ + c) =
                    packh(acc[mi][ni][0], acc[mi][ni][1]);
                *(uint32_t*)(C + (size_t)(r + 8) * M_ + c) =
                    packh(acc[mi][ni][2], acc[mi][ni][3]);
            }
        }
        return;
    }

    // ---- fused RoPE epilogue (q/k) ----
    __half* tile = (__half*)smraw;   // 128 x TILE_STR halves = 33280 B
    __syncthreads();                 // all warps done with stage buffers
#pragma unroll
    for (int mi = 0; mi < 4; mi++) {
#pragma unroll
        for (int ni = 0; ni < 8; ni++) {
            int rl = warp_m * 64 + mi * 16 + grp;
            int cl = warp_n * 64 + ni * 8 + tig * 2;
            *(uint32_t*)&tile[rl * TILE_STR + cl] =
                packh(acc[mi][ni][0], acc[mi][ni][1]);
            *(uint32_t*)&tile[(rl + 8) * TILE_STR + cl] =
                packh(acc[mi][ni][2], acc[mi][ni][3]);
        }
    }
    __syncthreads();

    const float scale = (z == 0) ? (1.0f / 128.0f) : 1.0f;
    const int d0 = lane * 2;  // d in [0,64), pairs (d, d+64)
    const float freq0 = exp2f(-(float)d0 * 0.20762050593045952f);
    const float freq1 = exp2f(-(float)(d0 + 1) * 0.20762050593045952f);

#pragma unroll 4
    for (int rr = 0; rr < 32; rr++) {
        const int rl = wid * 32 + rr;
        const int t = (row0 + rl) & (T_ - 1);
        float s0, c0, s1, c1;
        sincosf((float)t * freq0, &s0, &c0);
        sincosf((float)t * freq1, &s1, &c1);

        __half2 ev = *(__half2*)&tile[rl * TILE_STR + d0];
        __half2 od = *(__half2*)&tile[rl * TILE_STR + d0 + 64];
        float e0 = __half2float(ev.x), e1 = __half2float(ev.y);
        float o0 = __half2float(od.x), o1 = __half2float(od.y);

        float r0e = (e0 * c0 - o0 * s0) * scale;
        float r1e = (e1 * c1 - o1 * s1) * scale;
        float r0o = (e0 * s0 + o0 * c0) * scale;
        float r1o = (e1 * s1 + o1 * c1) * scale;

        __half* Cp = C + (size_t)(row0 + rl) * M_ + col0;
        *(uint32_t*)(Cp + d0)      = packh(r0e, r1e);
        *(uint32_t*)(Cp + d0 + 64) = packh(r0o, r1o);
    }
}

// ---------------------------------------------------------------------------
// Output projection GEMM (fp32 out)
// ---------------------------------------------------------------------------
__global__ __launch_bounds__(GTHREADS) void gemm_out(
    const __half* __restrict__ A, const __half* __restrict__ B0,
    float* __restrict__ C)
{
    extern __shared__ char smraw[];
    const uint32_t sb = s2u(smraw);
    const int tid = threadIdx.x;
    const int wid = tid >> 5, lane = tid & 31;
    const int warp_m = wid >> 1, warp_n = wid & 1;

    const int row0 = blockIdx.x * 128;
    const int col0 = blockIdx.y * 128;
    const __half* Ap = A + (size_t)row0 * K_;
    const __half* Bp = B0 + (size_t)col0 * K_;

    float acc[4][8][4];
    gemm_mainloop(sb, Ap, Bp, tid, acc);

    const int grp = lane >> 2, tig = lane & 3;
#pragma unroll
    for (int mi = 0; mi < 4; mi++) {
#pragma unroll
        for (int ni = 0; ni < 8; ni++) {
            int r = row0 + warp_m * 64 + mi * 16 + grp;
            int c = col0 + warp_n * 64 + ni * 8 + tig * 2;
            *(float2*)(C + (size_t)r * M_ + c) =
                make_float2(acc[mi][ni][0], acc[mi][ni][1]);
            *(float2*)(C + (size_t)(r + 8) * M_ + c) =
                make_float2(acc[mi][ni][2], acc[mi][ni][3]);
        }
    }
}

// ---------------------------------------------------------------------------
// HMMA causal flash attention: 128q x 64kv tiles, 8 warps, 2 CTAs/SM.
// (unchanged from round 9)
// ---------------------------------------------------------------------------
#define AROWB 272
#define AMAT  (64 * AROWB)            // 17408
#define QBYT  (128 * AROWB)           // 34816
#define KVK   QBYT
#define KVV   (QBYT + 2 * AMAT)
#define ATTN_SMEM (QBYT + 4 * AMAT)   // 104448

__device__ __forceinline__ void load_half_tile(
    uint32_t dst, const __half* __restrict__ src, int b, int h, int j0, int tid)
{
#pragma unroll
    for (int it = 0; it < 4; it++) {
        int idx = tid + it * 256;
        int r = idx >> 4, c = idx & 15;
        cp16(dst + (uint32_t)(r * AROWB + c * 16),
             src + ((size_t)(b * T_ + j0 + r) * H_ + h) * D_ + c * 8);
    }
}

__global__ __launch_bounds__(256, 2) void attn_mma(
    const __half* __restrict__ qh, const __half* __restrict__ kh,
    const __half* __restrict__ vh, __half* __restrict__ oh)
{
    extern __shared__ char smraw[];
    const uint32_t sb = s2u(smraw);
    const int tid = threadIdx.x, wid = tid >> 5, lane = tid & 31;
    const int qi = (int)gridDim.x - 1 - (int)blockIdx.x;  // heavy tiles first
    const int h = blockIdx.y, b = blockIdx.z;
    const int i0 = qi * 128;
    const int numkv = (qi + 1) * 2;

    const __half* Qp = qh + ((size_t)(b * T_ + i0) * H_ + h) * D_;
#pragma unroll
    for (int it = 0; it < 8; it++) {
        int idx = tid + it * 256;
        int r = idx >> 4, c = idx & 15;
        cp16(sb + (uint32_t)(r * AROWB + c * 16),
             Qp + (size_t)r * (H_ * D_) + c * 8);
    }
    load_half_tile(sb + KVK, kh, b, h, 0, tid);
    load_half_tile(sb + KVV, vh, b, h, 0, tid);
    asm volatile("cp.async.commit_group;" ::: "memory");
    load_half_tile(sb + KVK + AMAT, kh, b, h, 64, tid);
    load_half_tile(sb + KVV + AMAT, vh, b, h, 64, tid);
    asm volatile("cp.async.commit_group;" ::: "memory");

    float oacc[16][4];
#pragma unroll
    for (int i = 0; i < 16; i++)
#pragma unroll
        for (int j = 0; j < 4; j++) oacc[i][j] = 0.f;
    float m0 = -3.0e38f, m1 = -3.0e38f, l0 = 0.f, l1 = 0.f;

    const int lrow = lane & 15, lchk = (lane >> 4) * 16;
    const int grp = lane >> 2, tig = lane & 3;
    const int wrow = i0 + wid * 16;
    const int row0g = wrow + grp, row1g = row0g + 8;
    const uint32_t qln = sb + (uint32_t)((wid * 16 + lrow) * AROWB + lchk);

    for (int s = 0; s < numkv; s++) {
        if (s == 0)
            asm volatile("cp.async.wait_group 1;" ::: "memory");
        else
            asm volatile("cp.async.wait_group 2;" ::: "memory");
        __syncthreads();

        const uint32_t kbase = sb + KVK + (uint32_t)(s & 1) * AMAT;
        const uint32_t vbase = sb + KVV + (uint32_t)(s & 1) * AMAT;
        const int j0 = s * 64;

        // ---- S = Q * K^T ----
        float sacc[8][4];
#pragma unroll
        for (int i = 0; i < 8; i++)
#pragma unroll
            for (int j = 0; j < 4; j++) sacc[i][j] = 0.f;

        const uint32_t kln = kbase + (uint32_t)(lrow * AROWB + lchk);
#pragma unroll
        for (int kb = 0; kb < 8; kb++) {
            uint32_t a[4];
            LDSM4(a, qln + kb * 32);
#pragma unroll
            for (int ng = 0; ng < 4; ng++) {
                uint32_t bb[4];
                LDSM4(bb, kln + (uint32_t)(ng * (16 * AROWB)) + kb * 32);
                mma16816(sacc[2 * ng],     a, bb[0], bb[2]);
                mma16816(sacc[2 * ng + 1], a, bb[1], bb[3]);
            }
        }

        __syncthreads();
        if (s + 2 < numkv)
            load_half_tile(kbase, kh, b, h, (s + 2) * 64, tid);
        asm volatile("cp.async.commit_group;" ::: "memory");

        // ---- causal mask ----
        if (j0 + 63 > wrow) {
#pragma unroll
            for (int nb = 0; nb < 8; nb++) {
                int c0 = j0 + nb * 8 + tig * 2;
                if (c0     > row0g) sacc[nb][0] = -1e30f;
                if (c0 + 1 > row0g) sacc[nb][1] = -1e30f;
                if (c0     > row1g) sacc[nb][2] = -1e30f;
                if (c0 + 1 > row1g) sacc[nb][3] = -1e30f;
            }
        }

        // ---- online softmax ----
        float mx0 = -3.0e38f, mx1 = -3.0e38f;
#pragma unroll
        for (int nb = 0; nb < 8; nb++) {
            mx0 = fmaxf(mx0, fmaxf(sacc[nb][0], sacc[nb][1]));
            mx1 = fmaxf(mx1, fmaxf(sacc[nb][2], sacc[nb][3]));
        }
        mx0 = fmaxf(mx0, __shfl_xor_sync(0xffffffffu, mx0, 1));
        mx0 = fmaxf(mx0, __shfl_xor_sync(0xffffffffu, mx0, 2));
        mx1 = fmaxf(mx1, __shfl_xor_sync(0xffffffffu, mx1, 1));
        mx1 = fmaxf(mx1, __shfl_xor_sync(0xffffffffu, mx1, 2));
        float mn0 = fmaxf(m0, mx0), mn1 = fmaxf(m1, mx1);
        float al0 = __expf(m0 - mn0), al1 = __expf(m1 - mn1);
        m0 = mn0; m1 = mn1;
#pragma unroll
        for (int ng = 0; ng < 16; ng++) {
            oacc[ng][0] *= al0; oacc[ng][1] *= al0;
            oacc[ng][2] *= al1; oacc[ng][3] *= al1;
        }

        // ---- fused exp + PV ----
        float rs0 = 0.f, rs1 = 0.f;
        const uint32_t vln = vbase + (uint32_t)(lrow * AROWB + lchk);
#pragma unroll
        for (int kk = 0; kk < 4; kk++) {
            uint32_t aP[4];
#pragma unroll
            for (int hf = 0; hf < 2; hf++) {
                int nb = 2 * kk + hf;
                float p0 = __expf(sacc[nb][0] - m0);
                float p1 = __expf(sacc[nb][1] - m0);
                float p2 = __expf(sacc[nb][2] - m1);
                float p3 = __expf(sacc[nb][3] - m1);
                float h0 = __half2float(__float2half_rn(p0));
                float h1 = __half2float(__float2half_rn(p1));
                float h2 = __half2float(__float2half_rn(p2));
                float h3 = __half2float(__float2half_rn(p3));
                rs0 += h0 + h1;
                rs1 += h2 + h3;
                aP[2 * hf]     = packh(h0, h1);
                aP[2 * hf + 1] = packh(h2, h3);
            }
            const uint32_t vrow = vln + (uint32_t)(kk * (16 * AROWB));
#pragma unroll
            for (int ng = 0; ng < 8; ng++) {
                uint32_t bv[4];
                LDSM4T(bv, vrow + ng * 32);
                mma16816(oacc[2 * ng],     aP, bv[0], bv[1]);
                mma16816(oacc[2 * ng + 1], aP, bv[2], bv[3]);
            }
        }
        rs0 += __shfl_xor_sync(0xffffffffu, rs0, 1);
        rs0 += __shfl_xor_sync(0xffffffffu, rs0, 2);
        rs1 += __shfl_xor_sync(0xffffffffu, rs1, 1);
        rs1 += __shfl_xor_sync(0xffffffffu, rs1, 2);
        l0 = l0 * al0 + rs0;
        l1 = l1 * al1 + rs1;

        __syncthreads();
        if (s + 2 < numkv)
            load_half_tile(vbase, vh, b, h, (s + 2) * 64, tid);
        asm volatile("cp.async.commit_group;" ::: "memory");
    }

    // ---- epilogue: O / l -> fp16 ----
    const float inv0 = 1.0f / l0, inv1 = 1.0f / l1;
    const int orow0 = i0 + wid * 16 + grp;
    const size_t ob0 = ((size_t)(b * T_ + orow0) * H_ + h) * D_ + tig * 2;
    const size_t ob1 = ((size_t)(b * T_ + orow0 + 8) * H_ + h) * D_ + tig * 2;
#pragma unroll
    for (int ng = 0; ng < 16; ng++) {
        *(uint32_t*)(oh + ob0 + ng * 8) =
            packh(oacc[ng][0] * inv0, oacc[ng][1] * inv0);
        *(uint32_t*)(oh + ob1 + ng * 8) =
            packh(oacc[ng][2] * inv1, oacc[ng][3] * inv1);
    }
}

// ---------------------------------------------------------------------------
// Launch
// ---------------------------------------------------------------------------
extern "C" void kernel_launch(void* const* d_in, const int* in_sizes, int n_in,
                              void* d_out, int out_size)
{
    const float* x    = (const float*)d_in[0];
    const float* w_aq = (const float*)d_in[1];
    const float* w_ak = (const float*)d_in[2];
    const float* w_av = (const float*)d_in[3];
    const float* w_ao = (const float*)d_in[4];
    float* out = (float*)d_out;

    __half *xh, *qh, *kh, *vh, *oh;
    cudaGetSymbolAddress((void**)&xh, g_xh);
    cudaGetSymbolAddress((void**)&qh, g_qh);
    cudaGetSymbolAddress((void**)&kh, g_kh);
    cudaGetSymbolAddress((void**)&vh, g_vh);
    cudaGetSymbolAddress((void**)&oh, g_oh);

    __half *wq, *wk, *wv, *wo;
    cudaGetSymbolAddress((void**)&wq, g_wq);
    cudaGetSymbolAddress((void**)&wk, g_wk);
    cudaGetSymbolAddress((void**)&wv, g_wv);
    cudaGetSymbolAddress((void**)&wo, g_wo);

    // Weight transpose+convert: q/k/v in one launch, wo separate
    dim3 tb(32, 8);
    dim3 tg3(D_ / 32, M_ / 64, 3 * H_);
    tconv3_kernel<<<tg3, tb>>>(w_aq, w_ak, w_av, wq, wk, wv);
    dim3 tgo(M_ / 32, M_ / 64, 1);
    tconv_kernel<<<tgo, tb>>>(w_ao, wo, M_, M_);

    // Convert x -> fp16
    conv_kernel<<<(BT_ * M_ / 4 + 255) / 256, 256>>>(x, xh, BT_ * M_ / 4);

    // QKV projections with fused RoPE epilogue (4-warp fat-tile GEMM)
    cudaFuncSetAttribute(gemm_qkv,
                         cudaFuncAttributeMaxDynamicSharedMemorySize, GEMM_SMEM);
    cudaFuncSetAttribute(gemm_out,
                         cudaFuncAttributeMaxDynamicSharedMemorySize, GEMM_SMEM);
    dim3 gg(BT_ / 128, M_ / 128, 3);
    gemm_qkv<<<gg, GTHREADS, GEMM_SMEM>>>(xh, wq, wk, wv, qh, kh, vh);

    // HMMA flash attention -> oh (2 CTAs/SM)
    cudaFuncSetAttribute(attn_mma, cudaFuncAttributeMaxDynamicSharedMemorySize,
                         ATTN_SMEM);
    dim3 ga(T_ / 128, H_, B_);
    attn_mma<<<ga, 256, ATTN_SMEM>>>(qh, kh, vh, oh);

    // Output projection -> fp32 out
    dim3 ggo(BT_ / 128, M_ / 128, 1);
    gemm_out<<<ggo, GTHREADS, GEMM_SMEM>>>(oh, wo, out);
}